// round 1
// baseline (speedup 1.0000x reference)
#include <cuda_runtime.h>
#include <cuda_bf16.h>
#include <math.h>

// Problem constants
#define B_ 4
#define T_ 2048
#define C_ 1024
#define H_ 16
#define HS_ 64
#define BT_ (B_*T_)   // 8192

// Scratch (device globals: allocation-free rule)
__device__ float g_q[B_*H_*T_*HS_];     // [bh][t][d]
__device__ float g_k[B_*H_*T_*HS_];
__device__ float g_v[B_*H_*T_*HS_];
__device__ float g_att[BT_*C_];         // [b*T+t][h*HS+d]  (concat-heads layout)

// ---------------------------------------------------------------------------
// Kernel 1: fused QKV projection.
// GEMM per (head, matrix): M=8192, N=64, K=1024.
// out[(b*H+h)*T + t][d] = sum_c x[b*T+t][c] * W[h][c][d]
// Tiles: BM=128, BN=64, BK=32; 256 threads; 8x4 per-thread microtile.
// ---------------------------------------------------------------------------
__global__ __launch_bounds__(256) void qkv_kernel(
    const float* __restrict__ x,
    const float* __restrict__ Wq,
    const float* __restrict__ Wk,
    const float* __restrict__ Wv)
{
    __shared__ float As[32][128];   // [k][m] (transposed x tile)
    __shared__ float Bs[32][64];    // [k][n]

    const int tid = threadIdx.x;
    const int m0  = blockIdx.x * 128;
    const int h   = blockIdx.y;
    const int mat = blockIdx.z;

    const float* W = (mat == 0 ? Wq : (mat == 1 ? Wk : Wv)) + (size_t)h * C_ * HS_;
    float* out     = (mat == 0 ? g_q : (mat == 1 ? g_k : g_v));

    const int mrow = (tid >> 4) * 8;   // 0..120
    const int ncol = (tid & 15) * 4;   // 0..60

    float acc[8][4] = {};

    for (int k0 = 0; k0 < C_; k0 += 32) {
        // load A tile (128x32) transposed: 1024 float4, 4 per thread
        #pragma unroll
        for (int i = 0; i < 4; i++) {
            int v = tid + i * 256;
            int r = v >> 3;           // 0..127 (m)
            int kc = (v & 7) * 4;     // 0..28  (k)
            float4 a = *(const float4*)(x + (size_t)(m0 + r) * C_ + k0 + kc);
            As[kc + 0][r] = a.x; As[kc + 1][r] = a.y;
            As[kc + 2][r] = a.z; As[kc + 3][r] = a.w;
        }
        // load B tile (32x64): 512 float4, 2 per thread
        #pragma unroll
        for (int i = 0; i < 2; i++) {
            int v = tid + i * 256;
            int r = v >> 4;           // 0..31 (k)
            int c = (v & 15) * 4;     // 0..60 (n)
            *(float4*)&Bs[r][c] = *(const float4*)(W + (size_t)(k0 + r) * HS_ + c);
        }
        __syncthreads();

        #pragma unroll
        for (int k = 0; k < 32; k++) {
            float4 b  = *(float4*)&Bs[k][ncol];
            float4 a0 = *(float4*)&As[k][mrow];
            float4 a1 = *(float4*)&As[k][mrow + 4];
            float am[8] = {a0.x, a0.y, a0.z, a0.w, a1.x, a1.y, a1.z, a1.w};
            #pragma unroll
            for (int i = 0; i < 8; i++) {
                acc[i][0] += am[i] * b.x;
                acc[i][1] += am[i] * b.y;
                acc[i][2] += am[i] * b.z;
                acc[i][3] += am[i] * b.w;
            }
        }
        __syncthreads();
    }

    #pragma unroll
    for (int i = 0; i < 8; i++) {
        int m = m0 + mrow + i;
        int b = m >> 11;          // m / T_
        int t = m & (T_ - 1);
        float4 r = make_float4(acc[i][0], acc[i][1], acc[i][2], acc[i][3]);
        *(float4*)(out + (((size_t)(b * H_ + h) * T_ + t) * HS_ + ncol)) = r;
    }
}

// ---------------------------------------------------------------------------
// Kernel 2: causal flash attention per (b,h).
// Q block = 64 rows; KV tiles of 64. Online softmax in registers.
// smem: Qts[d][m] (Q^T, pre-scaled by C^-0.5), KPs (K^T [d][s], reused as
// P [m][s] after S-compute), Vs [s][d]. Exactly 48KB static shared.
// Heavy q-blocks scheduled first for load balance.
// ---------------------------------------------------------------------------
__global__ __launch_bounds__(256) void attn_kernel()
{
    __shared__ float Qts[64][64];   // [d][m]
    __shared__ float KPs[64][64];   // Kts [d][s]  -> later Ps [m][s]
    __shared__ float Vs[64][64];    // [s][d]

    const int tid  = threadIdx.x;
    const int qblk = (gridDim.x - 1) - blockIdx.x;   // heavy blocks first
    const int bh   = blockIdx.y;
    const int t0   = qblk * 64;

    const float* qb = g_q + (size_t)bh * T_ * HS_;
    const float* kb = g_k + (size_t)bh * T_ * HS_;
    const float* vb = g_v + (size_t)bh * T_ * HS_;

    const int mrow = (tid >> 4) * 4;   // 4 rows per thread
    const int ncol = (tid & 15) * 4;   // 4 cols per thread
    const float scale = 0.03125f;      // C^-0.5 = 1/32 (exact)

    // Load Q tile transposed, pre-scaled: 1024 float4, 4/thread
    #pragma unroll
    for (int i = 0; i < 4; i++) {
        int v = tid + i * 256;
        int r = v >> 4;           // t within tile
        int c = (v & 15) * 4;     // d
        float4 a = *(const float4*)(qb + (size_t)(t0 + r) * HS_ + c);
        Qts[c + 0][r] = a.x * scale; Qts[c + 1][r] = a.y * scale;
        Qts[c + 2][r] = a.z * scale; Qts[c + 3][r] = a.w * scale;
    }

    float row_max[4] = {-1e30f, -1e30f, -1e30f, -1e30f};
    float row_sum[4] = {0.f, 0.f, 0.f, 0.f};
    float Oacc[4][4] = {};

    for (int j = 0; j <= qblk; j++) {
        const int s0 = j * 64;
        // Load K tile transposed into KPs, V tile direct into Vs
        #pragma unroll
        for (int i = 0; i < 4; i++) {
            int v = tid + i * 256;
            int r = v >> 4;
            int c = (v & 15) * 4;
            float4 a = *(const float4*)(kb + (size_t)(s0 + r) * HS_ + c);
            KPs[c + 0][r] = a.x; KPs[c + 1][r] = a.y;
            KPs[c + 2][r] = a.z; KPs[c + 3][r] = a.w;
            *(float4*)&Vs[r][c] = *(const float4*)(vb + (size_t)(s0 + r) * HS_ + c);
        }
        __syncthreads();

        // S = (Q*scale) @ K^T   (microtile 4x4, reduce over d)
        float sacc[4][4] = {};
        #pragma unroll
        for (int d = 0; d < 64; d++) {
            float4 qa = *(float4*)&Qts[d][mrow];
            float4 kv = *(float4*)&KPs[d][ncol];
            float qm[4] = {qa.x, qa.y, qa.z, qa.w};
            #pragma unroll
            for (int i = 0; i < 4; i++) {
                sacc[i][0] += qm[i] * kv.x;
                sacc[i][1] += qm[i] * kv.y;
                sacc[i][2] += qm[i] * kv.z;
                sacc[i][3] += qm[i] * kv.w;
            }
        }
        __syncthreads();  // everyone done reading KPs (as K^T)

        // causal mask on diagonal tile
        if (j == qblk) {
            #pragma unroll
            for (int i = 0; i < 4; i++)
                #pragma unroll
                for (int jj = 0; jj < 4; jj++)
                    if (ncol + jj > mrow + i) sacc[i][jj] = -1e30f;
        }

        // online softmax stats (rows owned by 16-lane groups)
        float p[4][4];
        float psum[4];
        #pragma unroll
        for (int i = 0; i < 4; i++) {
            float mx = fmaxf(fmaxf(sacc[i][0], sacc[i][1]),
                             fmaxf(sacc[i][2], sacc[i][3]));
            #pragma unroll
            for (int w = 8; w >= 1; w >>= 1)
                mx = fmaxf(mx, __shfl_xor_sync(0xffffffffu, mx, w));
            float m_new = fmaxf(row_max[i], mx);
            float alpha = __expf(row_max[i] - m_new);
            row_max[i] = m_new;
            float ps = 0.f;
            #pragma unroll
            for (int jj = 0; jj < 4; jj++) {
                float e = __expf(sacc[i][jj] - m_new);
                p[i][jj] = e;
                ps += e;
            }
            #pragma unroll
            for (int w = 8; w >= 1; w >>= 1)
                ps += __shfl_xor_sync(0xffffffffu, ps, w);
            psum[i] = ps;
            row_sum[i] = row_sum[i] * alpha + ps;
            #pragma unroll
            for (int jj = 0; jj < 4; jj++) Oacc[i][jj] *= alpha;
        }
        (void)psum;

        // Write P into KPs as Ps[m][s]
        #pragma unroll
        for (int i = 0; i < 4; i++) {
            float4 r = make_float4(p[i][0], p[i][1], p[i][2], p[i][3]);
            *(float4*)&KPs[mrow + i][ncol] = r;
        }
        __syncthreads();

        // O += P @ V   (reduce over s, 4 s at a time)
        #pragma unroll
        for (int s4 = 0; s4 < 16; s4++) {
            float4 pr[4];
            #pragma unroll
            for (int i = 0; i < 4; i++)
                pr[i] = *(float4*)&KPs[mrow + i][s4 * 4];
            #pragma unroll
            for (int ss = 0; ss < 4; ss++) {
                float4 vv = *(float4*)&Vs[s4 * 4 + ss][ncol];
                float pm[4] = {pr[0].x, pr[1].x, pr[2].x, pr[3].x};
                // select component ss from pr[i]
                #pragma unroll
                for (int i = 0; i < 4; i++) {
                    float pv = (ss == 0) ? pr[i].x : (ss == 1) ? pr[i].y
                             : (ss == 2) ? pr[i].z : pr[i].w;
                    Oacc[i][0] += pv * vv.x;
                    Oacc[i][1] += pv * vv.y;
                    Oacc[i][2] += pv * vv.z;
                    Oacc[i][3] += pv * vv.w;
                }
                (void)pm;
            }
        }
        __syncthreads();  // before next tile overwrites KPs/Vs
    }

    // normalize + write to g_att[b*T+t][h*64+d]
    const int b = bh >> 4;   // bh / H_
    const int h = bh & 15;
    #pragma unroll
    for (int i = 0; i < 4; i++) {
        float inv = 1.0f / row_sum[i];
        int t = t0 + mrow + i;
        float4 r = make_float4(Oacc[i][0] * inv, Oacc[i][1] * inv,
                               Oacc[i][2] * inv, Oacc[i][3] * inv);
        *(float4*)(g_att + ((size_t)(b * T_ + t) * C_ + h * HS_ + ncol)) = r;
    }
}

// ---------------------------------------------------------------------------
// Kernel 3: output projection + bias.
// out[m][n] = sum_k g_att[m][k] * Wp[k][n] + bp[n];  M=8192, N=1024, K=1024.
// Same tiling as kernel 1 (BM=128, BN=64, BK=32).
// ---------------------------------------------------------------------------
__global__ __launch_bounds__(256) void proj_kernel(
    const float* __restrict__ Wp,
    const float* __restrict__ bp,
    float* __restrict__ out)
{
    __shared__ float As[32][128];   // [k][m]
    __shared__ float Bs[32][64];    // [k][n]

    const int tid = threadIdx.x;
    const int m0  = blockIdx.x * 128;
    const int n0  = blockIdx.y * 64;

    const int mrow = (tid >> 4) * 8;
    const int ncol = (tid & 15) * 4;

    float acc[8][4] = {};

    for (int k0 = 0; k0 < C_; k0 += 32) {
        #pragma unroll
        for (int i = 0; i < 4; i++) {
            int v = tid + i * 256;
            int r = v >> 3;
            int kc = (v & 7) * 4;
            float4 a = *(const float4*)(g_att + (size_t)(m0 + r) * C_ + k0 + kc);
            As[kc + 0][r] = a.x; As[kc + 1][r] = a.y;
            As[kc + 2][r] = a.z; As[kc + 3][r] = a.w;
        }
        #pragma unroll
        for (int i = 0; i < 2; i++) {
            int v = tid + i * 256;
            int r = v >> 4;
            int c = (v & 15) * 4;
            *(float4*)&Bs[r][c] = *(const float4*)(Wp + (size_t)(k0 + r) * C_ + n0 + c);
        }
        __syncthreads();

        #pragma unroll
        for (int k = 0; k < 32; k++) {
            float4 b  = *(float4*)&Bs[k][ncol];
            float4 a0 = *(float4*)&As[k][mrow];
            float4 a1 = *(float4*)&As[k][mrow + 4];
            float am[8] = {a0.x, a0.y, a0.z, a0.w, a1.x, a1.y, a1.z, a1.w};
            #pragma unroll
            for (int i = 0; i < 8; i++) {
                acc[i][0] += am[i] * b.x;
                acc[i][1] += am[i] * b.y;
                acc[i][2] += am[i] * b.z;
                acc[i][3] += am[i] * b.w;
            }
        }
        __syncthreads();
    }

    float4 bias = *(const float4*)(bp + n0 + ncol);
    #pragma unroll
    for (int i = 0; i < 8; i++) {
        int m = m0 + mrow + i;
        float4 r = make_float4(acc[i][0] + bias.x, acc[i][1] + bias.y,
                               acc[i][2] + bias.z, acc[i][3] + bias.w);
        *(float4*)(out + (size_t)m * C_ + n0 + ncol) = r;
    }
}

// ---------------------------------------------------------------------------
extern "C" void kernel_launch(void* const* d_in, const int* in_sizes, int n_in,
                              void* d_out, int out_size)
{
    const float* x  = (const float*)d_in[0];
    const float* Wq = (const float*)d_in[1];
    const float* Wk = (const float*)d_in[2];
    const float* Wv = (const float*)d_in[3];
    const float* Wp = (const float*)d_in[4];
    const float* bp = (const float*)d_in[5];
    float* out = (float*)d_out;

    qkv_kernel<<<dim3(BT_ / 128, H_, 3), 256>>>(x, Wq, Wk, Wv);
    attn_kernel<<<dim3(T_ / 64, B_ * H_), 256>>>();
    proj_kernel<<<dim3(BT_ / 128, C_ / 64), 256>>>(Wp, bp, out);
}

// round 3
// speedup vs baseline: 1.5036x; 1.5036x over previous
#include <cuda_runtime.h>
#include <cuda_bf16.h>
#include <math.h>
#include <stdint.h>

// Problem constants
#define B_ 4
#define T_ 2048
#define C_ 1024
#define H_ 16
#define HS_ 64
#define BT_ (B_*T_)      // 8192
#define NQKV_ 3072       // 3*H*HS

// ---------------------------------------------------------------------------
// Scratch (device globals: allocation-free rule)
// ---------------------------------------------------------------------------
__device__ __nv_bfloat16 g_x_hi[BT_*C_];
__device__ __nv_bfloat16 g_x_lo[BT_*C_];
__device__ __nv_bfloat16 g_wqkv_hi[NQKV_*C_];   // [n=mat*1024+h*64+d][c]  K-major
__device__ __nv_bfloat16 g_wqkv_lo[NQKV_*C_];
__device__ __nv_bfloat16 g_wp_hi[C_*C_];        // [n][k] K-major (transposed Wp)
__device__ __nv_bfloat16 g_wp_lo[C_*C_];
__device__ float g_q[B_*H_*T_*HS_];             // [bh][t][d] fp32
__device__ float g_k[B_*H_*T_*HS_];
__device__ float g_v[B_*H_*T_*HS_];
__device__ __nv_bfloat16 g_att_hi[BT_*C_];      // attention output hi/lo bf16
__device__ __nv_bfloat16 g_att_lo[BT_*C_];

// ---------------------------------------------------------------------------
// Portable (compute_100-safe) tensor-core primitives: ldmatrix + mma.sync
// ---------------------------------------------------------------------------
__device__ __forceinline__ uint32_t smem_to_u32(const void* p) {
    uint32_t a;
    asm("{ .reg .u64 t; cvta.to.shared.u64 t, %1; cvt.u32.u64 %0, t; }"
        : "=r"(a) : "l"(p));
    return a;
}

__device__ __forceinline__ void ldsm_x4(uint32_t* r, uint32_t addr) {
    asm volatile("ldmatrix.sync.aligned.m8n8.x4.shared.b16 {%0,%1,%2,%3}, [%4];\n"
        : "=r"(r[0]), "=r"(r[1]), "=r"(r[2]), "=r"(r[3]) : "r"(addr));
}

__device__ __forceinline__ void mma_bf16(float* c, const uint32_t* a, const uint32_t* b) {
    asm volatile(
        "mma.sync.aligned.m16n8k16.row.col.f32.bf16.bf16.f32 "
        "{%0,%1,%2,%3}, {%4,%5,%6,%7}, {%8,%9}, {%0,%1,%2,%3};\n"
        : "+f"(c[0]), "+f"(c[1]), "+f"(c[2]), "+f"(c[3])
        : "r"(a[0]), "r"(a[1]), "r"(a[2]), "r"(a[3]), "r"(b[0]), "r"(b[1]));
}

__device__ __forceinline__ void cp16(uint32_t dst, const void* src) {
    asm volatile("cp.async.cg.shared.global [%0], [%1], 16;\n" :: "r"(dst), "l"(src));
}
__device__ __forceinline__ void cp_commit() {
    asm volatile("cp.async.commit_group;\n" ::: "memory");
}
template <int N>
__device__ __forceinline__ void cp_wait() {
    asm volatile("cp.async.wait_group %0;\n" :: "n"(N) : "memory");
}

__device__ __forceinline__ uint32_t pack_bf16(float a, float b) {
    __nv_bfloat162 t = __floats2bfloat162_rn(a, b);
    return *(uint32_t*)&t;
}

// ---------------------------------------------------------------------------
// Conversion kernels
// ---------------------------------------------------------------------------
__global__ __launch_bounds__(256) void conv_x_kernel(const float* __restrict__ x)
{
    size_t idx = (size_t)blockIdx.x * 256 + threadIdx.x;   // float4 index
    float4 a = *(const float4*)(x + idx * 4);
    float h0 = __bfloat162float(__float2bfloat16_rn(a.x));
    float h1 = __bfloat162float(__float2bfloat16_rn(a.y));
    float h2 = __bfloat162float(__float2bfloat16_rn(a.z));
    float h3 = __bfloat162float(__float2bfloat16_rn(a.w));
    uint2 ph = make_uint2(pack_bf16(a.x, a.y), pack_bf16(a.z, a.w));
    uint2 pl = make_uint2(pack_bf16(a.x - h0, a.y - h1), pack_bf16(a.z - h2, a.w - h3));
    *(uint2*)(g_x_hi + idx * 4) = ph;
    *(uint2*)(g_x_lo + idx * 4) = pl;
}

// 64x64 transpose-convert tile: in [64 rows x 64 cols] row-major (stride
// in_stride floats); out[c][r] hi/lo at stride 1024 bf16.
__device__ __forceinline__ void transpose_tile(
    const float* __restrict__ in, int in_stride,
    __nv_bfloat16* __restrict__ oh, __nv_bfloat16* __restrict__ ol,
    float (*sm)[68])
{
    const int tid = threadIdx.x;
    #pragma unroll
    for (int it = 0; it < 4; it++) {
        int v = tid + it * 256;
        int r = v >> 4, c4 = (v & 15) * 4;
        float4 a = *(const float4*)(in + (size_t)r * in_stride + c4);
        sm[r][c4] = a.x; sm[r][c4 + 1] = a.y; sm[r][c4 + 2] = a.z; sm[r][c4 + 3] = a.w;
    }
    __syncthreads();
    #pragma unroll
    for (int it = 0; it < 4; it++) {
        int v = tid + it * 256;
        int d = v >> 4, r4 = (v & 15) * 4;
        float f0 = sm[r4][d], f1 = sm[r4 + 1][d], f2 = sm[r4 + 2][d], f3 = sm[r4 + 3][d];
        float h0 = __bfloat162float(__float2bfloat16_rn(f0));
        float h1 = __bfloat162float(__float2bfloat16_rn(f1));
        float h2 = __bfloat162float(__float2bfloat16_rn(f2));
        float h3 = __bfloat162float(__float2bfloat16_rn(f3));
        uint2 ph = make_uint2(pack_bf16(f0, f1), pack_bf16(f2, f3));
        uint2 pl = make_uint2(pack_bf16(f0 - h0, f1 - h1), pack_bf16(f2 - h2, f3 - h3));
        *(uint2*)(oh + (size_t)d * 1024 + r4) = ph;
        *(uint2*)(ol + (size_t)d * 1024 + r4) = pl;
    }
}

// Wq/Wk/Wv [H][C][HS] -> g_wqkv [mat*1024 + h*64 + d][c]
__global__ __launch_bounds__(256) void conv_wqkv_kernel(
    const float* __restrict__ Wq, const float* __restrict__ Wk,
    const float* __restrict__ Wv)
{
    __shared__ float sm[64][68];
    const int c0 = blockIdx.x * 64;
    const int g  = blockIdx.y;        // 0..47
    const int mat = g >> 4, h = g & 15;
    const float* Wsel = (mat == 0 ? Wq : (mat == 1 ? Wk : Wv));
    const float* in = Wsel + (size_t)h * C_ * HS_ + (size_t)c0 * HS_;
    size_t ob = (size_t)(mat * 1024 + h * 64) * C_ + c0;
    transpose_tile(in, HS_, g_wqkv_hi + ob, g_wqkv_lo + ob, sm);
}

// Wp [C][C] (k rows, n cols) -> g_wp [n][k]
__global__ __launch_bounds__(256) void conv_wp_kernel(const float* __restrict__ Wp)
{
    __shared__ float sm[64][68];
    const int k0 = blockIdx.x * 64;
    const int n0 = blockIdx.y * 64;
    const float* in = Wp + (size_t)k0 * C_ + n0;
    size_t ob = (size_t)n0 * C_ + k0;
    transpose_tile(in, C_, g_wp_hi + ob, g_wp_lo + ob, sm);
}

// ---------------------------------------------------------------------------
// bf16x3 GEMM mainloop (mma.sync).
// CTA 128x128, K-chunk 32, double-buffered cp.async stages of 32 KB.
// Stage layout: A_tile[128][64]bf16 (hi cols 0-31, lo 32-63) then B_tile same.
// SW128-style swizzle: physical 16B-chunk = logical_chunk ^ (row & 7).
// 8 warps: 2(M) x 4(N); warp tile 64x32; fragments m16n8k16.
// ---------------------------------------------------------------------------
#define STAGE_BYTES 32768
#define GEMM_SMEM_TOTAL (2*STAGE_BYTES)

__device__ __forceinline__ void load_stage(
    uint32_t sb, int s,
    const __nv_bfloat16* __restrict__ Ah, const __nv_bfloat16* __restrict__ Al,
    const __nv_bfloat16* __restrict__ Bh, const __nv_bfloat16* __restrict__ Bl,
    int m0, int n0, int k0, int tid)
{
    uint32_t abase = sb + s * STAGE_BYTES;
    uint32_t bbase = abase + 16384;
    #pragma unroll
    for (int it = 0; it < 4; it++) {
        int cid = tid + it * 256;         // 0..1023
        int r = cid >> 3, c = cid & 7;
        uint32_t off = (uint32_t)(r * 128 + ((c ^ (r & 7)) << 4));
        const __nv_bfloat16* srcA =
            (c < 4 ? Ah : Al) + (size_t)(m0 + r) * 1024 + k0 + (c & 3) * 8;
        cp16(abase + off, srcA);
        const __nv_bfloat16* srcB =
            (c < 4 ? Bh : Bl) + (size_t)(n0 + r) * 1024 + k0 + (c & 3) * 8;
        cp16(bbase + off, srcB);
    }
}

__device__ __forceinline__ void compute_stage(
    uint32_t sb, int s, int wm, int wn, int lane,
    float acc[4][4][4])
{
    uint32_t abase = sb + s * STAGE_BYTES;
    uint32_t bbase = abase + 16384;
    const int jlow  = (lane >> 3) & 1;   // row +8 within 16-tile
    const int jhigh = lane >> 4;         // k-half chunk select
    const int rsub  = lane & 7;

    #pragma unroll
    for (int ks = 0; ks < 2; ks++) {
        uint32_t a_hi[4][4], a_lo[4][4];
        #pragma unroll
        for (int mi = 0; mi < 4; mi++) {
            int row = wm + 16 * mi + jlow * 8 + rsub;
            int ch  = 2 * ks + jhigh;
            uint32_t base = abase + row * 128;
            ldsm_x4(a_hi[mi], base + (uint32_t)(((ch)     ^ (row & 7)) << 4));
            ldsm_x4(a_lo[mi], base + (uint32_t)(((ch + 4) ^ (row & 7)) << 4));
        }
        uint32_t b_hi[4][2], b_lo[4][2];
        #pragma unroll
        for (int nb = 0; nb < 2; nb++) {
            int row = wn + 16 * nb + jlow * 8 + rsub;
            int ch  = 2 * ks + jhigh;
            uint32_t base = bbase + row * 128;
            uint32_t t[4];
            ldsm_x4(t, base + (uint32_t)(((ch)     ^ (row & 7)) << 4));
            b_hi[2*nb][0] = t[0]; b_hi[2*nb+1][0] = t[1];
            b_hi[2*nb][1] = t[2]; b_hi[2*nb+1][1] = t[3];
            ldsm_x4(t, base + (uint32_t)(((ch + 4) ^ (row & 7)) << 4));
            b_lo[2*nb][0] = t[0]; b_lo[2*nb+1][0] = t[1];
            b_lo[2*nb][1] = t[2]; b_lo[2*nb+1][1] = t[3];
        }
        #pragma unroll
        for (int mi = 0; mi < 4; mi++)
            #pragma unroll
            for (int ni = 0; ni < 4; ni++)
                mma_bf16(acc[mi][ni], a_hi[mi], b_hi[ni]);
        #pragma unroll
        for (int mi = 0; mi < 4; mi++)
            #pragma unroll
            for (int ni = 0; ni < 4; ni++)
                mma_bf16(acc[mi][ni], a_hi[mi], b_lo[ni]);
        #pragma unroll
        for (int mi = 0; mi < 4; mi++)
            #pragma unroll
            for (int ni = 0; ni < 4; ni++)
                mma_bf16(acc[mi][ni], a_lo[mi], b_hi[ni]);
    }
}

__device__ __forceinline__ void gemm_mainloop(
    uint32_t sb,
    const __nv_bfloat16* Ah, const __nv_bfloat16* Al,
    const __nv_bfloat16* Bh, const __nv_bfloat16* Bl,
    int m0, int n0, int wm, int wn, int lane, int tid,
    float acc[4][4][4])
{
    load_stage(sb, 0, Ah, Al, Bh, Bl, m0, n0, 0, tid);
    cp_commit();
    for (int i = 0; i < 32; i++) {
        if (i < 31) {
            load_stage(sb, (i + 1) & 1, Ah, Al, Bh, Bl, m0, n0, (i + 1) * 32, tid);
            cp_commit();
            cp_wait<1>();
        } else {
            cp_wait<0>();
        }
        __syncthreads();
        compute_stage(sb, i & 1, wm, wn, lane, acc);
        __syncthreads();
    }
}

// ---------------------------------------------------------------------------
// QKV GEMM: out[m][n] = x[m][:] . wqkv[n][:],  n -> (mat, h, d)
// ---------------------------------------------------------------------------
__global__ __launch_bounds__(256, 1) void qkv_gemm_kernel()
{
    extern __shared__ char smem[];
    uint32_t sb = smem_to_u32(smem);
    const int tid = threadIdx.x;
    const int wid = tid >> 5, lane = tid & 31;
    const int n0 = blockIdx.x * 128;
    const int m0 = blockIdx.y * 128;
    const int wm = (wid & 1) * 64;
    const int wn = (wid >> 1) * 32;

    float acc[4][4][4] = {};
    gemm_mainloop(sb, g_x_hi, g_x_lo, g_wqkv_hi, g_wqkv_lo,
                  m0, n0, wm, wn, lane, tid, acc);

    const int b = m0 >> 11;          // whole CTA inside one batch
    #pragma unroll
    for (int mi = 0; mi < 4; mi++) {
        int m = m0 + wm + mi * 16 + (lane >> 2);
        int t = m & (T_ - 1);
        #pragma unroll
        for (int ni = 0; ni < 4; ni++) {
            int n = n0 + wn + ni * 8 + 2 * (lane & 3);
            int mat = n >> 10, h = (n >> 6) & 15, d = n & 63;
            float* o = (mat == 0 ? g_q : (mat == 1 ? g_k : g_v));
            float* dst = o + (((size_t)(b * H_ + h) * T_ + t) * HS_ + d);
            *(float2*)dst = make_float2(acc[mi][ni][0], acc[mi][ni][1]);
            *(float2*)(dst + 8 * HS_) = make_float2(acc[mi][ni][2], acc[mi][ni][3]);
        }
    }
}

// ---------------------------------------------------------------------------
// Projection GEMM: out[m][n] = att[m][:] . wp_t[n][:] + bp[n]
// ---------------------------------------------------------------------------
__global__ __launch_bounds__(256, 1) void proj_gemm_kernel(
    const float* __restrict__ bp, float* __restrict__ out)
{
    extern __shared__ char smem[];
    uint32_t sb = smem_to_u32(smem);
    const int tid = threadIdx.x;
    const int wid = tid >> 5, lane = tid & 31;
    const int n0 = blockIdx.x * 128;
    const int m0 = blockIdx.y * 128;
    const int wm = (wid & 1) * 64;
    const int wn = (wid >> 1) * 32;

    float acc[4][4][4] = {};
    gemm_mainloop(sb, g_att_hi, g_att_lo, g_wp_hi, g_wp_lo,
                  m0, n0, wm, wn, lane, tid, acc);

    #pragma unroll
    for (int mi = 0; mi < 4; mi++) {
        int m = m0 + wm + mi * 16 + (lane >> 2);
        #pragma unroll
        for (int ni = 0; ni < 4; ni++) {
            int n = n0 + wn + ni * 8 + 2 * (lane & 3);
            float2 bb = *(const float2*)(bp + n);
            float* dst = out + (size_t)m * C_ + n;
            *(float2*)dst = make_float2(acc[mi][ni][0] + bb.x, acc[mi][ni][1] + bb.y);
            *(float2*)(dst + 8 * C_) = make_float2(acc[mi][ni][2] + bb.x, acc[mi][ni][3] + bb.y);
        }
    }
}

// ---------------------------------------------------------------------------
// Causal flash attention per (b,h) — SIMT fp32 (round-1 proven math).
// Epilogue writes hi/lo bf16 split for the projection GEMM.
// ---------------------------------------------------------------------------
__global__ __launch_bounds__(256) void attn_kernel()
{
    __shared__ float Qts[64][64];   // [d][m]
    __shared__ float KPs[64][64];   // K^T [d][s] -> later P [m][s]
    __shared__ float Vs[64][64];    // [s][d]

    const int tid  = threadIdx.x;
    const int qblk = (gridDim.x - 1) - blockIdx.x;   // heavy blocks first
    const int bh   = blockIdx.y;
    const int t0   = qblk * 64;

    const float* qb = g_q + (size_t)bh * T_ * HS_;
    const float* kb = g_k + (size_t)bh * T_ * HS_;
    const float* vb = g_v + (size_t)bh * T_ * HS_;

    const int mrow = (tid >> 4) * 4;
    const int ncol = (tid & 15) * 4;
    const float scale = 0.03125f;   // C^-0.5 = 1/32

    #pragma unroll
    for (int i = 0; i < 4; i++) {
        int v = tid + i * 256;
        int r = v >> 4;
        int c = (v & 15) * 4;
        float4 a = *(const float4*)(qb + (size_t)(t0 + r) * HS_ + c);
        Qts[c + 0][r] = a.x * scale; Qts[c + 1][r] = a.y * scale;
        Qts[c + 2][r] = a.z * scale; Qts[c + 3][r] = a.w * scale;
    }

    float row_max[4] = {-1e30f, -1e30f, -1e30f, -1e30f};
    float row_sum[4] = {0.f, 0.f, 0.f, 0.f};
    float Oacc[4][4] = {};

    for (int j = 0; j <= qblk; j++) {
        const int s0 = j * 64;
        #pragma unroll
        for (int i = 0; i < 4; i++) {
            int v = tid + i * 256;
            int r = v >> 4;
            int c = (v & 15) * 4;
            float4 a = *(const float4*)(kb + (size_t)(s0 + r) * HS_ + c);
            KPs[c + 0][r] = a.x; KPs[c + 1][r] = a.y;
            KPs[c + 2][r] = a.z; KPs[c + 3][r] = a.w;
            *(float4*)&Vs[r][c] = *(const float4*)(vb + (size_t)(s0 + r) * HS_ + c);
        }
        __syncthreads();

        float sacc[4][4] = {};
        #pragma unroll
        for (int d = 0; d < 64; d++) {
            float4 qa = *(float4*)&Qts[d][mrow];
            float4 kv = *(float4*)&KPs[d][ncol];
            float qm[4] = {qa.x, qa.y, qa.z, qa.w};
            #pragma unroll
            for (int i = 0; i < 4; i++) {
                sacc[i][0] += qm[i] * kv.x;
                sacc[i][1] += qm[i] * kv.y;
                sacc[i][2] += qm[i] * kv.z;
                sacc[i][3] += qm[i] * kv.w;
            }
        }
        __syncthreads();

        if (j == qblk) {
            #pragma unroll
            for (int i = 0; i < 4; i++)
                #pragma unroll
                for (int jj = 0; jj < 4; jj++)
                    if (ncol + jj > mrow + i) sacc[i][jj] = -1e30f;
        }

        float p[4][4];
        #pragma unroll
        for (int i = 0; i < 4; i++) {
            float mx = fmaxf(fmaxf(sacc[i][0], sacc[i][1]),
                             fmaxf(sacc[i][2], sacc[i][3]));
            #pragma unroll
            for (int w = 8; w >= 1; w >>= 1)
                mx = fmaxf(mx, __shfl_xor_sync(0xffffffffu, mx, w));
            float m_new = fmaxf(row_max[i], mx);
            float alpha = __expf(row_max[i] - m_new);
            row_max[i] = m_new;
            float ps = 0.f;
            #pragma unroll
            for (int jj = 0; jj < 4; jj++) {
                float e = __expf(sacc[i][jj] - m_new);
                p[i][jj] = e;
                ps += e;
            }
            #pragma unroll
            for (int w = 8; w >= 1; w >>= 1)
                ps += __shfl_xor_sync(0xffffffffu, ps, w);
            row_sum[i] = row_sum[i] * alpha + ps;
            #pragma unroll
            for (int jj = 0; jj < 4; jj++) Oacc[i][jj] *= alpha;
        }

        #pragma unroll
        for (int i = 0; i < 4; i++) {
            float4 r = make_float4(p[i][0], p[i][1], p[i][2], p[i][3]);
            *(float4*)&KPs[mrow + i][ncol] = r;
        }
        __syncthreads();

        #pragma unroll
        for (int s4 = 0; s4 < 16; s4++) {
            float4 pr[4];
            #pragma unroll
            for (int i = 0; i < 4; i++)
                pr[i] = *(float4*)&KPs[mrow + i][s4 * 4];
            #pragma unroll
            for (int ss = 0; ss < 4; ss++) {
                float4 vv = *(float4*)&Vs[s4 * 4 + ss][ncol];
                #pragma unroll
                for (int i = 0; i < 4; i++) {
                    float pv = (ss == 0) ? pr[i].x : (ss == 1) ? pr[i].y
                             : (ss == 2) ? pr[i].z : pr[i].w;
                    Oacc[i][0] += pv * vv.x;
                    Oacc[i][1] += pv * vv.y;
                    Oacc[i][2] += pv * vv.z;
                    Oacc[i][3] += pv * vv.w;
                }
            }
        }
        __syncthreads();
    }

    // normalize + split write to g_att_hi/lo at [b*T+t][h*64+d]
    const int b = bh >> 4;
    const int h = bh & 15;
    #pragma unroll
    for (int i = 0; i < 4; i++) {
        float inv = 1.0f / row_sum[i];
        int t = t0 + mrow + i;
        float f0 = Oacc[i][0] * inv, f1 = Oacc[i][1] * inv;
        float f2 = Oacc[i][2] * inv, f3 = Oacc[i][3] * inv;
        float h0 = __bfloat162float(__float2bfloat16_rn(f0));
        float h1 = __bfloat162float(__float2bfloat16_rn(f1));
        float h2 = __bfloat162float(__float2bfloat16_rn(f2));
        float h3 = __bfloat162float(__float2bfloat16_rn(f3));
        uint2 ph = make_uint2(pack_bf16(f0, f1), pack_bf16(f2, f3));
        uint2 pl = make_uint2(pack_bf16(f0 - h0, f1 - h1), pack_bf16(f2 - h2, f3 - h3));
        size_t off = (size_t)(b * T_ + t) * C_ + h * HS_ + ncol;
        *(uint2*)(g_att_hi + off) = ph;
        *(uint2*)(g_att_lo + off) = pl;
    }
}

// ---------------------------------------------------------------------------
extern "C" void kernel_launch(void* const* d_in, const int* in_sizes, int n_in,
                              void* d_out, int out_size)
{
    const float* x  = (const float*)d_in[0];
    const float* Wq = (const float*)d_in[1];
    const float* Wk = (const float*)d_in[2];
    const float* Wv = (const float*)d_in[3];
    const float* Wp = (const float*)d_in[4];
    const float* bp = (const float*)d_in[5];
    float* out = (float*)d_out;

    cudaFuncSetAttribute(qkv_gemm_kernel,
        cudaFuncAttributeMaxDynamicSharedMemorySize, GEMM_SMEM_TOTAL);
    cudaFuncSetAttribute(proj_gemm_kernel,
        cudaFuncAttributeMaxDynamicSharedMemorySize, GEMM_SMEM_TOTAL);

    conv_x_kernel<<<BT_*C_/1024, 256>>>(x);
    conv_wqkv_kernel<<<dim3(16, 48), 256>>>(Wq, Wk, Wv);
    conv_wp_kernel<<<dim3(16, 16), 256>>>(Wp);
    qkv_gemm_kernel<<<dim3(NQKV_/128, BT_/128), 256, GEMM_SMEM_TOTAL>>>();
    attn_kernel<<<dim3(T_/64, B_*H_), 256>>>();
    proj_gemm_kernel<<<dim3(C_/128, BT_/128), 256, GEMM_SMEM_TOTAL>>>(bp, out);
}

// round 4
// speedup vs baseline: 2.7087x; 1.8014x over previous
#include <cuda_runtime.h>
#include <cuda_bf16.h>
#include <math.h>
#include <stdint.h>

// Problem constants
#define B_ 4
#define T_ 2048
#define C_ 1024
#define H_ 16
#define HS_ 64
#define BT_ (B_*T_)      // 8192
#define NQKV_ 3072       // 3*H*HS
#define NBH_ (B_*H_)     // 64

// ---------------------------------------------------------------------------
// Scratch (device globals: allocation-free rule)
// ---------------------------------------------------------------------------
__device__ __nv_bfloat16 g_x_hi[BT_*C_];
__device__ __nv_bfloat16 g_x_lo[BT_*C_];
__device__ __nv_bfloat16 g_wqkv_hi[NQKV_*C_];   // [n=mat*1024+h*64+d][c]  K-major
__device__ __nv_bfloat16 g_wqkv_lo[NQKV_*C_];
__device__ __nv_bfloat16 g_wp_hi[C_*C_];        // [n][k] K-major (transposed Wp)
__device__ __nv_bfloat16 g_wp_lo[C_*C_];
__device__ __nv_bfloat16 g_q_hi[NBH_*T_*HS_];   // [bh][t][d], pre-scaled by 1/32
__device__ __nv_bfloat16 g_q_lo[NBH_*T_*HS_];
__device__ __nv_bfloat16 g_k_hi[NBH_*T_*HS_];   // [bh][s][d]
__device__ __nv_bfloat16 g_k_lo[NBH_*T_*HS_];
__device__ float         g_v  [NBH_*T_*HS_];    // fp32, [bh][s][d]
__device__ __nv_bfloat16 g_vt_hi[NBH_*HS_*T_];  // [bh][d][s]  (V transposed)
__device__ __nv_bfloat16 g_vt_lo[NBH_*HS_*T_];
__device__ __nv_bfloat16 g_att_hi[BT_*C_];      // attention output hi/lo bf16
__device__ __nv_bfloat16 g_att_lo[BT_*C_];

// ---------------------------------------------------------------------------
// Portable (compute_100-safe) tensor-core primitives: ldmatrix + mma.sync
// ---------------------------------------------------------------------------
__device__ __forceinline__ uint32_t smem_to_u32(const void* p) {
    uint32_t a;
    asm("{ .reg .u64 t; cvta.to.shared.u64 t, %1; cvt.u32.u64 %0, t; }"
        : "=r"(a) : "l"(p));
    return a;
}

__device__ __forceinline__ void ldsm_x4(uint32_t* r, uint32_t addr) {
    asm volatile("ldmatrix.sync.aligned.m8n8.x4.shared.b16 {%0,%1,%2,%3}, [%4];\n"
        : "=r"(r[0]), "=r"(r[1]), "=r"(r[2]), "=r"(r[3]) : "r"(addr));
}

__device__ __forceinline__ void mma_bf16(float* c, const uint32_t* a, const uint32_t* b) {
    asm volatile(
        "mma.sync.aligned.m16n8k16.row.col.f32.bf16.bf16.f32 "
        "{%0,%1,%2,%3}, {%4,%5,%6,%7}, {%8,%9}, {%0,%1,%2,%3};\n"
        : "+f"(c[0]), "+f"(c[1]), "+f"(c[2]), "+f"(c[3])
        : "r"(a[0]), "r"(a[1]), "r"(a[2]), "r"(a[3]), "r"(b[0]), "r"(b[1]));
}

__device__ __forceinline__ void cp16(uint32_t dst, const void* src) {
    asm volatile("cp.async.cg.shared.global [%0], [%1], 16;\n" :: "r"(dst), "l"(src));
}
__device__ __forceinline__ void cp_commit() {
    asm volatile("cp.async.commit_group;\n" ::: "memory");
}
template <int N>
__device__ __forceinline__ void cp_wait() {
    asm volatile("cp.async.wait_group %0;\n" :: "n"(N) : "memory");
}

__device__ __forceinline__ uint32_t pack_bf16(float a, float b) {
    __nv_bfloat162 t = __floats2bfloat162_rn(a, b);
    return *(uint32_t*)&t;
}
__device__ __forceinline__ uint32_t lo_pack(float a, float b) {
    float ra = a - __bfloat162float(__float2bfloat16_rn(a));
    float rb = b - __bfloat162float(__float2bfloat16_rn(b));
    return pack_bf16(ra, rb);
}

// ---------------------------------------------------------------------------
// Conversion kernels
// ---------------------------------------------------------------------------
__global__ __launch_bounds__(256) void conv_x_kernel(const float* __restrict__ x)
{
    size_t idx = (size_t)blockIdx.x * 256 + threadIdx.x;   // float4 index
    float4 a = *(const float4*)(x + idx * 4);
    uint2 ph = make_uint2(pack_bf16(a.x, a.y), pack_bf16(a.z, a.w));
    uint2 pl = make_uint2(lo_pack(a.x, a.y), lo_pack(a.z, a.w));
    *(uint2*)(g_x_hi + idx * 4) = ph;
    *(uint2*)(g_x_lo + idx * 4) = pl;
}

// 64x64 transpose-convert tile: in [64 rows x 64 cols] row-major (stride
// in_stride floats); out[c][r] hi/lo at given stride (bf16).
__device__ __forceinline__ void transpose_tile(
    const float* __restrict__ in, int in_stride,
    __nv_bfloat16* __restrict__ oh, __nv_bfloat16* __restrict__ ol,
    size_t out_stride, float (*sm)[68])
{
    const int tid = threadIdx.x;
    #pragma unroll
    for (int it = 0; it < 4; it++) {
        int v = tid + it * 256;
        int r = v >> 4, c4 = (v & 15) * 4;
        float4 a = *(const float4*)(in + (size_t)r * in_stride + c4);
        sm[r][c4] = a.x; sm[r][c4 + 1] = a.y; sm[r][c4 + 2] = a.z; sm[r][c4 + 3] = a.w;
    }
    __syncthreads();
    #pragma unroll
    for (int it = 0; it < 4; it++) {
        int v = tid + it * 256;
        int d = v >> 4, r4 = (v & 15) * 4;
        float f0 = sm[r4][d], f1 = sm[r4 + 1][d], f2 = sm[r4 + 2][d], f3 = sm[r4 + 3][d];
        uint2 ph = make_uint2(pack_bf16(f0, f1), pack_bf16(f2, f3));
        uint2 pl = make_uint2(lo_pack(f0, f1), lo_pack(f2, f3));
        *(uint2*)(oh + (size_t)d * out_stride + r4) = ph;
        *(uint2*)(ol + (size_t)d * out_stride + r4) = pl;
    }
}

// Wq/Wk/Wv [H][C][HS] -> g_wqkv [mat*1024 + h*64 + d][c]
__global__ __launch_bounds__(256) void conv_wqkv_kernel(
    const float* __restrict__ Wq, const float* __restrict__ Wk,
    const float* __restrict__ Wv)
{
    __shared__ float sm[64][68];
    const int c0 = blockIdx.x * 64;
    const int g  = blockIdx.y;        // 0..47
    const int mat = g >> 4, h = g & 15;
    const float* Wsel = (mat == 0 ? Wq : (mat == 1 ? Wk : Wv));
    const float* in = Wsel + (size_t)h * C_ * HS_ + (size_t)c0 * HS_;
    size_t ob = (size_t)(mat * 1024 + h * 64) * C_ + c0;
    transpose_tile(in, HS_, g_wqkv_hi + ob, g_wqkv_lo + ob, C_, sm);
}

// Wp [C][C] (k rows, n cols) -> g_wp [n][k]
__global__ __launch_bounds__(256) void conv_wp_kernel(const float* __restrict__ Wp)
{
    __shared__ float sm[64][68];
    const int k0 = blockIdx.x * 64;
    const int n0 = blockIdx.y * 64;
    const float* in = Wp + (size_t)k0 * C_ + n0;
    size_t ob = (size_t)n0 * C_ + k0;
    transpose_tile(in, C_, g_wp_hi + ob, g_wp_lo + ob, C_, sm);
}

// g_v [bh][s][d] -> g_vt_hi/lo [bh][d][s]
__global__ __launch_bounds__(256) void conv_vt_kernel()
{
    __shared__ float sm[64][68];
    const int s0 = blockIdx.x * 64;
    const int bh = blockIdx.y;
    const float* in = g_v + ((size_t)bh * T_ + s0) * HS_;
    size_t ob = (size_t)bh * HS_ * T_ + s0;
    transpose_tile(in, HS_, g_vt_hi + ob, g_vt_lo + ob, T_, sm);
}

// ---------------------------------------------------------------------------
// bf16x3 GEMM mainloop (mma.sync) — unchanged structure from round 3.
// ---------------------------------------------------------------------------
#define STAGE_BYTES 32768
#define GEMM_SMEM_TOTAL (2*STAGE_BYTES)

__device__ __forceinline__ void load_stage(
    uint32_t sb, int s,
    const __nv_bfloat16* __restrict__ Ah, const __nv_bfloat16* __restrict__ Al,
    const __nv_bfloat16* __restrict__ Bh, const __nv_bfloat16* __restrict__ Bl,
    int m0, int n0, int k0, int tid)
{
    uint32_t abase = sb + s * STAGE_BYTES;
    uint32_t bbase = abase + 16384;
    #pragma unroll
    for (int it = 0; it < 4; it++) {
        int cid = tid + it * 256;         // 0..1023
        int r = cid >> 3, c = cid & 7;
        uint32_t off = (uint32_t)(r * 128 + ((c ^ (r & 7)) << 4));
        const __nv_bfloat16* srcA =
            (c < 4 ? Ah : Al) + (size_t)(m0 + r) * 1024 + k0 + (c & 3) * 8;
        cp16(abase + off, srcA);
        const __nv_bfloat16* srcB =
            (c < 4 ? Bh : Bl) + (size_t)(n0 + r) * 1024 + k0 + (c & 3) * 8;
        cp16(bbase + off, srcB);
    }
}

__device__ __forceinline__ void compute_stage(
    uint32_t sb, int s, int wm, int wn, int lane,
    float acc[4][4][4])
{
    uint32_t abase = sb + s * STAGE_BYTES;
    uint32_t bbase = abase + 16384;
    const int jlow  = (lane >> 3) & 1;
    const int jhigh = lane >> 4;
    const int rsub  = lane & 7;

    #pragma unroll
    for (int ks = 0; ks < 2; ks++) {
        uint32_t a_hi[4][4], a_lo[4][4];
        #pragma unroll
        for (int mi = 0; mi < 4; mi++) {
            int row = wm + 16 * mi + jlow * 8 + rsub;
            int ch  = 2 * ks + jhigh;
            uint32_t base = abase + row * 128;
            ldsm_x4(a_hi[mi], base + (uint32_t)(((ch)     ^ (row & 7)) << 4));
            ldsm_x4(a_lo[mi], base + (uint32_t)(((ch + 4) ^ (row & 7)) << 4));
        }
        uint32_t b_hi[4][2], b_lo[4][2];
        #pragma unroll
        for (int nb = 0; nb < 2; nb++) {
            int row = wn + 16 * nb + jlow * 8 + rsub;
            int ch  = 2 * ks + jhigh;
            uint32_t base = bbase + row * 128;
            uint32_t t[4];
            ldsm_x4(t, base + (uint32_t)(((ch)     ^ (row & 7)) << 4));
            b_hi[2*nb][0] = t[0]; b_hi[2*nb+1][0] = t[1];
            b_hi[2*nb][1] = t[2]; b_hi[2*nb+1][1] = t[3];
            ldsm_x4(t, base + (uint32_t)(((ch + 4) ^ (row & 7)) << 4));
            b_lo[2*nb][0] = t[0]; b_lo[2*nb+1][0] = t[1];
            b_lo[2*nb][1] = t[2]; b_lo[2*nb+1][1] = t[3];
        }
        #pragma unroll
        for (int mi = 0; mi < 4; mi++)
            #pragma unroll
            for (int ni = 0; ni < 4; ni++)
                mma_bf16(acc[mi][ni], a_hi[mi], b_hi[ni]);
        #pragma unroll
        for (int mi = 0; mi < 4; mi++)
            #pragma unroll
            for (int ni = 0; ni < 4; ni++)
                mma_bf16(acc[mi][ni], a_hi[mi], b_lo[ni]);
        #pragma unroll
        for (int mi = 0; mi < 4; mi++)
            #pragma unroll
            for (int ni = 0; ni < 4; ni++)
                mma_bf16(acc[mi][ni], a_lo[mi], b_hi[ni]);
    }
}

__device__ __forceinline__ void gemm_mainloop(
    uint32_t sb,
    const __nv_bfloat16* Ah, const __nv_bfloat16* Al,
    const __nv_bfloat16* Bh, const __nv_bfloat16* Bl,
    int m0, int n0, int wm, int wn, int lane, int tid,
    float acc[4][4][4])
{
    load_stage(sb, 0, Ah, Al, Bh, Bl, m0, n0, 0, tid);
    cp_commit();
    for (int i = 0; i < 32; i++) {
        if (i < 31) {
            load_stage(sb, (i + 1) & 1, Ah, Al, Bh, Bl, m0, n0, (i + 1) * 32, tid);
            cp_commit();
            cp_wait<1>();
        } else {
            cp_wait<0>();
        }
        __syncthreads();
        compute_stage(sb, i & 1, wm, wn, lane, acc);
        __syncthreads();
    }
}

// ---------------------------------------------------------------------------
// QKV GEMM: epilogue writes Q(hi/lo, scaled), K(hi/lo), V(fp32)
// ---------------------------------------------------------------------------
__global__ __launch_bounds__(256, 1) void qkv_gemm_kernel()
{
    extern __shared__ char smem[];
    uint32_t sb = smem_to_u32(smem);
    const int tid = threadIdx.x;
    const int wid = tid >> 5, lane = tid & 31;
    const int n0 = blockIdx.x * 128;
    const int m0 = blockIdx.y * 128;
    const int wm = (wid & 1) * 64;
    const int wn = (wid >> 1) * 32;

    float acc[4][4][4] = {};
    gemm_mainloop(sb, g_x_hi, g_x_lo, g_wqkv_hi, g_wqkv_lo,
                  m0, n0, wm, wn, lane, tid, acc);

    const int b = m0 >> 11;          // whole CTA inside one batch
    #pragma unroll
    for (int mi = 0; mi < 4; mi++) {
        int m = m0 + wm + mi * 16 + (lane >> 2);
        int t = m & (T_ - 1);
        #pragma unroll
        for (int ni = 0; ni < 4; ni++) {
            int n = n0 + wn + ni * 8 + 2 * (lane & 3);
            int mat = n >> 10, h = (n >> 6) & 15, d = n & 63;
            int bh = b * H_ + h;
            size_t off0 = ((size_t)bh * T_ + t) * HS_ + d;
            size_t off1 = off0 + 8 * HS_;
            float c0 = acc[mi][ni][0], c1 = acc[mi][ni][1];
            float c2 = acc[mi][ni][2], c3 = acc[mi][ni][3];
            if (mat == 0) {
                c0 *= 0.03125f; c1 *= 0.03125f; c2 *= 0.03125f; c3 *= 0.03125f;
                *(uint32_t*)(g_q_hi + off0) = pack_bf16(c0, c1);
                *(uint32_t*)(g_q_lo + off0) = lo_pack(c0, c1);
                *(uint32_t*)(g_q_hi + off1) = pack_bf16(c2, c3);
                *(uint32_t*)(g_q_lo + off1) = lo_pack(c2, c3);
            } else if (mat == 1) {
                *(uint32_t*)(g_k_hi + off0) = pack_bf16(c0, c1);
                *(uint32_t*)(g_k_lo + off0) = lo_pack(c0, c1);
                *(uint32_t*)(g_k_hi + off1) = pack_bf16(c2, c3);
                *(uint32_t*)(g_k_lo + off1) = lo_pack(c2, c3);
            } else {
                *(float2*)(g_v + off0) = make_float2(c0, c1);
                *(float2*)(g_v + off1) = make_float2(c2, c3);
            }
        }
    }
}

// ---------------------------------------------------------------------------
// Projection GEMM: out[m][n] = att[m][:] . wp_t[n][:] + bp[n]
// ---------------------------------------------------------------------------
__global__ __launch_bounds__(256, 1) void proj_gemm_kernel(
    const float* __restrict__ bp, float* __restrict__ out)
{
    extern __shared__ char smem[];
    uint32_t sb = smem_to_u32(smem);
    const int tid = threadIdx.x;
    const int wid = tid >> 5, lane = tid & 31;
    const int n0 = blockIdx.x * 128;
    const int m0 = blockIdx.y * 128;
    const int wm = (wid & 1) * 64;
    const int wn = (wid >> 1) * 32;

    float acc[4][4][4] = {};
    gemm_mainloop(sb, g_att_hi, g_att_lo, g_wp_hi, g_wp_lo,
                  m0, n0, wm, wn, lane, tid, acc);

    #pragma unroll
    for (int mi = 0; mi < 4; mi++) {
        int m = m0 + wm + mi * 16 + (lane >> 2);
        #pragma unroll
        for (int ni = 0; ni < 4; ni++) {
            int n = n0 + wn + ni * 8 + 2 * (lane & 3);
            float2 bb = *(const float2*)(bp + n);
            float* dst = out + (size_t)m * C_ + n;
            *(float2*)dst = make_float2(acc[mi][ni][0] + bb.x, acc[mi][ni][1] + bb.y);
            *(float2*)(dst + 8 * C_) = make_float2(acc[mi][ni][2] + bb.x, acc[mi][ni][3] + bb.y);
        }
    }
}

// ---------------------------------------------------------------------------
// Tensor-core causal flash attention.
// CTA: 128 Q rows x one bh. 8 warps, each owns 16 rows.
// KV tiles of 64; 3-stage cp.async pipeline.
// S = Q@K^T and O = P@V both bf16x3 (hi/lo) on mma.sync.
// smem: Q hi/lo 32KB + 3 stages x (K hi/lo + Vt hi/lo = 32KB) = 128KB.
// ---------------------------------------------------------------------------
#define AT_QLO   16384
#define AT_STAGE 32768
#define AT_STAGE_BYTES 32768
#define AT_KLO    8192
#define AT_VHI   16384
#define AT_VLO   24576
#define AT_SMEM_TOTAL (AT_STAGE + 3*AT_STAGE_BYTES)

__device__ __forceinline__ void issue_kv_stage(uint32_t sb, int bh, int stage,
                                               int s0, int tid)
{
    uint32_t st = sb + AT_STAGE + stage * AT_STAGE_BYTES;
    const __nv_bfloat16* kh = g_k_hi + ((size_t)bh * T_ + s0) * HS_;
    const __nv_bfloat16* kl = g_k_lo + ((size_t)bh * T_ + s0) * HS_;
    const __nv_bfloat16* vh = g_vt_hi + (size_t)bh * HS_ * T_ + s0;
    const __nv_bfloat16* vl = g_vt_lo + (size_t)bh * HS_ * T_ + s0;
    #pragma unroll
    for (int it = 0; it < 2; it++) {
        int cid = tid + it * 256;        // 0..511
        int r = cid >> 3, c = cid & 7;
        uint32_t off = (uint32_t)(r * 128 + ((c ^ (r & 7)) << 4));
        cp16(st + off,          kh + (size_t)r * HS_ + c * 8);
        cp16(st + AT_KLO + off, kl + (size_t)r * HS_ + c * 8);
        cp16(st + AT_VHI + off, vh + (size_t)r * T_ + c * 8);
        cp16(st + AT_VLO + off, vl + (size_t)r * T_ + c * 8);
    }
}

__global__ __launch_bounds__(256) void attn2_kernel()
{
    extern __shared__ char smem[];
    uint32_t sb = smem_to_u32(smem);
    const int tid = threadIdx.x;
    const int wid = tid >> 5, lane = tid & 31;
    const int qi = (int)gridDim.x - 1 - (int)blockIdx.x;   // heavy first
    const int bh = blockIdx.y;
    const int t0 = qi * 128;
    const int ntiles = 2 * qi + 2;

    const int jlow = (lane >> 3) & 1, jhigh = lane >> 4, rsub = lane & 7;

    // Prologue: Q hi/lo (128 rows) + stage0 as group0; stage1 as group1.
    {
        const __nv_bfloat16* qh = g_q_hi + ((size_t)bh * T_ + t0) * HS_;
        const __nv_bfloat16* ql = g_q_lo + ((size_t)bh * T_ + t0) * HS_;
        #pragma unroll
        for (int it = 0; it < 4; it++) {
            int cid = tid + it * 256;    // 0..1023
            int r = cid >> 3, c = cid & 7;
            uint32_t off = (uint32_t)(r * 128 + ((c ^ (r & 7)) << 4));
            cp16(sb + off,          qh + (size_t)r * HS_ + c * 8);
            cp16(sb + AT_QLO + off, ql + (size_t)r * HS_ + c * 8);
        }
        issue_kv_stage(sb, bh, 0, 0, tid);
        cp_commit();
        issue_kv_stage(sb, bh, 1, 64, tid);   // ntiles >= 2 always
        cp_commit();
    }

    uint32_t aq_hi[4][4], aq_lo[4][4];
    float O[8][4] = {};
    float rm0 = -1e30f, rm1 = -1e30f, rl0 = 0.f, rl1 = 0.f;

    for (int j = 0; j < ntiles; j++) {
        cp_wait<1>();          // groups <= j complete
        __syncthreads();       // data visible; all warps done with tile j-1

        if (j == 0) {
            // Q a-fragments (loop-invariant)
            #pragma unroll
            for (int kc = 0; kc < 4; kc++) {
                int row = 16 * wid + jlow * 8 + rsub;
                int ch = 2 * kc + jhigh;
                uint32_t sw = (uint32_t)(row * 128 + ((ch ^ (row & 7)) << 4));
                ldsm_x4(aq_hi[kc], sb + sw);
                ldsm_x4(aq_lo[kc], sb + AT_QLO + sw);
            }
        }

        if (j + 2 < ntiles)
            issue_kv_stage(sb, bh, (j + 2) % 3, (j + 2) * 64, tid);
        cp_commit();           // always commit: fixed group arithmetic

        uint32_t kbase = sb + AT_STAGE + (j % 3) * AT_STAGE_BYTES;

        // ---- S = Q @ K^T (bf16x3) ----
        float s[8][4] = {};
        #pragma unroll
        for (int kc = 0; kc < 4; kc++) {
            #pragma unroll
            for (int nbp = 0; nbp < 4; nbp++) {
                int row = 16 * nbp + jlow * 8 + rsub;
                uint32_t sw = (uint32_t)(row * 128 +
                              (((2 * kc + jhigh) ^ (row & 7)) << 4));
                uint32_t t4[4];
                ldsm_x4(t4, kbase + sw);                   // K hi
                uint32_t b0[2] = {t4[0], t4[2]}, b1[2] = {t4[1], t4[3]};
                mma_bf16(s[2*nbp],   aq_hi[kc], b0);
                mma_bf16(s[2*nbp+1], aq_hi[kc], b1);
                mma_bf16(s[2*nbp],   aq_lo[kc], b0);
                mma_bf16(s[2*nbp+1], aq_lo[kc], b1);
                ldsm_x4(t4, kbase + AT_KLO + sw);          // K lo
                uint32_t c0[2] = {t4[0], t4[2]}, c1[2] = {t4[1], t4[3]};
                mma_bf16(s[2*nbp],   aq_hi[kc], c0);
                mma_bf16(s[2*nbp+1], aq_hi[kc], c1);
            }
        }

        // ---- causal mask (last two tiles only) ----
        const int grow0 = t0 + 16 * wid + (lane >> 2);
        if (j >= ntiles - 2) {
            int s0 = j * 64;
            #pragma unroll
            for (int j8 = 0; j8 < 8; j8++) {
                int col = s0 + j8 * 8 + 2 * (lane & 3);
                if (col     > grow0)     s[j8][0] = -1e30f;
                if (col + 1 > grow0)     s[j8][1] = -1e30f;
                if (col     > grow0 + 8) s[j8][2] = -1e30f;
                if (col + 1 > grow0 + 8) s[j8][3] = -1e30f;
            }
        }

        // ---- online softmax (rows r0 = grow0, r1 = grow0+8) ----
        float mx0 = -1e30f, mx1 = -1e30f;
        #pragma unroll
        for (int j8 = 0; j8 < 8; j8++) {
            mx0 = fmaxf(mx0, fmaxf(s[j8][0], s[j8][1]));
            mx1 = fmaxf(mx1, fmaxf(s[j8][2], s[j8][3]));
        }
        mx0 = fmaxf(mx0, __shfl_xor_sync(0xffffffffu, mx0, 1));
        mx0 = fmaxf(mx0, __shfl_xor_sync(0xffffffffu, mx0, 2));
        mx1 = fmaxf(mx1, __shfl_xor_sync(0xffffffffu, mx1, 1));
        mx1 = fmaxf(mx1, __shfl_xor_sync(0xffffffffu, mx1, 2));
        float mn0 = fmaxf(rm0, mx0), mn1 = fmaxf(rm1, mx1);
        float al0 = __expf(rm0 - mn0), al1 = __expf(rm1 - mn1);
        rm0 = mn0; rm1 = mn1;
        float sum0 = 0.f, sum1 = 0.f;
        #pragma unroll
        for (int j8 = 0; j8 < 8; j8++) {
            s[j8][0] = __expf(s[j8][0] - mn0); sum0 += s[j8][0];
            s[j8][1] = __expf(s[j8][1] - mn0); sum0 += s[j8][1];
            s[j8][2] = __expf(s[j8][2] - mn1); sum1 += s[j8][2];
            s[j8][3] = __expf(s[j8][3] - mn1); sum1 += s[j8][3];
        }
        sum0 += __shfl_xor_sync(0xffffffffu, sum0, 1);
        sum0 += __shfl_xor_sync(0xffffffffu, sum0, 2);
        sum1 += __shfl_xor_sync(0xffffffffu, sum1, 1);
        sum1 += __shfl_xor_sync(0xffffffffu, sum1, 2);
        rl0 = rl0 * al0 + sum0;
        rl1 = rl1 * al1 + sum1;
        #pragma unroll
        for (int j8 = 0; j8 < 8; j8++) {
            O[j8][0] *= al0; O[j8][1] *= al0;
            O[j8][2] *= al1; O[j8][3] *= al1;
        }

        // ---- P fragments (C-layout -> A-layout identity) ----
        uint32_t pa_hi[4][4], pa_lo[4][4];
        #pragma unroll
        for (int kc = 0; kc < 4; kc++) {
            pa_hi[kc][0] = pack_bf16(s[2*kc][0],   s[2*kc][1]);
            pa_hi[kc][1] = pack_bf16(s[2*kc][2],   s[2*kc][3]);
            pa_hi[kc][2] = pack_bf16(s[2*kc+1][0], s[2*kc+1][1]);
            pa_hi[kc][3] = pack_bf16(s[2*kc+1][2], s[2*kc+1][3]);
            pa_lo[kc][0] = lo_pack(s[2*kc][0],   s[2*kc][1]);
            pa_lo[kc][1] = lo_pack(s[2*kc][2],   s[2*kc][3]);
            pa_lo[kc][2] = lo_pack(s[2*kc+1][0], s[2*kc+1][1]);
            pa_lo[kc][3] = lo_pack(s[2*kc+1][2], s[2*kc+1][3]);
        }

        // ---- O += P @ V  (Vt rows = d, cols = s; bf16x3) ----
        uint32_t vbase = kbase + AT_VHI;
        #pragma unroll
        for (int kc = 0; kc < 4; kc++) {
            #pragma unroll
            for (int nbp = 0; nbp < 4; nbp++) {
                int row = 16 * nbp + jlow * 8 + rsub;
                uint32_t sw = (uint32_t)(row * 128 +
                              (((2 * kc + jhigh) ^ (row & 7)) << 4));
                uint32_t t4[4];
                ldsm_x4(t4, vbase + sw);                   // Vt hi
                uint32_t b0[2] = {t4[0], t4[2]}, b1[2] = {t4[1], t4[3]};
                mma_bf16(O[2*nbp],   pa_hi[kc], b0);
                mma_bf16(O[2*nbp+1], pa_hi[kc], b1);
                mma_bf16(O[2*nbp],   pa_lo[kc], b0);
                mma_bf16(O[2*nbp+1], pa_lo[kc], b1);
                ldsm_x4(t4, vbase + 8192 + sw);            // Vt lo
                uint32_t c0[2] = {t4[0], t4[2]}, c1[2] = {t4[1], t4[3]};
                mma_bf16(O[2*nbp],   pa_hi[kc], c0);
                mma_bf16(O[2*nbp+1], pa_hi[kc], c1);
            }
        }
    }

    // ---- epilogue: normalize, hi/lo split, write g_att ----
    float inv0 = 1.0f / rl0, inv1 = 1.0f / rl1;
    const int b = bh >> 4, h = bh & 15;
    const int trow = t0 + 16 * wid + (lane >> 2);
    size_t base0 = ((size_t)(b * T_) + trow) * C_ + h * HS_;
    size_t base1 = base0 + (size_t)8 * C_;
    #pragma unroll
    for (int j8 = 0; j8 < 8; j8++) {
        int d = j8 * 8 + 2 * (lane & 3);
        float f0 = O[j8][0] * inv0, f1 = O[j8][1] * inv0;
        float f2 = O[j8][2] * inv1, f3 = O[j8][3] * inv1;
        *(uint32_t*)(g_att_hi + base0 + d) = pack_bf16(f0, f1);
        *(uint32_t*)(g_att_lo + base0 + d) = lo_pack(f0, f1);
        *(uint32_t*)(g_att_hi + base1 + d) = pack_bf16(f2, f3);
        *(uint32_t*)(g_att_lo + base1 + d) = lo_pack(f2, f3);
    }
}

// ---------------------------------------------------------------------------
extern "C" void kernel_launch(void* const* d_in, const int* in_sizes, int n_in,
                              void* d_out, int out_size)
{
    const float* x  = (const float*)d_in[0];
    const float* Wq = (const float*)d_in[1];
    const float* Wk = (const float*)d_in[2];
    const float* Wv = (const float*)d_in[3];
    const float* Wp = (const float*)d_in[4];
    const float* bp = (const float*)d_in[5];
    float* out = (float*)d_out;

    cudaFuncSetAttribute(qkv_gemm_kernel,
        cudaFuncAttributeMaxDynamicSharedMemorySize, GEMM_SMEM_TOTAL);
    cudaFuncSetAttribute(proj_gemm_kernel,
        cudaFuncAttributeMaxDynamicSharedMemorySize, GEMM_SMEM_TOTAL);
    cudaFuncSetAttribute(attn2_kernel,
        cudaFuncAttributeMaxDynamicSharedMemorySize, AT_SMEM_TOTAL);

    conv_x_kernel<<<BT_*C_/1024, 256>>>(x);
    conv_wqkv_kernel<<<dim3(16, 48), 256>>>(Wq, Wk, Wv);
    conv_wp_kernel<<<dim3(16, 16), 256>>>(Wp);
    qkv_gemm_kernel<<<dim3(NQKV_/128, BT_/128), 256, GEMM_SMEM_TOTAL>>>();
    conv_vt_kernel<<<dim3(T_/64, NBH_), 256>>>();
    attn2_kernel<<<dim3(T_/128, NBH_), 256, AT_SMEM_TOTAL>>>();
    proj_gemm_kernel<<<dim3(C_/128, BT_/128), 256, GEMM_SMEM_TOTAL>>>(bp, out);
}

// round 5
// speedup vs baseline: 2.8879x; 1.0662x over previous
#include <cuda_runtime.h>
#include <cuda_bf16.h>
#include <math.h>
#include <stdint.h>

// Problem constants
#define B_ 4
#define T_ 2048
#define C_ 1024
#define H_ 16
#define HS_ 64
#define BT_ (B_*T_)      // 8192
#define NQKV_ 3072       // 3*H*HS
#define NBH_ (B_*H_)     // 64

// ---------------------------------------------------------------------------
// Scratch (device globals: allocation-free rule)
// ---------------------------------------------------------------------------
__device__ __nv_bfloat16 g_x_hi[BT_*C_];
__device__ __nv_bfloat16 g_x_lo[BT_*C_];
__device__ __nv_bfloat16 g_wqkv_hi[NQKV_*C_];   // [n=mat*1024+h*64+d][c]  K-major
__device__ __nv_bfloat16 g_wqkv_lo[NQKV_*C_];
__device__ __nv_bfloat16 g_wp_hi[C_*C_];        // [n][k] K-major (transposed Wp)
__device__ __nv_bfloat16 g_wp_lo[C_*C_];
__device__ __nv_bfloat16 g_q_hi[NBH_*T_*HS_];   // [bh][t][d], pre-scaled by 1/32
__device__ __nv_bfloat16 g_q_lo[NBH_*T_*HS_];
__device__ __nv_bfloat16 g_k_hi[NBH_*T_*HS_];   // [bh][s][d]
__device__ __nv_bfloat16 g_k_lo[NBH_*T_*HS_];
__device__ float         g_v  [NBH_*T_*HS_];    // fp32, [bh][s][d]
__device__ __nv_bfloat16 g_vt_hi[NBH_*HS_*T_];  // [bh][d][s]  (V transposed)
__device__ __nv_bfloat16 g_vt_lo[NBH_*HS_*T_];
__device__ __nv_bfloat16 g_att_hi[BT_*C_];      // attention output hi/lo bf16
__device__ __nv_bfloat16 g_att_lo[BT_*C_];

// ---------------------------------------------------------------------------
// Portable (compute_100-safe) tensor-core primitives: ldmatrix + mma.sync
// ---------------------------------------------------------------------------
__device__ __forceinline__ uint32_t smem_to_u32(const void* p) {
    uint32_t a;
    asm("{ .reg .u64 t; cvta.to.shared.u64 t, %1; cvt.u32.u64 %0, t; }"
        : "=r"(a) : "l"(p));
    return a;
}

__device__ __forceinline__ void ldsm_x4(uint32_t* r, uint32_t addr) {
    asm volatile("ldmatrix.sync.aligned.m8n8.x4.shared.b16 {%0,%1,%2,%3}, [%4];\n"
        : "=r"(r[0]), "=r"(r[1]), "=r"(r[2]), "=r"(r[3]) : "r"(addr));
}

__device__ __forceinline__ void mma_bf16(float* c, const uint32_t* a, const uint32_t* b) {
    asm volatile(
        "mma.sync.aligned.m16n8k16.row.col.f32.bf16.bf16.f32 "
        "{%0,%1,%2,%3}, {%4,%5,%6,%7}, {%8,%9}, {%0,%1,%2,%3};\n"
        : "+f"(c[0]), "+f"(c[1]), "+f"(c[2]), "+f"(c[3])
        : "r"(a[0]), "r"(a[1]), "r"(a[2]), "r"(a[3]), "r"(b[0]), "r"(b[1]));
}

__device__ __forceinline__ void cp16(uint32_t dst, const void* src) {
    asm volatile("cp.async.cg.shared.global [%0], [%1], 16;\n" :: "r"(dst), "l"(src));
}
__device__ __forceinline__ void cp_commit() {
    asm volatile("cp.async.commit_group;\n" ::: "memory");
}
template <int N>
__device__ __forceinline__ void cp_wait() {
    asm volatile("cp.async.wait_group %0;\n" :: "n"(N) : "memory");
}

__device__ __forceinline__ uint32_t pack_bf16(float a, float b) {
    __nv_bfloat162 t = __floats2bfloat162_rn(a, b);
    return *(uint32_t*)&t;
}
__device__ __forceinline__ uint32_t lo_pack(float a, float b) {
    float ra = a - __bfloat162float(__float2bfloat16_rn(a));
    float rb = b - __bfloat162float(__float2bfloat16_rn(b));
    return pack_bf16(ra, rb);
}

// ---------------------------------------------------------------------------
// Conversion kernels
// ---------------------------------------------------------------------------
__global__ __launch_bounds__(256) void conv_x_kernel(const float* __restrict__ x)
{
    size_t idx = (size_t)blockIdx.x * 256 + threadIdx.x;   // float4 index
    float4 a = *(const float4*)(x + idx * 4);
    uint2 ph = make_uint2(pack_bf16(a.x, a.y), pack_bf16(a.z, a.w));
    uint2 pl = make_uint2(lo_pack(a.x, a.y), lo_pack(a.z, a.w));
    *(uint2*)(g_x_hi + idx * 4) = ph;
    *(uint2*)(g_x_lo + idx * 4) = pl;
}

// 64x64 transpose-convert tile
__device__ __forceinline__ void transpose_tile(
    const float* __restrict__ in, int in_stride,
    __nv_bfloat16* __restrict__ oh, __nv_bfloat16* __restrict__ ol,
    size_t out_stride, float (*sm)[68])
{
    const int tid = threadIdx.x;
    #pragma unroll
    for (int it = 0; it < 4; it++) {
        int v = tid + it * 256;
        int r = v >> 4, c4 = (v & 15) * 4;
        float4 a = *(const float4*)(in + (size_t)r * in_stride + c4);
        sm[r][c4] = a.x; sm[r][c4 + 1] = a.y; sm[r][c4 + 2] = a.z; sm[r][c4 + 3] = a.w;
    }
    __syncthreads();
    #pragma unroll
    for (int it = 0; it < 4; it++) {
        int v = tid + it * 256;
        int d = v >> 4, r4 = (v & 15) * 4;
        float f0 = sm[r4][d], f1 = sm[r4 + 1][d], f2 = sm[r4 + 2][d], f3 = sm[r4 + 3][d];
        uint2 ph = make_uint2(pack_bf16(f0, f1), pack_bf16(f2, f3));
        uint2 pl = make_uint2(lo_pack(f0, f1), lo_pack(f2, f3));
        *(uint2*)(oh + (size_t)d * out_stride + r4) = ph;
        *(uint2*)(ol + (size_t)d * out_stride + r4) = pl;
    }
}

__global__ __launch_bounds__(256) void conv_wqkv_kernel(
    const float* __restrict__ Wq, const float* __restrict__ Wk,
    const float* __restrict__ Wv)
{
    __shared__ float sm[64][68];
    const int c0 = blockIdx.x * 64;
    const int g  = blockIdx.y;        // 0..47
    const int mat = g >> 4, h = g & 15;
    const float* Wsel = (mat == 0 ? Wq : (mat == 1 ? Wk : Wv));
    const float* in = Wsel + (size_t)h * C_ * HS_ + (size_t)c0 * HS_;
    size_t ob = (size_t)(mat * 1024 + h * 64) * C_ + c0;
    transpose_tile(in, HS_, g_wqkv_hi + ob, g_wqkv_lo + ob, C_, sm);
}

__global__ __launch_bounds__(256) void conv_wp_kernel(const float* __restrict__ Wp)
{
    __shared__ float sm[64][68];
    const int k0 = blockIdx.x * 64;
    const int n0 = blockIdx.y * 64;
    const float* in = Wp + (size_t)k0 * C_ + n0;
    size_t ob = (size_t)n0 * C_ + k0;
    transpose_tile(in, C_, g_wp_hi + ob, g_wp_lo + ob, C_, sm);
}

__global__ __launch_bounds__(256) void conv_vt_kernel()
{
    __shared__ float sm[64][68];
    const int s0 = blockIdx.x * 64;
    const int bh = blockIdx.y;
    const float* in = g_v + ((size_t)bh * T_ + s0) * HS_;
    size_t ob = (size_t)bh * HS_ * T_ + s0;
    transpose_tile(in, HS_, g_vt_hi + ob, g_vt_lo + ob, T_, sm);
}

// ---------------------------------------------------------------------------
// bf16x3 GEMM mainloop (mma.sync).
// CTA 128x128, K-chunk 32, 3-stage cp.async pipeline (96 KB smem).
// 2 CTAs/SM (<=128 regs via a-fragment reuse).
// ---------------------------------------------------------------------------
#define STAGE_BYTES 32768
#define NSTAGE 3
#define GEMM_SMEM_TOTAL (NSTAGE*STAGE_BYTES)

__device__ __forceinline__ void load_stage(
    uint32_t sb, int s,
    const __nv_bfloat16* __restrict__ Ah, const __nv_bfloat16* __restrict__ Al,
    const __nv_bfloat16* __restrict__ Bh, const __nv_bfloat16* __restrict__ Bl,
    int m0, int n0, int k0, int tid)
{
    uint32_t abase = sb + s * STAGE_BYTES;
    uint32_t bbase = abase + 16384;
    #pragma unroll
    for (int it = 0; it < 4; it++) {
        int cid = tid + it * 256;         // 0..1023
        int r = cid >> 3, c = cid & 7;
        uint32_t off = (uint32_t)(r * 128 + ((c ^ (r & 7)) << 4));
        const __nv_bfloat16* srcA =
            (c < 4 ? Ah : Al) + (size_t)(m0 + r) * 1024 + k0 + (c & 3) * 8;
        cp16(abase + off, srcA);
        const __nv_bfloat16* srcB =
            (c < 4 ? Bh : Bl) + (size_t)(n0 + r) * 1024 + k0 + (c & 3) * 8;
        cp16(bbase + off, srcB);
    }
}

// Register-lean compute: b hi+lo resident (16 regs), one shared a array (16
// regs) reused hi -> lo.  Per ks: a_hi*b_hi, a_hi*b_lo, then a_lo*b_hi.
__device__ __forceinline__ void compute_stage(
    uint32_t abase, uint32_t bbase, int wm, int wn, int lane,
    float acc[4][4][4])
{
    const int jlow  = (lane >> 3) & 1;
    const int jhigh = lane >> 4;
    const int rsub  = lane & 7;

    #pragma unroll
    for (int ks = 0; ks < 2; ks++) {
        const int ch = 2 * ks + jhigh;
        uint32_t b_hi[4][2], b_lo[4][2];
        #pragma unroll
        for (int nb = 0; nb < 2; nb++) {
            int row = wn + 16 * nb + jlow * 8 + rsub;
            uint32_t base = bbase + row * 128;
            uint32_t t[4];
            ldsm_x4(t, base + (uint32_t)(((ch)     ^ (row & 7)) << 4));
            b_hi[2*nb][0] = t[0]; b_hi[2*nb+1][0] = t[1];
            b_hi[2*nb][1] = t[2]; b_hi[2*nb+1][1] = t[3];
            ldsm_x4(t, base + (uint32_t)(((ch + 4) ^ (row & 7)) << 4));
            b_lo[2*nb][0] = t[0]; b_lo[2*nb+1][0] = t[1];
            b_lo[2*nb][1] = t[2]; b_lo[2*nb+1][1] = t[3];
        }
        uint32_t a[4][4];
        #pragma unroll
        for (int mi = 0; mi < 4; mi++) {
            int row = wm + 16 * mi + jlow * 8 + rsub;
            ldsm_x4(a[mi], abase + row * 128 +
                    (uint32_t)(((ch) ^ (row & 7)) << 4));
        }
        #pragma unroll
        for (int mi = 0; mi < 4; mi++)
            #pragma unroll
            for (int ni = 0; ni < 4; ni++)
                mma_bf16(acc[mi][ni], a[mi], b_hi[ni]);
        #pragma unroll
        for (int mi = 0; mi < 4; mi++)
            #pragma unroll
            for (int ni = 0; ni < 4; ni++)
                mma_bf16(acc[mi][ni], a[mi], b_lo[ni]);
        #pragma unroll
        for (int mi = 0; mi < 4; mi++) {
            int row = wm + 16 * mi + jlow * 8 + rsub;
            ldsm_x4(a[mi], abase + row * 128 +
                    (uint32_t)(((ch + 4) ^ (row & 7)) << 4));
        }
        #pragma unroll
        for (int mi = 0; mi < 4; mi++)
            #pragma unroll
            for (int ni = 0; ni < 4; ni++)
                mma_bf16(acc[mi][ni], a[mi], b_hi[ni]);
    }
}

__device__ __forceinline__ void gemm_mainloop(
    uint32_t sb,
    const __nv_bfloat16* Ah, const __nv_bfloat16* Al,
    const __nv_bfloat16* Bh, const __nv_bfloat16* Bl,
    int m0, int n0, int wm, int wn, int lane, int tid,
    float acc[4][4][4])
{
    load_stage(sb, 0, Ah, Al, Bh, Bl, m0, n0, 0, tid);
    cp_commit();
    load_stage(sb, 1, Ah, Al, Bh, Bl, m0, n0, 32, tid);
    cp_commit();
    #pragma unroll 1
    for (int i = 0; i < 32; i++) {
        if (i < 31) cp_wait<1>(); else cp_wait<0>();
        __syncthreads();          // stage i ready; all warps done with i-1
        if (i + 2 < 32) {
            load_stage(sb, (i + 2) % NSTAGE, Ah, Al, Bh, Bl, m0, n0,
                       (i + 2) * 32, tid);
            cp_commit();
        }
        uint32_t abase = sb + (i % NSTAGE) * STAGE_BYTES;
        compute_stage(abase, abase + 16384, wm, wn, lane, acc);
    }
}

// ---------------------------------------------------------------------------
// QKV GEMM: epilogue writes Q(hi/lo, scaled), K(hi/lo), V(fp32)
// ---------------------------------------------------------------------------
__global__ __launch_bounds__(256, 2) void qkv_gemm_kernel()
{
    extern __shared__ char smem[];
    uint32_t sb = smem_to_u32(smem);
    const int tid = threadIdx.x;
    const int wid = tid >> 5, lane = tid & 31;
    const int n0 = blockIdx.x * 128;
    const int m0 = blockIdx.y * 128;
    const int wm = (wid & 1) * 64;
    const int wn = (wid >> 1) * 32;

    float acc[4][4][4] = {};
    gemm_mainloop(sb, g_x_hi, g_x_lo, g_wqkv_hi, g_wqkv_lo,
                  m0, n0, wm, wn, lane, tid, acc);

    const int b = m0 >> 11;          // whole CTA inside one batch
    #pragma unroll
    for (int mi = 0; mi < 4; mi++) {
        int m = m0 + wm + mi * 16 + (lane >> 2);
        int t = m & (T_ - 1);
        #pragma unroll
        for (int ni = 0; ni < 4; ni++) {
            int n = n0 + wn + ni * 8 + 2 * (lane & 3);
            int mat = n >> 10, h = (n >> 6) & 15, d = n & 63;
            int bh = b * H_ + h;
            size_t off0 = ((size_t)bh * T_ + t) * HS_ + d;
            size_t off1 = off0 + 8 * HS_;
            float c0 = acc[mi][ni][0], c1 = acc[mi][ni][1];
            float c2 = acc[mi][ni][2], c3 = acc[mi][ni][3];
            if (mat == 0) {
                c0 *= 0.03125f; c1 *= 0.03125f; c2 *= 0.03125f; c3 *= 0.03125f;
                *(uint32_t*)(g_q_hi + off0) = pack_bf16(c0, c1);
                *(uint32_t*)(g_q_lo + off0) = lo_pack(c0, c1);
                *(uint32_t*)(g_q_hi + off1) = pack_bf16(c2, c3);
                *(uint32_t*)(g_q_lo + off1) = lo_pack(c2, c3);
            } else if (mat == 1) {
                *(uint32_t*)(g_k_hi + off0) = pack_bf16(c0, c1);
                *(uint32_t*)(g_k_lo + off0) = lo_pack(c0, c1);
                *(uint32_t*)(g_k_hi + off1) = pack_bf16(c2, c3);
                *(uint32_t*)(g_k_lo + off1) = lo_pack(c2, c3);
            } else {
                *(float2*)(g_v + off0) = make_float2(c0, c1);
                *(float2*)(g_v + off1) = make_float2(c2, c3);
            }
        }
    }
}

// ---------------------------------------------------------------------------
// Projection GEMM: out[m][n] = att[m][:] . wp_t[n][:] + bp[n]
// ---------------------------------------------------------------------------
__global__ __launch_bounds__(256, 2) void proj_gemm_kernel(
    const float* __restrict__ bp, float* __restrict__ out)
{
    extern __shared__ char smem[];
    uint32_t sb = smem_to_u32(smem);
    const int tid = threadIdx.x;
    const int wid = tid >> 5, lane = tid & 31;
    const int n0 = blockIdx.x * 128;
    const int m0 = blockIdx.y * 128;
    const int wm = (wid & 1) * 64;
    const int wn = (wid >> 1) * 32;

    float acc[4][4][4] = {};
    gemm_mainloop(sb, g_att_hi, g_att_lo, g_wp_hi, g_wp_lo,
                  m0, n0, wm, wn, lane, tid, acc);

    #pragma unroll
    for (int mi = 0; mi < 4; mi++) {
        int m = m0 + wm + mi * 16 + (lane >> 2);
        #pragma unroll
        for (int ni = 0; ni < 4; ni++) {
            int n = n0 + wn + ni * 8 + 2 * (lane & 3);
            float2 bb = *(const float2*)(bp + n);
            float* dst = out + (size_t)m * C_ + n;
            *(float2*)dst = make_float2(acc[mi][ni][0] + bb.x, acc[mi][ni][1] + bb.y);
            *(float2*)(dst + 8 * C_) = make_float2(acc[mi][ni][2] + bb.x, acc[mi][ni][3] + bb.y);
        }
    }
}

// ---------------------------------------------------------------------------
// Tensor-core causal flash attention (unchanged from round 4).
// ---------------------------------------------------------------------------
#define AT_QLO   16384
#define AT_STAGE 32768
#define AT_STAGE_BYTES 32768
#define AT_KLO    8192
#define AT_VHI   16384
#define AT_VLO   24576
#define AT_SMEM_TOTAL (AT_STAGE + 3*AT_STAGE_BYTES)

__device__ __forceinline__ void issue_kv_stage(uint32_t sb, int bh, int stage,
                                               int s0, int tid)
{
    uint32_t st = sb + AT_STAGE + stage * AT_STAGE_BYTES;
    const __nv_bfloat16* kh = g_k_hi + ((size_t)bh * T_ + s0) * HS_;
    const __nv_bfloat16* kl = g_k_lo + ((size_t)bh * T_ + s0) * HS_;
    const __nv_bfloat16* vh = g_vt_hi + (size_t)bh * HS_ * T_ + s0;
    const __nv_bfloat16* vl = g_vt_lo + (size_t)bh * HS_ * T_ + s0;
    #pragma unroll
    for (int it = 0; it < 2; it++) {
        int cid = tid + it * 256;        // 0..511
        int r = cid >> 3, c = cid & 7;
        uint32_t off = (uint32_t)(r * 128 + ((c ^ (r & 7)) << 4));
        cp16(st + off,          kh + (size_t)r * HS_ + c * 8);
        cp16(st + AT_KLO + off, kl + (size_t)r * HS_ + c * 8);
        cp16(st + AT_VHI + off, vh + (size_t)r * T_ + c * 8);
        cp16(st + AT_VLO + off, vl + (size_t)r * T_ + c * 8);
    }
}

__global__ __launch_bounds__(256) void attn2_kernel()
{
    extern __shared__ char smem[];
    uint32_t sb = smem_to_u32(smem);
    const int tid = threadIdx.x;
    const int wid = tid >> 5, lane = tid & 31;
    const int qi = (int)gridDim.x - 1 - (int)blockIdx.x;   // heavy first
    const int bh = blockIdx.y;
    const int t0 = qi * 128;
    const int ntiles = 2 * qi + 2;

    const int jlow = (lane >> 3) & 1, jhigh = lane >> 4, rsub = lane & 7;

    {
        const __nv_bfloat16* qh = g_q_hi + ((size_t)bh * T_ + t0) * HS_;
        const __nv_bfloat16* ql = g_q_lo + ((size_t)bh * T_ + t0) * HS_;
        #pragma unroll
        for (int it = 0; it < 4; it++) {
            int cid = tid + it * 256;    // 0..1023
            int r = cid >> 3, c = cid & 7;
            uint32_t off = (uint32_t)(r * 128 + ((c ^ (r & 7)) << 4));
            cp16(sb + off,          qh + (size_t)r * HS_ + c * 8);
            cp16(sb + AT_QLO + off, ql + (size_t)r * HS_ + c * 8);
        }
        issue_kv_stage(sb, bh, 0, 0, tid);
        cp_commit();
        issue_kv_stage(sb, bh, 1, 64, tid);
        cp_commit();
    }

    uint32_t aq_hi[4][4], aq_lo[4][4];
    float O[8][4] = {};
    float rm0 = -1e30f, rm1 = -1e30f, rl0 = 0.f, rl1 = 0.f;

    for (int j = 0; j < ntiles; j++) {
        cp_wait<1>();
        __syncthreads();

        if (j == 0) {
            #pragma unroll
            for (int kc = 0; kc < 4; kc++) {
                int row = 16 * wid + jlow * 8 + rsub;
                int ch = 2 * kc + jhigh;
                uint32_t sw = (uint32_t)(row * 128 + ((ch ^ (row & 7)) << 4));
                ldsm_x4(aq_hi[kc], sb + sw);
                ldsm_x4(aq_lo[kc], sb + AT_QLO + sw);
            }
        }

        if (j + 2 < ntiles)
            issue_kv_stage(sb, bh, (j + 2) % 3, (j + 2) * 64, tid);
        cp_commit();

        uint32_t kbase = sb + AT_STAGE + (j % 3) * AT_STAGE_BYTES;

        float s[8][4] = {};
        #pragma unroll
        for (int kc = 0; kc < 4; kc++) {
            #pragma unroll
            for (int nbp = 0; nbp < 4; nbp++) {
                int row = 16 * nbp + jlow * 8 + rsub;
                uint32_t sw = (uint32_t)(row * 128 +
                              (((2 * kc + jhigh) ^ (row & 7)) << 4));
                uint32_t t4[4];
                ldsm_x4(t4, kbase + sw);
                uint32_t b0[2] = {t4[0], t4[2]}, b1[2] = {t4[1], t4[3]};
                mma_bf16(s[2*nbp],   aq_hi[kc], b0);
                mma_bf16(s[2*nbp+1], aq_hi[kc], b1);
                mma_bf16(s[2*nbp],   aq_lo[kc], b0);
                mma_bf16(s[2*nbp+1], aq_lo[kc], b1);
                ldsm_x4(t4, kbase + AT_KLO + sw);
                uint32_t c0[2] = {t4[0], t4[2]}, c1[2] = {t4[1], t4[3]};
                mma_bf16(s[2*nbp],   aq_hi[kc], c0);
                mma_bf16(s[2*nbp+1], aq_hi[kc], c1);
            }
        }

        const int grow0 = t0 + 16 * wid + (lane >> 2);
        if (j >= ntiles - 2) {
            int s0 = j * 64;
            #pragma unroll
            for (int j8 = 0; j8 < 8; j8++) {
                int col = s0 + j8 * 8 + 2 * (lane & 3);
                if (col     > grow0)     s[j8][0] = -1e30f;
                if (col + 1 > grow0)     s[j8][1] = -1e30f;
                if (col     > grow0 + 8) s[j8][2] = -1e30f;
                if (col + 1 > grow0 + 8) s[j8][3] = -1e30f;
            }
        }

        float mx0 = -1e30f, mx1 = -1e30f;
        #pragma unroll
        for (int j8 = 0; j8 < 8; j8++) {
            mx0 = fmaxf(mx0, fmaxf(s[j8][0], s[j8][1]));
            mx1 = fmaxf(mx1, fmaxf(s[j8][2], s[j8][3]));
        }
        mx0 = fmaxf(mx0, __shfl_xor_sync(0xffffffffu, mx0, 1));
        mx0 = fmaxf(mx0, __shfl_xor_sync(0xffffffffu, mx0, 2));
        mx1 = fmaxf(mx1, __shfl_xor_sync(0xffffffffu, mx1, 1));
        mx1 = fmaxf(mx1, __shfl_xor_sync(0xffffffffu, mx1, 2));
        float mn0 = fmaxf(rm0, mx0), mn1 = fmaxf(rm1, mx1);
        float al0 = __expf(rm0 - mn0), al1 = __expf(rm1 - mn1);
        rm0 = mn0; rm1 = mn1;
        float sum0 = 0.f, sum1 = 0.f;
        #pragma unroll
        for (int j8 = 0; j8 < 8; j8++) {
            s[j8][0] = __expf(s[j8][0] - mn0); sum0 += s[j8][0];
            s[j8][1] = __expf(s[j8][1] - mn0); sum0 += s[j8][1];
            s[j8][2] = __expf(s[j8][2] - mn1); sum1 += s[j8][2];
            s[j8][3] = __expf(s[j8][3] - mn1); sum1 += s[j8][3];
        }
        sum0 += __shfl_xor_sync(0xffffffffu, sum0, 1);
        sum0 += __shfl_xor_sync(0xffffffffu, sum0, 2);
        sum1 += __shfl_xor_sync(0xffffffffu, sum1, 1);
        sum1 += __shfl_xor_sync(0xffffffffu, sum1, 2);
        rl0 = rl0 * al0 + sum0;
        rl1 = rl1 * al1 + sum1;
        #pragma unroll
        for (int j8 = 0; j8 < 8; j8++) {
            O[j8][0] *= al0; O[j8][1] *= al0;
            O[j8][2] *= al1; O[j8][3] *= al1;
        }

        uint32_t pa_hi[4][4], pa_lo[4][4];
        #pragma unroll
        for (int kc = 0; kc < 4; kc++) {
            pa_hi[kc][0] = pack_bf16(s[2*kc][0],   s[2*kc][1]);
            pa_hi[kc][1] = pack_bf16(s[2*kc][2],   s[2*kc][3]);
            pa_hi[kc][2] = pack_bf16(s[2*kc+1][0], s[2*kc+1][1]);
            pa_hi[kc][3] = pack_bf16(s[2*kc+1][2], s[2*kc+1][3]);
            pa_lo[kc][0] = lo_pack(s[2*kc][0],   s[2*kc][1]);
            pa_lo[kc][1] = lo_pack(s[2*kc][2],   s[2*kc][3]);
            pa_lo[kc][2] = lo_pack(s[2*kc+1][0], s[2*kc+1][1]);
            pa_lo[kc][3] = lo_pack(s[2*kc+1][2], s[2*kc+1][3]);
        }

        uint32_t vbase = kbase + AT_VHI;
        #pragma unroll
        for (int kc = 0; kc < 4; kc++) {
            #pragma unroll
            for (int nbp = 0; nbp < 4; nbp++) {
                int row = 16 * nbp + jlow * 8 + rsub;
                uint32_t sw = (uint32_t)(row * 128 +
                              (((2 * kc + jhigh) ^ (row & 7)) << 4));
                uint32_t t4[4];
                ldsm_x4(t4, vbase + sw);
                uint32_t b0[2] = {t4[0], t4[2]}, b1[2] = {t4[1], t4[3]};
                mma_bf16(O[2*nbp],   pa_hi[kc], b0);
                mma_bf16(O[2*nbp+1], pa_hi[kc], b1);
                mma_bf16(O[2*nbp],   pa_lo[kc], b0);
                mma_bf16(O[2*nbp+1], pa_lo[kc], b1);
                ldsm_x4(t4, vbase + 8192 + sw);
                uint32_t c0[2] = {t4[0], t4[2]}, c1[2] = {t4[1], t4[3]};
                mma_bf16(O[2*nbp],   pa_hi[kc], c0);
                mma_bf16(O[2*nbp+1], pa_hi[kc], c1);
            }
        }
    }

    float inv0 = 1.0f / rl0, inv1 = 1.0f / rl1;
    const int b = bh >> 4, h = bh & 15;
    const int trow = t0 + 16 * wid + (lane >> 2);
    size_t base0 = ((size_t)(b * T_) + trow) * C_ + h * HS_;
    size_t base1 = base0 + (size_t)8 * C_;
    #pragma unroll
    for (int j8 = 0; j8 < 8; j8++) {
        int d = j8 * 8 + 2 * (lane & 3);
        float f0 = O[j8][0] * inv0, f1 = O[j8][1] * inv0;
        float f2 = O[j8][2] * inv1, f3 = O[j8][3] * inv1;
        *(uint32_t*)(g_att_hi + base0 + d) = pack_bf16(f0, f1);
        *(uint32_t*)(g_att_lo + base0 + d) = lo_pack(f0, f1);
        *(uint32_t*)(g_att_hi + base1 + d) = pack_bf16(f2, f3);
        *(uint32_t*)(g_att_lo + base1 + d) = lo_pack(f2, f3);
    }
}

// ---------------------------------------------------------------------------
extern "C" void kernel_launch(void* const* d_in, const int* in_sizes, int n_in,
                              void* d_out, int out_size)
{
    const float* x  = (const float*)d_in[0];
    const float* Wq = (const float*)d_in[1];
    const float* Wk = (const float*)d_in[2];
    const float* Wv = (const float*)d_in[3];
    const float* Wp = (const float*)d_in[4];
    const float* bp = (const float*)d_in[5];
    float* out = (float*)d_out;

    cudaFuncSetAttribute(qkv_gemm_kernel,
        cudaFuncAttributeMaxDynamicSharedMemorySize, GEMM_SMEM_TOTAL);
    cudaFuncSetAttribute(proj_gemm_kernel,
        cudaFuncAttributeMaxDynamicSharedMemorySize, GEMM_SMEM_TOTAL);
    cudaFuncSetAttribute(attn2_kernel,
        cudaFuncAttributeMaxDynamicSharedMemorySize, AT_SMEM_TOTAL);

    conv_x_kernel<<<BT_*C_/1024, 256>>>(x);
    conv_wqkv_kernel<<<dim3(16, 48), 256>>>(Wq, Wk, Wv);
    conv_wp_kernel<<<dim3(16, 16), 256>>>(Wp);
    qkv_gemm_kernel<<<dim3(NQKV_/128, BT_/128), 256, GEMM_SMEM_TOTAL>>>();
    conv_vt_kernel<<<dim3(T_/64, NBH_), 256>>>();
    attn2_kernel<<<dim3(T_/128, NBH_), 256, AT_SMEM_TOTAL>>>();
    proj_gemm_kernel<<<dim3(C_/128, BT_/128), 256, GEMM_SMEM_TOTAL>>>(bp, out);
}

// round 6
// speedup vs baseline: 4.1291x; 1.4298x over previous
#include <cuda_runtime.h>
#include <cuda_fp16.h>
#include <math.h>
#include <stdint.h>

// Problem constants
#define B_ 4
#define T_ 2048
#define C_ 1024
#define H_ 16
#define HS_ 64
#define BT_ (B_*T_)      // 8192
#define NQKV_ 3072       // 3*H*HS
#define NBH_ (B_*H_)     // 64

// ---------------------------------------------------------------------------
// Scratch (device globals: allocation-free rule)
// ---------------------------------------------------------------------------
__device__ __half g_x_hi[BT_*C_];
__device__ __half g_x_lo[BT_*C_];
__device__ __half g_wqkv[NQKV_*C_];     // [n=mat*1024+h*64+d][c] K-major, single
__device__ __half g_wp[C_*C_];          // [n][k] K-major (transposed Wp), single
__device__ __half g_q_hi[NBH_*T_*HS_];  // [bh][t][d], pre-scaled by 1/32
__device__ __half g_q_lo[NBH_*T_*HS_];
__device__ __half g_k  [NBH_*T_*HS_];   // [bh][s][d], single fp16
__device__ float  g_v  [NBH_*T_*HS_];   // fp32, [bh][s][d]
__device__ __half g_vt_hi[NBH_*HS_*T_]; // [bh][d][s]  (V transposed, hi/lo)
__device__ __half g_vt_lo[NBH_*HS_*T_];
__device__ __half g_att_hi[BT_*C_];     // attention output hi/lo fp16
__device__ __half g_att_lo[BT_*C_];

// ---------------------------------------------------------------------------
// Portable (compute_100-safe) tensor-core primitives
// ---------------------------------------------------------------------------
__device__ __forceinline__ uint32_t smem_to_u32(const void* p) {
    uint32_t a;
    asm("{ .reg .u64 t; cvta.to.shared.u64 t, %1; cvt.u32.u64 %0, t; }"
        : "=r"(a) : "l"(p));
    return a;
}

__device__ __forceinline__ void ldsm_x4(uint32_t* r, uint32_t addr) {
    asm volatile("ldmatrix.sync.aligned.m8n8.x4.shared.b16 {%0,%1,%2,%3}, [%4];\n"
        : "=r"(r[0]), "=r"(r[1]), "=r"(r[2]), "=r"(r[3]) : "r"(addr));
}

__device__ __forceinline__ void mma_f16(float* c, const uint32_t* a, const uint32_t* b) {
    asm volatile(
        "mma.sync.aligned.m16n8k16.row.col.f32.f16.f16.f32 "
        "{%0,%1,%2,%3}, {%4,%5,%6,%7}, {%8,%9}, {%0,%1,%2,%3};\n"
        : "+f"(c[0]), "+f"(c[1]), "+f"(c[2]), "+f"(c[3])
        : "r"(a[0]), "r"(a[1]), "r"(a[2]), "r"(a[3]), "r"(b[0]), "r"(b[1]));
}

__device__ __forceinline__ void cp16(uint32_t dst, const void* src) {
    asm volatile("cp.async.cg.shared.global [%0], [%1], 16;\n" :: "r"(dst), "l"(src));
}
__device__ __forceinline__ void cp_commit() {
    asm volatile("cp.async.commit_group;\n" ::: "memory");
}
template <int N>
__device__ __forceinline__ void cp_wait() {
    asm volatile("cp.async.wait_group %0;\n" :: "n"(N) : "memory");
}

__device__ __forceinline__ uint32_t pack_h(float a, float b) {
    __half2 t = __floats2half2_rn(a, b);
    return *(uint32_t*)&t;
}
__device__ __forceinline__ uint32_t lo_pack_h(float a, float b) {
    float ra = a - __half2float(__float2half_rn(a));
    float rb = b - __half2float(__float2half_rn(b));
    return pack_h(ra, rb);
}

// ---------------------------------------------------------------------------
// Conversion kernels
// ---------------------------------------------------------------------------
__global__ __launch_bounds__(256) void conv_x_kernel(const float* __restrict__ x)
{
    size_t idx = (size_t)blockIdx.x * 256 + threadIdx.x;   // float4 index
    float4 a = *(const float4*)(x + idx * 4);
    uint2 ph = make_uint2(pack_h(a.x, a.y), pack_h(a.z, a.w));
    uint2 pl = make_uint2(lo_pack_h(a.x, a.y), lo_pack_h(a.z, a.w));
    *(uint2*)(g_x_hi + idx * 4) = ph;
    *(uint2*)(g_x_lo + idx * 4) = pl;
}

// 64x64 transpose-convert tile, single fp16 output
__device__ __forceinline__ void transpose_tile_s(
    const float* __restrict__ in, int in_stride,
    __half* __restrict__ oh, size_t out_stride, float (*sm)[68])
{
    const int tid = threadIdx.x;
    #pragma unroll
    for (int it = 0; it < 4; it++) {
        int v = tid + it * 256;
        int r = v >> 4, c4 = (v & 15) * 4;
        float4 a = *(const float4*)(in + (size_t)r * in_stride + c4);
        sm[r][c4] = a.x; sm[r][c4 + 1] = a.y; sm[r][c4 + 2] = a.z; sm[r][c4 + 3] = a.w;
    }
    __syncthreads();
    #pragma unroll
    for (int it = 0; it < 4; it++) {
        int v = tid + it * 256;
        int d = v >> 4, r4 = (v & 15) * 4;
        float f0 = sm[r4][d], f1 = sm[r4 + 1][d], f2 = sm[r4 + 2][d], f3 = sm[r4 + 3][d];
        uint2 ph = make_uint2(pack_h(f0, f1), pack_h(f2, f3));
        *(uint2*)(oh + (size_t)d * out_stride + r4) = ph;
    }
}

// 64x64 transpose-convert tile, hi/lo fp16 output
__device__ __forceinline__ void transpose_tile_hl(
    const float* __restrict__ in, int in_stride,
    __half* __restrict__ oh, __half* __restrict__ ol,
    size_t out_stride, float (*sm)[68])
{
    const int tid = threadIdx.x;
    #pragma unroll
    for (int it = 0; it < 4; it++) {
        int v = tid + it * 256;
        int r = v >> 4, c4 = (v & 15) * 4;
        float4 a = *(const float4*)(in + (size_t)r * in_stride + c4);
        sm[r][c4] = a.x; sm[r][c4 + 1] = a.y; sm[r][c4 + 2] = a.z; sm[r][c4 + 3] = a.w;
    }
    __syncthreads();
    #pragma unroll
    for (int it = 0; it < 4; it++) {
        int v = tid + it * 256;
        int d = v >> 4, r4 = (v & 15) * 4;
        float f0 = sm[r4][d], f1 = sm[r4 + 1][d], f2 = sm[r4 + 2][d], f3 = sm[r4 + 3][d];
        *(uint2*)(oh + (size_t)d * out_stride + r4) =
            make_uint2(pack_h(f0, f1), pack_h(f2, f3));
        *(uint2*)(ol + (size_t)d * out_stride + r4) =
            make_uint2(lo_pack_h(f0, f1), lo_pack_h(f2, f3));
    }
}

__global__ __launch_bounds__(256) void conv_wqkv_kernel(
    const float* __restrict__ Wq, const float* __restrict__ Wk,
    const float* __restrict__ Wv)
{
    __shared__ float sm[64][68];
    const int c0 = blockIdx.x * 64;
    const int g  = blockIdx.y;        // 0..47
    const int mat = g >> 4, h = g & 15;
    const float* Wsel = (mat == 0 ? Wq : (mat == 1 ? Wk : Wv));
    const float* in = Wsel + (size_t)h * C_ * HS_ + (size_t)c0 * HS_;
    size_t ob = (size_t)(mat * 1024 + h * 64) * C_ + c0;
    transpose_tile_s(in, HS_, g_wqkv + ob, C_, sm);
}

__global__ __launch_bounds__(256) void conv_wp_kernel(const float* __restrict__ Wp)
{
    __shared__ float sm[64][68];
    const int k0 = blockIdx.x * 64;
    const int n0 = blockIdx.y * 64;
    const float* in = Wp + (size_t)k0 * C_ + n0;
    size_t ob = (size_t)n0 * C_ + k0;
    transpose_tile_s(in, C_, g_wp + ob, C_, sm);
}

__global__ __launch_bounds__(256) void conv_vt_kernel()
{
    __shared__ float sm[64][68];
    const int s0 = blockIdx.x * 64;
    const int bh = blockIdx.y;
    const float* in = g_v + ((size_t)bh * T_ + s0) * HS_;
    size_t ob = (size_t)bh * HS_ * T_ + s0;
    transpose_tile_hl(in, HS_, g_vt_hi + ob, g_vt_lo + ob, T_, sm);
}

// ---------------------------------------------------------------------------
// fp16 2-pass GEMM mainloop (mma.sync).
// CTA 128x128, K-chunk 32, 4-stage cp.async pipeline (96 KB smem), 2 CTAs/SM.
// Stage: A (hi cols 0-31, lo 32-63; 128B rows, 16KB) + B (single, 64B rows, 8KB).
// ---------------------------------------------------------------------------
#define ST_BYTES 24576
#define NST 4
#define GEMM_SMEM_TOTAL (NST*ST_BYTES)   // 98304

__device__ __forceinline__ void load_stage(
    uint32_t sb, int s,
    const __half* __restrict__ Ah, const __half* __restrict__ Al,
    const __half* __restrict__ Bs,
    int m0, int n0, int k0, int tid)
{
    uint32_t abase = sb + s * ST_BYTES;
    uint32_t bbase = abase + 16384;
    #pragma unroll
    for (int it = 0; it < 4; it++) {
        int cid = tid + it * 256;         // 0..1023
        int r = cid >> 3, c = cid & 7;
        uint32_t off = (uint32_t)(r * 128 + ((c ^ (r & 7)) << 4));
        const __half* srcA =
            (c < 4 ? Ah : Al) + (size_t)(m0 + r) * 1024 + k0 + (c & 3) * 8;
        cp16(abase + off, srcA);
    }
    #pragma unroll
    for (int it = 0; it < 2; it++) {
        int cid = tid + it * 256;         // 0..511
        int r = cid >> 2, c = cid & 3;
        uint32_t off = (uint32_t)(r * 64 + ((c ^ (r & 3)) << 4));
        cp16(bbase + off, Bs + (size_t)(n0 + r) * 1024 + k0 + c * 8);
    }
}

__device__ __forceinline__ void compute_stage(
    uint32_t abase, uint32_t bbase, int wm, int wn, int lane,
    float acc[4][4][4])
{
    const int jlow  = (lane >> 3) & 1;
    const int jhigh = lane >> 4;
    const int rsub  = lane & 7;

    #pragma unroll
    for (int ks = 0; ks < 2; ks++) {
        const int ch = 2 * ks + jhigh;     // 0..3
        uint32_t b[4][2];
        #pragma unroll
        for (int nb = 0; nb < 2; nb++) {
            int row = wn + 16 * nb + jlow * 8 + rsub;
            uint32_t t[4];
            ldsm_x4(t, bbase + (uint32_t)(row * 64 + ((ch ^ (row & 3)) << 4)));
            b[2*nb][0] = t[0]; b[2*nb+1][0] = t[1];
            b[2*nb][1] = t[2]; b[2*nb+1][1] = t[3];
        }
        uint32_t a[4][4];
        #pragma unroll
        for (int mi = 0; mi < 4; mi++) {
            int row = wm + 16 * mi + jlow * 8 + rsub;
            ldsm_x4(a[mi], abase + (uint32_t)(row * 128 + ((ch ^ (row & 7)) << 4)));
        }
        #pragma unroll
        for (int mi = 0; mi < 4; mi++)
            #pragma unroll
            for (int ni = 0; ni < 4; ni++)
                mma_f16(acc[mi][ni], a[mi], b[ni]);
        #pragma unroll
        for (int mi = 0; mi < 4; mi++) {
            int row = wm + 16 * mi + jlow * 8 + rsub;
            ldsm_x4(a[mi], abase + (uint32_t)(row * 128 + (((ch + 4) ^ (row & 7)) << 4)));
        }
        #pragma unroll
        for (int mi = 0; mi < 4; mi++)
            #pragma unroll
            for (int ni = 0; ni < 4; ni++)
                mma_f16(acc[mi][ni], a[mi], b[ni]);
    }
}

__device__ __forceinline__ void gemm_mainloop(
    uint32_t sb,
    const __half* Ah, const __half* Al, const __half* Bs,
    int m0, int n0, int wm, int wn, int lane, int tid,
    float acc[4][4][4])
{
    load_stage(sb, 0, Ah, Al, Bs, m0, n0, 0, tid);   cp_commit();
    load_stage(sb, 1, Ah, Al, Bs, m0, n0, 32, tid);  cp_commit();
    load_stage(sb, 2, Ah, Al, Bs, m0, n0, 64, tid);  cp_commit();
    #pragma unroll 1
    for (int i = 0; i < 32; i++) {
        if (i < 30)       cp_wait<2>();
        else if (i == 30) cp_wait<1>();
        else              cp_wait<0>();
        __syncthreads();          // stage i ready; all warps done with stage i-4's slot
        if (i + 3 < 32) {
            load_stage(sb, (i + 3) % NST, Ah, Al, Bs, m0, n0, (i + 3) * 32, tid);
            cp_commit();
        }
        uint32_t abase = sb + (i % NST) * ST_BYTES;
        compute_stage(abase, abase + 16384, wm, wn, lane, acc);
    }
}

// ---------------------------------------------------------------------------
// QKV GEMM: epilogue writes Q(hi/lo fp16, scaled), K(single fp16), V(fp32)
// ---------------------------------------------------------------------------
__global__ __launch_bounds__(256, 2) void qkv_gemm_kernel()
{
    extern __shared__ char smem[];
    uint32_t sb = smem_to_u32(smem);
    const int tid = threadIdx.x;
    const int wid = tid >> 5, lane = tid & 31;
    const int n0 = blockIdx.x * 128;
    const int m0 = blockIdx.y * 128;
    const int wm = (wid & 1) * 64;
    const int wn = (wid >> 1) * 32;

    float acc[4][4][4] = {};
    gemm_mainloop(sb, g_x_hi, g_x_lo, g_wqkv, m0, n0, wm, wn, lane, tid, acc);

    const int b = m0 >> 11;          // whole CTA inside one batch
    #pragma unroll
    for (int mi = 0; mi < 4; mi++) {
        int m = m0 + wm + mi * 16 + (lane >> 2);
        int t = m & (T_ - 1);
        #pragma unroll
        for (int ni = 0; ni < 4; ni++) {
            int n = n0 + wn + ni * 8 + 2 * (lane & 3);
            int mat = n >> 10, h = (n >> 6) & 15, d = n & 63;
            int bh = b * H_ + h;
            size_t off0 = ((size_t)bh * T_ + t) * HS_ + d;
            size_t off1 = off0 + 8 * HS_;
            float c0 = acc[mi][ni][0], c1 = acc[mi][ni][1];
            float c2 = acc[mi][ni][2], c3 = acc[mi][ni][3];
            if (mat == 0) {
                c0 *= 0.03125f; c1 *= 0.03125f; c2 *= 0.03125f; c3 *= 0.03125f;
                *(uint32_t*)(g_q_hi + off0) = pack_h(c0, c1);
                *(uint32_t*)(g_q_lo + off0) = lo_pack_h(c0, c1);
                *(uint32_t*)(g_q_hi + off1) = pack_h(c2, c3);
                *(uint32_t*)(g_q_lo + off1) = lo_pack_h(c2, c3);
            } else if (mat == 1) {
                *(uint32_t*)(g_k + off0) = pack_h(c0, c1);
                *(uint32_t*)(g_k + off1) = pack_h(c2, c3);
            } else {
                *(float2*)(g_v + off0) = make_float2(c0, c1);
                *(float2*)(g_v + off1) = make_float2(c2, c3);
            }
        }
    }
}

// ---------------------------------------------------------------------------
// Projection GEMM: out[m][n] = att[m][:] . wp_t[n][:] + bp[n]
// ---------------------------------------------------------------------------
__global__ __launch_bounds__(256, 2) void proj_gemm_kernel(
    const float* __restrict__ bp, float* __restrict__ out)
{
    extern __shared__ char smem[];
    uint32_t sb = smem_to_u32(smem);
    const int tid = threadIdx.x;
    const int wid = tid >> 5, lane = tid & 31;
    const int n0 = blockIdx.x * 128;
    const int m0 = blockIdx.y * 128;
    const int wm = (wid & 1) * 64;
    const int wn = (wid >> 1) * 32;

    float acc[4][4][4] = {};
    gemm_mainloop(sb, g_att_hi, g_att_lo, g_wp, m0, n0, wm, wn, lane, tid, acc);

    #pragma unroll
    for (int mi = 0; mi < 4; mi++) {
        int m = m0 + wm + mi * 16 + (lane >> 2);
        #pragma unroll
        for (int ni = 0; ni < 4; ni++) {
            int n = n0 + wn + ni * 8 + 2 * (lane & 3);
            float2 bb = *(const float2*)(bp + n);
            float* dst = out + (size_t)m * C_ + n;
            *(float2*)dst = make_float2(acc[mi][ni][0] + bb.x, acc[mi][ni][1] + bb.y);
            *(float2*)(dst + 8 * C_) = make_float2(acc[mi][ni][2] + bb.x, acc[mi][ni][3] + bb.y);
        }
    }
}

// ---------------------------------------------------------------------------
// Tensor-core causal flash attention, fp16 2-pass.
// CTA: 128 Q rows x one bh. Q hi/lo split; K single; P single; V hi/lo split.
// KV tiles of 64; 3-stage cp.async pipeline.
// smem: Q hi/lo 32KB + 3 x (K 8KB + Vt hi 8KB + Vt lo 8KB) = 104KB.
// ---------------------------------------------------------------------------
#define AT_QLO   16384
#define AT_STAGE 32768
#define AT_STAGE_BYTES 24576
#define AT_VHI    8192
#define AT_VLO   16384
#define AT_SMEM_TOTAL (AT_STAGE + 3*AT_STAGE_BYTES)   // 106496

__device__ __forceinline__ void issue_kv_stage(uint32_t sb, int bh, int stage,
                                               int s0, int tid)
{
    uint32_t st = sb + AT_STAGE + stage * AT_STAGE_BYTES;
    const __half* kk = g_k    + ((size_t)bh * T_ + s0) * HS_;
    const __half* vh = g_vt_hi + (size_t)bh * HS_ * T_ + s0;
    const __half* vl = g_vt_lo + (size_t)bh * HS_ * T_ + s0;
    #pragma unroll
    for (int it = 0; it < 2; it++) {
        int cid = tid + it * 256;        // 0..511
        int r = cid >> 3, c = cid & 7;
        uint32_t off = (uint32_t)(r * 128 + ((c ^ (r & 7)) << 4));
        cp16(st + off,          kk + (size_t)r * HS_ + c * 8);
        cp16(st + AT_VHI + off, vh + (size_t)r * T_ + c * 8);
        cp16(st + AT_VLO + off, vl + (size_t)r * T_ + c * 8);
    }
}

__global__ __launch_bounds__(256) void attn2_kernel()
{
    extern __shared__ char smem[];
    uint32_t sb = smem_to_u32(smem);
    const int tid = threadIdx.x;
    const int wid = tid >> 5, lane = tid & 31;
    const int qi = (int)gridDim.x - 1 - (int)blockIdx.x;   // heavy first
    const int bh = blockIdx.y;
    const int t0 = qi * 128;
    const int ntiles = 2 * qi + 2;

    const int jlow = (lane >> 3) & 1, jhigh = lane >> 4, rsub = lane & 7;

    {
        const __half* qh = g_q_hi + ((size_t)bh * T_ + t0) * HS_;
        const __half* ql = g_q_lo + ((size_t)bh * T_ + t0) * HS_;
        #pragma unroll
        for (int it = 0; it < 4; it++) {
            int cid = tid + it * 256;    // 0..1023
            int r = cid >> 3, c = cid & 7;
            uint32_t off = (uint32_t)(r * 128 + ((c ^ (r & 7)) << 4));
            cp16(sb + off,          qh + (size_t)r * HS_ + c * 8);
            cp16(sb + AT_QLO + off, ql + (size_t)r * HS_ + c * 8);
        }
        issue_kv_stage(sb, bh, 0, 0, tid);
        cp_commit();
        issue_kv_stage(sb, bh, 1, 64, tid);
        cp_commit();
    }

    uint32_t aq_hi[4][4], aq_lo[4][4];
    float O[8][4] = {};
    float rm0 = -1e30f, rm1 = -1e30f, rl0 = 0.f, rl1 = 0.f;

    for (int j = 0; j < ntiles; j++) {
        cp_wait<1>();
        __syncthreads();

        if (j == 0) {
            #pragma unroll
            for (int kc = 0; kc < 4; kc++) {
                int row = 16 * wid + jlow * 8 + rsub;
                int ch = 2 * kc + jhigh;
                uint32_t sw = (uint32_t)(row * 128 + ((ch ^ (row & 7)) << 4));
                ldsm_x4(aq_hi[kc], sb + sw);
                ldsm_x4(aq_lo[kc], sb + AT_QLO + sw);
            }
        }

        if (j + 2 < ntiles)
            issue_kv_stage(sb, bh, (j + 2) % 3, (j + 2) * 64, tid);
        cp_commit();

        uint32_t kbase = sb + AT_STAGE + (j % 3) * AT_STAGE_BYTES;

        // ---- S = Q @ K^T (Q hi/lo x K single) ----
        float s[8][4] = {};
        #pragma unroll
        for (int kc = 0; kc < 4; kc++) {
            #pragma unroll
            for (int nbp = 0; nbp < 4; nbp++) {
                int row = 16 * nbp + jlow * 8 + rsub;
                uint32_t sw = (uint32_t)(row * 128 +
                              (((2 * kc + jhigh) ^ (row & 7)) << 4));
                uint32_t t4[4];
                ldsm_x4(t4, kbase + sw);
                uint32_t b0[2] = {t4[0], t4[2]}, b1[2] = {t4[1], t4[3]};
                mma_f16(s[2*nbp],   aq_hi[kc], b0);
                mma_f16(s[2*nbp+1], aq_hi[kc], b1);
                mma_f16(s[2*nbp],   aq_lo[kc], b0);
                mma_f16(s[2*nbp+1], aq_lo[kc], b1);
            }
        }

        const int grow0 = t0 + 16 * wid + (lane >> 2);
        if (j >= ntiles - 2) {
            int s0 = j * 64;
            #pragma unroll
            for (int j8 = 0; j8 < 8; j8++) {
                int col = s0 + j8 * 8 + 2 * (lane & 3);
                if (col     > grow0)     s[j8][0] = -1e30f;
                if (col + 1 > grow0)     s[j8][1] = -1e30f;
                if (col     > grow0 + 8) s[j8][2] = -1e30f;
                if (col + 1 > grow0 + 8) s[j8][3] = -1e30f;
            }
        }

        // ---- online softmax ----
        float mx0 = -1e30f, mx1 = -1e30f;
        #pragma unroll
        for (int j8 = 0; j8 < 8; j8++) {
            mx0 = fmaxf(mx0, fmaxf(s[j8][0], s[j8][1]));
            mx1 = fmaxf(mx1, fmaxf(s[j8][2], s[j8][3]));
        }
        mx0 = fmaxf(mx0, __shfl_xor_sync(0xffffffffu, mx0, 1));
        mx0 = fmaxf(mx0, __shfl_xor_sync(0xffffffffu, mx0, 2));
        mx1 = fmaxf(mx1, __shfl_xor_sync(0xffffffffu, mx1, 1));
        mx1 = fmaxf(mx1, __shfl_xor_sync(0xffffffffu, mx1, 2));
        float mn0 = fmaxf(rm0, mx0), mn1 = fmaxf(rm1, mx1);
        float al0 = __expf(rm0 - mn0), al1 = __expf(rm1 - mn1);
        rm0 = mn0; rm1 = mn1;
        float sum0 = 0.f, sum1 = 0.f;
        #pragma unroll
        for (int j8 = 0; j8 < 8; j8++) {
            s[j8][0] = __expf(s[j8][0] - mn0); sum0 += s[j8][0];
            s[j8][1] = __expf(s[j8][1] - mn0); sum0 += s[j8][1];
            s[j8][2] = __expf(s[j8][2] - mn1); sum1 += s[j8][2];
            s[j8][3] = __expf(s[j8][3] - mn1); sum1 += s[j8][3];
        }
        sum0 += __shfl_xor_sync(0xffffffffu, sum0, 1);
        sum0 += __shfl_xor_sync(0xffffffffu, sum0, 2);
        sum1 += __shfl_xor_sync(0xffffffffu, sum1, 1);
        sum1 += __shfl_xor_sync(0xffffffffu, sum1, 2);
        rl0 = rl0 * al0 + sum0;
        rl1 = rl1 * al1 + sum1;
        #pragma unroll
        for (int j8 = 0; j8 < 8; j8++) {
            O[j8][0] *= al0; O[j8][1] *= al0;
            O[j8][2] *= al1; O[j8][3] *= al1;
        }

        // ---- P fragments (single fp16; C-layout -> A-layout identity) ----
        uint32_t pa[4][4];
        #pragma unroll
        for (int kc = 0; kc < 4; kc++) {
            pa[kc][0] = pack_h(s[2*kc][0],   s[2*kc][1]);
            pa[kc][1] = pack_h(s[2*kc][2],   s[2*kc][3]);
            pa[kc][2] = pack_h(s[2*kc+1][0], s[2*kc+1][1]);
            pa[kc][3] = pack_h(s[2*kc+1][2], s[2*kc+1][3]);
        }

        // ---- O += P @ V (P single x V hi/lo) ----
        uint32_t vbase = kbase + AT_VHI;
        #pragma unroll
        for (int kc = 0; kc < 4; kc++) {
            #pragma unroll
            for (int nbp = 0; nbp < 4; nbp++) {
                int row = 16 * nbp + jlow * 8 + rsub;
                uint32_t sw = (uint32_t)(row * 128 +
                              (((2 * kc + jhigh) ^ (row & 7)) << 4));
                uint32_t t4[4];
                ldsm_x4(t4, vbase + sw);                   // Vt hi
                uint32_t b0[2] = {t4[0], t4[2]}, b1[2] = {t4[1], t4[3]};
                mma_f16(O[2*nbp],   pa[kc], b0);
                mma_f16(O[2*nbp+1], pa[kc], b1);
                ldsm_x4(t4, vbase + 8192 + sw);            // Vt lo
                uint32_t c0[2] = {t4[0], t4[2]}, c1[2] = {t4[1], t4[3]};
                mma_f16(O[2*nbp],   pa[kc], c0);
                mma_f16(O[2*nbp+1], pa[kc], c1);
            }
        }
    }

    // ---- epilogue: normalize, hi/lo split, write g_att ----
    float inv0 = 1.0f / rl0, inv1 = 1.0f / rl1;
    const int b = bh >> 4, h = bh & 15;
    const int trow = t0 + 16 * wid + (lane >> 2);
    size_t base0 = ((size_t)(b * T_) + trow) * C_ + h * HS_;
    size_t base1 = base0 + (size_t)8 * C_;
    #pragma unroll
    for (int j8 = 0; j8 < 8; j8++) {
        int d = j8 * 8 + 2 * (lane & 3);
        float f0 = O[j8][0] * inv0, f1 = O[j8][1] * inv0;
        float f2 = O[j8][2] * inv1, f3 = O[j8][3] * inv1;
        *(uint32_t*)(g_att_hi + base0 + d) = pack_h(f0, f1);
        *(uint32_t*)(g_att_lo + base0 + d) = lo_pack_h(f0, f1);
        *(uint32_t*)(g_att_hi + base1 + d) = pack_h(f2, f3);
        *(uint32_t*)(g_att_lo + base1 + d) = lo_pack_h(f2, f3);
    }
}

// ---------------------------------------------------------------------------
extern "C" void kernel_launch(void* const* d_in, const int* in_sizes, int n_in,
                              void* d_out, int out_size)
{
    const float* x  = (const float*)d_in[0];
    const float* Wq = (const float*)d_in[1];
    const float* Wk = (const float*)d_in[2];
    const float* Wv = (const float*)d_in[3];
    const float* Wp = (const float*)d_in[4];
    const float* bp = (const float*)d_in[5];
    float* out = (float*)d_out;

    cudaFuncSetAttribute(qkv_gemm_kernel,
        cudaFuncAttributeMaxDynamicSharedMemorySize, GEMM_SMEM_TOTAL);
    cudaFuncSetAttribute(proj_gemm_kernel,
        cudaFuncAttributeMaxDynamicSharedMemorySize, GEMM_SMEM_TOTAL);
    cudaFuncSetAttribute(attn2_kernel,
        cudaFuncAttributeMaxDynamicSharedMemorySize, AT_SMEM_TOTAL);

    conv_x_kernel<<<BT_*C_/1024, 256>>>(x);
    conv_wqkv_kernel<<<dim3(16, 48), 256>>>(Wq, Wk, Wv);
    conv_wp_kernel<<<dim3(16, 16), 256>>>(Wp);
    qkv_gemm_kernel<<<dim3(NQKV_/128, BT_/128), 256, GEMM_SMEM_TOTAL>>>();
    conv_vt_kernel<<<dim3(T_/64, NBH_), 256>>>();
    attn2_kernel<<<dim3(T_/128, NBH_), 256, AT_SMEM_TOTAL>>>();
    proj_gemm_kernel<<<dim3(C_/128, BT_/128), 256, GEMM_SMEM_TOTAL>>>(bp, out);
}

// round 7
// speedup vs baseline: 4.4253x; 1.0717x over previous
#include <cuda_runtime.h>
#include <cuda_fp16.h>
#include <math.h>
#include <stdint.h>

// Problem constants
#define B_ 4
#define T_ 2048
#define C_ 1024
#define H_ 16
#define HS_ 64
#define BT_ (B_*T_)      // 8192
#define NQKV_ 3072       // 3*H*HS
#define NBH_ (B_*H_)     // 64

// ---------------------------------------------------------------------------
// Scratch (device globals: allocation-free rule)
// ---------------------------------------------------------------------------
__device__ __half g_x_hi[BT_*C_];
__device__ __half g_x_lo[BT_*C_];
__device__ __half g_wqkv[NQKV_*C_];     // [n=mat*1024+h*64+d][c] K-major, single
__device__ __half g_wp[C_*C_];          // [n][k] K-major (transposed Wp), single
__device__ __half g_q_hi[NBH_*T_*HS_];  // [bh][t][d], pre-scaled by 1/32
__device__ __half g_q_lo[NBH_*T_*HS_];
__device__ __half g_k  [NBH_*T_*HS_];   // [bh][s][d], single fp16
__device__ float  g_v  [NBH_*T_*HS_];   // fp32, [bh][s][d]
__device__ __half g_vt [NBH_*HS_*T_];   // [bh][d][s]  (V transposed, single fp16)
__device__ __half g_att_hi[BT_*C_];     // attention output hi/lo fp16
__device__ __half g_att_lo[BT_*C_];

// ---------------------------------------------------------------------------
// Portable (compute_100-safe) tensor-core primitives
// ---------------------------------------------------------------------------
__device__ __forceinline__ uint32_t smem_to_u32(const void* p) {
    uint32_t a;
    asm("{ .reg .u64 t; cvta.to.shared.u64 t, %1; cvt.u32.u64 %0, t; }"
        : "=r"(a) : "l"(p));
    return a;
}

__device__ __forceinline__ void ldsm_x4(uint32_t* r, uint32_t addr) {
    asm volatile("ldmatrix.sync.aligned.m8n8.x4.shared.b16 {%0,%1,%2,%3}, [%4];\n"
        : "=r"(r[0]), "=r"(r[1]), "=r"(r[2]), "=r"(r[3]) : "r"(addr));
}

__device__ __forceinline__ void mma_f16(float* c, const uint32_t* a, const uint32_t* b) {
    asm volatile(
        "mma.sync.aligned.m16n8k16.row.col.f32.f16.f16.f32 "
        "{%0,%1,%2,%3}, {%4,%5,%6,%7}, {%8,%9}, {%0,%1,%2,%3};\n"
        : "+f"(c[0]), "+f"(c[1]), "+f"(c[2]), "+f"(c[3])
        : "r"(a[0]), "r"(a[1]), "r"(a[2]), "r"(a[3]), "r"(b[0]), "r"(b[1]));
}

__device__ __forceinline__ void cp16(uint32_t dst, const void* src) {
    asm volatile("cp.async.cg.shared.global [%0], [%1], 16;\n" :: "r"(dst), "l"(src));
}
__device__ __forceinline__ void cp_commit() {
    asm volatile("cp.async.commit_group;\n" ::: "memory");
}
template <int N>
__device__ __forceinline__ void cp_wait() {
    asm volatile("cp.async.wait_group %0;\n" :: "n"(N) : "memory");
}

__device__ __forceinline__ uint32_t pack_h(float a, float b) {
    __half2 t = __floats2half2_rn(a, b);
    return *(uint32_t*)&t;
}
__device__ __forceinline__ uint32_t lo_pack_h(float a, float b) {
    float ra = a - __half2float(__float2half_rn(a));
    float rb = b - __half2float(__float2half_rn(b));
    return pack_h(ra, rb);
}

// ---------------------------------------------------------------------------
// Conversion kernels
// ---------------------------------------------------------------------------
__global__ __launch_bounds__(256) void conv_x_kernel(const float* __restrict__ x)
{
    size_t idx = (size_t)blockIdx.x * 256 + threadIdx.x;   // float4 index
    float4 a = *(const float4*)(x + idx * 4);
    uint2 ph = make_uint2(pack_h(a.x, a.y), pack_h(a.z, a.w));
    uint2 pl = make_uint2(lo_pack_h(a.x, a.y), lo_pack_h(a.z, a.w));
    *(uint2*)(g_x_hi + idx * 4) = ph;
    *(uint2*)(g_x_lo + idx * 4) = pl;
}

// 64x64 transpose-convert tile, single fp16 output
__device__ __forceinline__ void transpose_tile_s(
    const float* __restrict__ in, int in_stride,
    __half* __restrict__ oh, size_t out_stride, float (*sm)[68])
{
    const int tid = threadIdx.x;
    #pragma unroll
    for (int it = 0; it < 4; it++) {
        int v = tid + it * 256;
        int r = v >> 4, c4 = (v & 15) * 4;
        float4 a = *(const float4*)(in + (size_t)r * in_stride + c4);
        sm[r][c4] = a.x; sm[r][c4 + 1] = a.y; sm[r][c4 + 2] = a.z; sm[r][c4 + 3] = a.w;
    }
    __syncthreads();
    #pragma unroll
    for (int it = 0; it < 4; it++) {
        int v = tid + it * 256;
        int d = v >> 4, r4 = (v & 15) * 4;
        float f0 = sm[r4][d], f1 = sm[r4 + 1][d], f2 = sm[r4 + 2][d], f3 = sm[r4 + 3][d];
        uint2 ph = make_uint2(pack_h(f0, f1), pack_h(f2, f3));
        *(uint2*)(oh + (size_t)d * out_stride + r4) = ph;
    }
}

__global__ __launch_bounds__(256) void conv_wqkv_kernel(
    const float* __restrict__ Wq, const float* __restrict__ Wk,
    const float* __restrict__ Wv)
{
    __shared__ float sm[64][68];
    const int c0 = blockIdx.x * 64;
    const int g  = blockIdx.y;        // 0..47
    const int mat = g >> 4, h = g & 15;
    const float* Wsel = (mat == 0 ? Wq : (mat == 1 ? Wk : Wv));
    const float* in = Wsel + (size_t)h * C_ * HS_ + (size_t)c0 * HS_;
    size_t ob = (size_t)(mat * 1024 + h * 64) * C_ + c0;
    transpose_tile_s(in, HS_, g_wqkv + ob, C_, sm);
}

__global__ __launch_bounds__(256) void conv_wp_kernel(const float* __restrict__ Wp)
{
    __shared__ float sm[64][68];
    const int k0 = blockIdx.x * 64;
    const int n0 = blockIdx.y * 64;
    const float* in = Wp + (size_t)k0 * C_ + n0;
    size_t ob = (size_t)n0 * C_ + k0;
    transpose_tile_s(in, C_, g_wp + ob, C_, sm);
}

__global__ __launch_bounds__(256) void conv_vt_kernel()
{
    __shared__ float sm[64][68];
    const int s0 = blockIdx.x * 64;
    const int bh = blockIdx.y;
    const float* in = g_v + ((size_t)bh * T_ + s0) * HS_;
    size_t ob = (size_t)bh * HS_ * T_ + s0;
    transpose_tile_s(in, HS_, g_vt + ob, T_, sm);
}

// ---------------------------------------------------------------------------
// fp16 2-pass GEMM mainloop (mma.sync) — unchanged from round 6.
// CTA 128x128, K-chunk 32, 4-stage cp.async pipeline (96 KB smem), 2 CTAs/SM.
// ---------------------------------------------------------------------------
#define ST_BYTES 24576
#define NST 4
#define GEMM_SMEM_TOTAL (NST*ST_BYTES)   // 98304

__device__ __forceinline__ void load_stage(
    uint32_t sb, int s,
    const __half* __restrict__ Ah, const __half* __restrict__ Al,
    const __half* __restrict__ Bs,
    int m0, int n0, int k0, int tid)
{
    uint32_t abase = sb + s * ST_BYTES;
    uint32_t bbase = abase + 16384;
    #pragma unroll
    for (int it = 0; it < 4; it++) {
        int cid = tid + it * 256;         // 0..1023
        int r = cid >> 3, c = cid & 7;
        uint32_t off = (uint32_t)(r * 128 + ((c ^ (r & 7)) << 4));
        const __half* srcA =
            (c < 4 ? Ah : Al) + (size_t)(m0 + r) * 1024 + k0 + (c & 3) * 8;
        cp16(abase + off, srcA);
    }
    #pragma unroll
    for (int it = 0; it < 2; it++) {
        int cid = tid + it * 256;         // 0..511
        int r = cid >> 2, c = cid & 3;
        uint32_t off = (uint32_t)(r * 64 + ((c ^ (r & 3)) << 4));
        cp16(bbase + off, Bs + (size_t)(n0 + r) * 1024 + k0 + c * 8);
    }
}

__device__ __forceinline__ void compute_stage(
    uint32_t abase, uint32_t bbase, int wm, int wn, int lane,
    float acc[4][4][4])
{
    const int jlow  = (lane >> 3) & 1;
    const int jhigh = lane >> 4;
    const int rsub  = lane & 7;

    #pragma unroll
    for (int ks = 0; ks < 2; ks++) {
        const int ch = 2 * ks + jhigh;     // 0..3
        uint32_t b[4][2];
        #pragma unroll
        for (int nb = 0; nb < 2; nb++) {
            int row = wn + 16 * nb + jlow * 8 + rsub;
            uint32_t t[4];
            ldsm_x4(t, bbase + (uint32_t)(row * 64 + ((ch ^ (row & 3)) << 4)));
            b[2*nb][0] = t[0]; b[2*nb+1][0] = t[1];
            b[2*nb][1] = t[2]; b[2*nb+1][1] = t[3];
        }
        uint32_t a[4][4];
        #pragma unroll
        for (int mi = 0; mi < 4; mi++) {
            int row = wm + 16 * mi + jlow * 8 + rsub;
            ldsm_x4(a[mi], abase + (uint32_t)(row * 128 + ((ch ^ (row & 7)) << 4)));
        }
        #pragma unroll
        for (int mi = 0; mi < 4; mi++)
            #pragma unroll
            for (int ni = 0; ni < 4; ni++)
                mma_f16(acc[mi][ni], a[mi], b[ni]);
        #pragma unroll
        for (int mi = 0; mi < 4; mi++) {
            int row = wm + 16 * mi + jlow * 8 + rsub;
            ldsm_x4(a[mi], abase + (uint32_t)(row * 128 + (((ch + 4) ^ (row & 7)) << 4)));
        }
        #pragma unroll
        for (int mi = 0; mi < 4; mi++)
            #pragma unroll
            for (int ni = 0; ni < 4; ni++)
                mma_f16(acc[mi][ni], a[mi], b[ni]);
    }
}

__device__ __forceinline__ void gemm_mainloop(
    uint32_t sb,
    const __half* Ah, const __half* Al, const __half* Bs,
    int m0, int n0, int wm, int wn, int lane, int tid,
    float acc[4][4][4])
{
    load_stage(sb, 0, Ah, Al, Bs, m0, n0, 0, tid);   cp_commit();
    load_stage(sb, 1, Ah, Al, Bs, m0, n0, 32, tid);  cp_commit();
    load_stage(sb, 2, Ah, Al, Bs, m0, n0, 64, tid);  cp_commit();
    #pragma unroll 1
    for (int i = 0; i < 32; i++) {
        if (i < 30)       cp_wait<2>();
        else if (i == 30) cp_wait<1>();
        else              cp_wait<0>();
        __syncthreads();
        if (i + 3 < 32) {
            load_stage(sb, (i + 3) % NST, Ah, Al, Bs, m0, n0, (i + 3) * 32, tid);
            cp_commit();
        }
        uint32_t abase = sb + (i % NST) * ST_BYTES;
        compute_stage(abase, abase + 16384, wm, wn, lane, acc);
    }
}

// ---------------------------------------------------------------------------
// QKV GEMM: epilogue writes Q(hi/lo fp16, scaled), K(single fp16), V(fp32)
// ---------------------------------------------------------------------------
__global__ __launch_bounds__(256, 2) void qkv_gemm_kernel()
{
    extern __shared__ char smem[];
    uint32_t sb = smem_to_u32(smem);
    const int tid = threadIdx.x;
    const int wid = tid >> 5, lane = tid & 31;
    const int n0 = blockIdx.x * 128;
    const int m0 = blockIdx.y * 128;
    const int wm = (wid & 1) * 64;
    const int wn = (wid >> 1) * 32;

    float acc[4][4][4] = {};
    gemm_mainloop(sb, g_x_hi, g_x_lo, g_wqkv, m0, n0, wm, wn, lane, tid, acc);

    const int b = m0 >> 11;          // whole CTA inside one batch
    #pragma unroll
    for (int mi = 0; mi < 4; mi++) {
        int m = m0 + wm + mi * 16 + (lane >> 2);
        int t = m & (T_ - 1);
        #pragma unroll
        for (int ni = 0; ni < 4; ni++) {
            int n = n0 + wn + ni * 8 + 2 * (lane & 3);
            int mat = n >> 10, h = (n >> 6) & 15, d = n & 63;
            int bh = b * H_ + h;
            size_t off0 = ((size_t)bh * T_ + t) * HS_ + d;
            size_t off1 = off0 + 8 * HS_;
            float c0 = acc[mi][ni][0], c1 = acc[mi][ni][1];
            float c2 = acc[mi][ni][2], c3 = acc[mi][ni][3];
            if (mat == 0) {
                c0 *= 0.03125f; c1 *= 0.03125f; c2 *= 0.03125f; c3 *= 0.03125f;
                *(uint32_t*)(g_q_hi + off0) = pack_h(c0, c1);
                *(uint32_t*)(g_q_lo + off0) = lo_pack_h(c0, c1);
                *(uint32_t*)(g_q_hi + off1) = pack_h(c2, c3);
                *(uint32_t*)(g_q_lo + off1) = lo_pack_h(c2, c3);
            } else if (mat == 1) {
                *(uint32_t*)(g_k + off0) = pack_h(c0, c1);
                *(uint32_t*)(g_k + off1) = pack_h(c2, c3);
            } else {
                *(float2*)(g_v + off0) = make_float2(c0, c1);
                *(float2*)(g_v + off1) = make_float2(c2, c3);
            }
        }
    }
}

// ---------------------------------------------------------------------------
// Projection GEMM: out[m][n] = att[m][:] . wp_t[n][:] + bp[n]
// ---------------------------------------------------------------------------
__global__ __launch_bounds__(256, 2) void proj_gemm_kernel(
    const float* __restrict__ bp, float* __restrict__ out)
{
    extern __shared__ char smem[];
    uint32_t sb = smem_to_u32(smem);
    const int tid = threadIdx.x;
    const int wid = tid >> 5, lane = tid & 31;
    const int n0 = blockIdx.x * 128;
    const int m0 = blockIdx.y * 128;
    const int wm = (wid & 1) * 64;
    const int wn = (wid >> 1) * 32;

    float acc[4][4][4] = {};
    gemm_mainloop(sb, g_att_hi, g_att_lo, g_wp, m0, n0, wm, wn, lane, tid, acc);

    #pragma unroll
    for (int mi = 0; mi < 4; mi++) {
        int m = m0 + wm + mi * 16 + (lane >> 2);
        #pragma unroll
        for (int ni = 0; ni < 4; ni++) {
            int n = n0 + wn + ni * 8 + 2 * (lane & 3);
            float2 bb = *(const float2*)(bp + n);
            float* dst = out + (size_t)m * C_ + n;
            *(float2*)dst = make_float2(acc[mi][ni][0] + bb.x, acc[mi][ni][1] + bb.y);
            *(float2*)(dst + 8 * C_) = make_float2(acc[mi][ni][2] + bb.x, acc[mi][ni][3] + bb.y);
        }
    }
}

// ---------------------------------------------------------------------------
// Tensor-core causal flash attention, fp16.
// CTA: 128 Q rows x one bh; 2 CTAs/SM. Q hi/lo; K single; P single; V single.
// KV tiles of 64; 4-stage cp.async pipeline (16 KB stages).
// smem: Q hi/lo 32KB + 4 x (K 8KB + Vt 8KB) = 96KB.
// ---------------------------------------------------------------------------
#define AT_QLO   16384
#define AT_STAGE 32768
#define AT_STAGE_BYTES 16384
#define AT_VHI    8192
#define AT_NST 4
#define AT_SMEM_TOTAL (AT_STAGE + AT_NST*AT_STAGE_BYTES)   // 98304

__device__ __forceinline__ void issue_kv_stage(uint32_t sb, int bh, int stage,
                                               int s0, int tid)
{
    uint32_t st = sb + AT_STAGE + stage * AT_STAGE_BYTES;
    const __half* kk = g_k  + ((size_t)bh * T_ + s0) * HS_;
    const __half* vh = g_vt + (size_t)bh * HS_ * T_ + s0;
    #pragma unroll
    for (int it = 0; it < 2; it++) {
        int cid = tid + it * 256;        // 0..511
        int r = cid >> 3, c = cid & 7;
        uint32_t off = (uint32_t)(r * 128 + ((c ^ (r & 7)) << 4));
        cp16(st + off,          kk + (size_t)r * HS_ + c * 8);
        cp16(st + AT_VHI + off, vh + (size_t)r * T_ + c * 8);
    }
}

__global__ __launch_bounds__(256, 2) void attn2_kernel()
{
    extern __shared__ char smem[];
    uint32_t sb = smem_to_u32(smem);
    const int tid = threadIdx.x;
    const int wid = tid >> 5, lane = tid & 31;
    const int qi = (int)gridDim.x - 1 - (int)blockIdx.x;   // heavy first
    const int bh = blockIdx.y;
    const int t0 = qi * 128;
    const int ntiles = 2 * qi + 2;

    const int jlow = (lane >> 3) & 1, jhigh = lane >> 4, rsub = lane & 7;

    // Prologue: Q hi/lo + stage0 (group0); stage1 (group1); stage2 (group2).
    {
        const __half* qh = g_q_hi + ((size_t)bh * T_ + t0) * HS_;
        const __half* ql = g_q_lo + ((size_t)bh * T_ + t0) * HS_;
        #pragma unroll
        for (int it = 0; it < 4; it++) {
            int cid = tid + it * 256;    // 0..1023
            int r = cid >> 3, c = cid & 7;
            uint32_t off = (uint32_t)(r * 128 + ((c ^ (r & 7)) << 4));
            cp16(sb + off,          qh + (size_t)r * HS_ + c * 8);
            cp16(sb + AT_QLO + off, ql + (size_t)r * HS_ + c * 8);
        }
        issue_kv_stage(sb, bh, 0, 0, tid);
        cp_commit();
        issue_kv_stage(sb, bh, 1, 64, tid);   // ntiles >= 2 always
        cp_commit();
        if (2 < ntiles) issue_kv_stage(sb, bh, 2, 128, tid);
        cp_commit();                          // empty group OK
    }

    uint32_t aq_hi[4][4], aq_lo[4][4];
    float O[8][4] = {};
    float rm0 = -1e30f, rm1 = -1e30f, rl0 = 0.f, rl1 = 0.f;

    for (int j = 0; j < ntiles; j++) {
        cp_wait<2>();          // groups <= j complete (3+j committed so far)
        __syncthreads();       // data visible; all warps done with stage j-1

        if (j == 0) {
            #pragma unroll
            for (int kc = 0; kc < 4; kc++) {
                int row = 16 * wid + jlow * 8 + rsub;
                int ch = 2 * kc + jhigh;
                uint32_t sw = (uint32_t)(row * 128 + ((ch ^ (row & 7)) << 4));
                ldsm_x4(aq_hi[kc], sb + sw);
                ldsm_x4(aq_lo[kc], sb + AT_QLO + sw);
            }
        }

        if (j + 3 < ntiles)
            issue_kv_stage(sb, bh, (j + 3) % AT_NST, (j + 3) * 64, tid);
        cp_commit();           // fixed group arithmetic

        uint32_t kbase = sb + AT_STAGE + (j % AT_NST) * AT_STAGE_BYTES;

        // ---- S = Q @ K^T (Q hi/lo x K single) ----
        float s[8][4] = {};
        #pragma unroll
        for (int kc = 0; kc < 4; kc++) {
            #pragma unroll
            for (int nbp = 0; nbp < 4; nbp++) {
                int row = 16 * nbp + jlow * 8 + rsub;
                uint32_t sw = (uint32_t)(row * 128 +
                              (((2 * kc + jhigh) ^ (row & 7)) << 4));
                uint32_t t4[4];
                ldsm_x4(t4, kbase + sw);
                uint32_t b0[2] = {t4[0], t4[2]}, b1[2] = {t4[1], t4[3]};
                mma_f16(s[2*nbp],   aq_hi[kc], b0);
                mma_f16(s[2*nbp+1], aq_hi[kc], b1);
                mma_f16(s[2*nbp],   aq_lo[kc], b0);
                mma_f16(s[2*nbp+1], aq_lo[kc], b1);
            }
        }

        const int grow0 = t0 + 16 * wid + (lane >> 2);
        if (j >= ntiles - 2) {
            int s0 = j * 64;
            #pragma unroll
            for (int j8 = 0; j8 < 8; j8++) {
                int col = s0 + j8 * 8 + 2 * (lane & 3);
                if (col     > grow0)     s[j8][0] = -1e30f;
                if (col + 1 > grow0)     s[j8][1] = -1e30f;
                if (col     > grow0 + 8) s[j8][2] = -1e30f;
                if (col + 1 > grow0 + 8) s[j8][3] = -1e30f;
            }
        }

        // ---- online softmax ----
        float mx0 = -1e30f, mx1 = -1e30f;
        #pragma unroll
        for (int j8 = 0; j8 < 8; j8++) {
            mx0 = fmaxf(mx0, fmaxf(s[j8][0], s[j8][1]));
            mx1 = fmaxf(mx1, fmaxf(s[j8][2], s[j8][3]));
        }
        mx0 = fmaxf(mx0, __shfl_xor_sync(0xffffffffu, mx0, 1));
        mx0 = fmaxf(mx0, __shfl_xor_sync(0xffffffffu, mx0, 2));
        mx1 = fmaxf(mx1, __shfl_xor_sync(0xffffffffu, mx1, 1));
        mx1 = fmaxf(mx1, __shfl_xor_sync(0xffffffffu, mx1, 2));
        float mn0 = fmaxf(rm0, mx0), mn1 = fmaxf(rm1, mx1);
        float al0 = __expf(rm0 - mn0), al1 = __expf(rm1 - mn1);
        rm0 = mn0; rm1 = mn1;
        float sum0 = 0.f, sum1 = 0.f;
        #pragma unroll
        for (int j8 = 0; j8 < 8; j8++) {
            s[j8][0] = __expf(s[j8][0] - mn0); sum0 += s[j8][0];
            s[j8][1] = __expf(s[j8][1] - mn0); sum0 += s[j8][1];
            s[j8][2] = __expf(s[j8][2] - mn1); sum1 += s[j8][2];
            s[j8][3] = __expf(s[j8][3] - mn1); sum1 += s[j8][3];
        }
        sum0 += __shfl_xor_sync(0xffffffffu, sum0, 1);
        sum0 += __shfl_xor_sync(0xffffffffu, sum0, 2);
        sum1 += __shfl_xor_sync(0xffffffffu, sum1, 1);
        sum1 += __shfl_xor_sync(0xffffffffu, sum1, 2);
        rl0 = rl0 * al0 + sum0;
        rl1 = rl1 * al1 + sum1;
        #pragma unroll
        for (int j8 = 0; j8 < 8; j8++) {
            O[j8][0] *= al0; O[j8][1] *= al0;
            O[j8][2] *= al1; O[j8][3] *= al1;
        }

        // ---- P fragments (single fp16) ----
        uint32_t pa[4][4];
        #pragma unroll
        for (int kc = 0; kc < 4; kc++) {
            pa[kc][0] = pack_h(s[2*kc][0],   s[2*kc][1]);
            pa[kc][1] = pack_h(s[2*kc][2],   s[2*kc][3]);
            pa[kc][2] = pack_h(s[2*kc+1][0], s[2*kc+1][1]);
            pa[kc][3] = pack_h(s[2*kc+1][2], s[2*kc+1][3]);
        }

        // ---- O += P @ V (both single fp16) ----
        uint32_t vbase = kbase + AT_VHI;
        #pragma unroll
        for (int kc = 0; kc < 4; kc++) {
            #pragma unroll
            for (int nbp = 0; nbp < 4; nbp++) {
                int row = 16 * nbp + jlow * 8 + rsub;
                uint32_t sw = (uint32_t)(row * 128 +
                              (((2 * kc + jhigh) ^ (row & 7)) << 4));
                uint32_t t4[4];
                ldsm_x4(t4, vbase + sw);
                uint32_t b0[2] = {t4[0], t4[2]}, b1[2] = {t4[1], t4[3]};
                mma_f16(O[2*nbp],   pa[kc], b0);
                mma_f16(O[2*nbp+1], pa[kc], b1);
            }
        }
    }

    // ---- epilogue: normalize, hi/lo split, write g_att ----
    float inv0 = 1.0f / rl0, inv1 = 1.0f / rl1;
    const int b = bh >> 4, h = bh & 15;
    const int trow = t0 + 16 * wid + (lane >> 2);
    size_t base0 = ((size_t)(b * T_) + trow) * C_ + h * HS_;
    size_t base1 = base0 + (size_t)8 * C_;
    #pragma unroll
    for (int j8 = 0; j8 < 8; j8++) {
        int d = j8 * 8 + 2 * (lane & 3);
        float f0 = O[j8][0] * inv0, f1 = O[j8][1] * inv0;
        float f2 = O[j8][2] * inv1, f3 = O[j8][3] * inv1;
        *(uint32_t*)(g_att_hi + base0 + d) = pack_h(f0, f1);
        *(uint32_t*)(g_att_lo + base0 + d) = lo_pack_h(f0, f1);
        *(uint32_t*)(g_att_hi + base1 + d) = pack_h(f2, f3);
        *(uint32_t*)(g_att_lo + base1 + d) = lo_pack_h(f2, f3);
    }
}

// ---------------------------------------------------------------------------
extern "C" void kernel_launch(void* const* d_in, const int* in_sizes, int n_in,
                              void* d_out, int out_size)
{
    const float* x  = (const float*)d_in[0];
    const float* Wq = (const float*)d_in[1];
    const float* Wk = (const float*)d_in[2];
    const float* Wv = (const float*)d_in[3];
    const float* Wp = (const float*)d_in[4];
    const float* bp = (const float*)d_in[5];
    float* out = (float*)d_out;

    cudaFuncSetAttribute(qkv_gemm_kernel,
        cudaFuncAttributeMaxDynamicSharedMemorySize, GEMM_SMEM_TOTAL);
    cudaFuncSetAttribute(proj_gemm_kernel,
        cudaFuncAttributeMaxDynamicSharedMemorySize, GEMM_SMEM_TOTAL);
    cudaFuncSetAttribute(attn2_kernel,
        cudaFuncAttributeMaxDynamicSharedMemorySize, AT_SMEM_TOTAL);

    conv_x_kernel<<<BT_*C_/1024, 256>>>(x);
    conv_wqkv_kernel<<<dim3(16, 48), 256>>>(Wq, Wk, Wv);
    conv_wp_kernel<<<dim3(16, 16), 256>>>(Wp);
    qkv_gemm_kernel<<<dim3(NQKV_/128, BT_/128), 256, GEMM_SMEM_TOTAL>>>();
    conv_vt_kernel<<<dim3(T_/64, NBH_), 256>>>();
    attn2_kernel<<<dim3(T_/128, NBH_), 256, AT_SMEM_TOTAL>>>();
    proj_gemm_kernel<<<dim3(C_/128, BT_/128), 256, GEMM_SMEM_TOTAL>>>(bp, out);
}

// round 8
// speedup vs baseline: 4.8484x; 1.0956x over previous
#include <cuda_runtime.h>
#include <cuda_fp16.h>
#include <math.h>
#include <stdint.h>

// Problem constants
#define B_ 4
#define T_ 2048
#define C_ 1024
#define H_ 16
#define HS_ 64
#define BT_ (B_*T_)      // 8192
#define NQKV_ 3072       // 3*H*HS
#define NBH_ (B_*H_)     // 64

// ---------------------------------------------------------------------------
// Scratch (device globals: allocation-free rule)
// ---------------------------------------------------------------------------
__device__ __half g_x_hi[BT_*C_];
__device__ __half g_x_lo[BT_*C_];
__device__ __half g_wqkv[NQKV_*C_];     // [n=mat*1024+h*64+d][c] K-major, single
__device__ __half g_wp[C_*C_];          // [n][k] K-major (transposed Wp), single
__device__ __half g_q_hi[NBH_*T_*HS_];  // [bh][t][d], pre-scaled by 1/32
__device__ __half g_q_lo[NBH_*T_*HS_];
__device__ __half g_k  [NBH_*T_*HS_];   // [bh][s][d], single fp16
__device__ float  g_v  [NBH_*T_*HS_];   // fp32, [bh][s][d]
__device__ __half g_vt [NBH_*HS_*T_];   // [bh][d][s]  (V transposed, single fp16)
__device__ __half g_att_hi[BT_*C_];     // attention output hi/lo fp16
__device__ __half g_att_lo[BT_*C_];

// ---------------------------------------------------------------------------
// Portable (compute_100-safe) tensor-core primitives
// ---------------------------------------------------------------------------
__device__ __forceinline__ uint32_t smem_to_u32(const void* p) {
    uint32_t a;
    asm("{ .reg .u64 t; cvta.to.shared.u64 t, %1; cvt.u32.u64 %0, t; }"
        : "=r"(a) : "l"(p));
    return a;
}

__device__ __forceinline__ void ldsm_x4(uint32_t* r, uint32_t addr) {
    asm volatile("ldmatrix.sync.aligned.m8n8.x4.shared.b16 {%0,%1,%2,%3}, [%4];\n"
        : "=r"(r[0]), "=r"(r[1]), "=r"(r[2]), "=r"(r[3]) : "r"(addr));
}

__device__ __forceinline__ void mma_f16(float* c, const uint32_t* a, const uint32_t* b) {
    asm volatile(
        "mma.sync.aligned.m16n8k16.row.col.f32.f16.f16.f32 "
        "{%0,%1,%2,%3}, {%4,%5,%6,%7}, {%8,%9}, {%0,%1,%2,%3};\n"
        : "+f"(c[0]), "+f"(c[1]), "+f"(c[2]), "+f"(c[3])
        : "r"(a[0]), "r"(a[1]), "r"(a[2]), "r"(a[3]), "r"(b[0]), "r"(b[1]));
}

__device__ __forceinline__ void cp16(uint32_t dst, const void* src) {
    asm volatile("cp.async.cg.shared.global [%0], [%1], 16;\n" :: "r"(dst), "l"(src));
}
__device__ __forceinline__ void cp_commit() {
    asm volatile("cp.async.commit_group;\n" ::: "memory");
}
template <int N>
__device__ __forceinline__ void cp_wait() {
    asm volatile("cp.async.wait_group %0;\n" :: "n"(N) : "memory");
}

__device__ __forceinline__ uint32_t pack_h(float a, float b) {
    __half2 t = __floats2half2_rn(a, b);
    return *(uint32_t*)&t;
}
__device__ __forceinline__ uint32_t lo_pack_h(float a, float b) {
    float ra = a - __half2float(__float2half_rn(a));
    float rb = b - __half2float(__float2half_rn(b));
    return pack_h(ra, rb);
}

// ---------------------------------------------------------------------------
// Conversion kernels
// ---------------------------------------------------------------------------
__global__ __launch_bounds__(256) void conv_x_kernel(const float* __restrict__ x)
{
    size_t idx = (size_t)blockIdx.x * 256 + threadIdx.x;   // float4 index
    float4 a = *(const float4*)(x + idx * 4);
    uint2 ph = make_uint2(pack_h(a.x, a.y), pack_h(a.z, a.w));
    uint2 pl = make_uint2(lo_pack_h(a.x, a.y), lo_pack_h(a.z, a.w));
    *(uint2*)(g_x_hi + idx * 4) = ph;
    *(uint2*)(g_x_lo + idx * 4) = pl;
}

// 64x64 transpose-convert tile, single fp16 output
__device__ __forceinline__ void transpose_tile_s(
    const float* __restrict__ in, int in_stride,
    __half* __restrict__ oh, size_t out_stride, float (*sm)[68])
{
    const int tid = threadIdx.x;
    #pragma unroll
    for (int it = 0; it < 4; it++) {
        int v = tid + it * 256;
        int r = v >> 4, c4 = (v & 15) * 4;
        float4 a = *(const float4*)(in + (size_t)r * in_stride + c4);
        sm[r][c4] = a.x; sm[r][c4 + 1] = a.y; sm[r][c4 + 2] = a.z; sm[r][c4 + 3] = a.w;
    }
    __syncthreads();
    #pragma unroll
    for (int it = 0; it < 4; it++) {
        int v = tid + it * 256;
        int d = v >> 4, r4 = (v & 15) * 4;
        float f0 = sm[r4][d], f1 = sm[r4 + 1][d], f2 = sm[r4 + 2][d], f3 = sm[r4 + 3][d];
        uint2 ph = make_uint2(pack_h(f0, f1), pack_h(f2, f3));
        *(uint2*)(oh + (size_t)d * out_stride + r4) = ph;
    }
}

__global__ __launch_bounds__(256) void conv_wqkv_kernel(
    const float* __restrict__ Wq, const float* __restrict__ Wk,
    const float* __restrict__ Wv)
{
    __shared__ float sm[64][68];
    const int c0 = blockIdx.x * 64;
    const int g  = blockIdx.y;        // 0..47
    const int mat = g >> 4, h = g & 15;
    const float* Wsel = (mat == 0 ? Wq : (mat == 1 ? Wk : Wv));
    const float* in = Wsel + (size_t)h * C_ * HS_ + (size_t)c0 * HS_;
    size_t ob = (size_t)(mat * 1024 + h * 64) * C_ + c0;
    transpose_tile_s(in, HS_, g_wqkv + ob, C_, sm);
}

__global__ __launch_bounds__(256) void conv_wp_kernel(const float* __restrict__ Wp)
{
    __shared__ float sm[64][68];
    const int k0 = blockIdx.x * 64;
    const int n0 = blockIdx.y * 64;
    const float* in = Wp + (size_t)k0 * C_ + n0;
    size_t ob = (size_t)n0 * C_ + k0;
    transpose_tile_s(in, C_, g_wp + ob, C_, sm);
}

__global__ __launch_bounds__(256) void conv_vt_kernel()
{
    __shared__ float sm[64][68];
    const int s0 = blockIdx.x * 64;
    const int bh = blockIdx.y;
    const float* in = g_v + ((size_t)bh * T_ + s0) * HS_;
    size_t ob = (size_t)bh * HS_ * T_ + s0;
    transpose_tile_s(in, HS_, g_vt + ob, T_, sm);
}

// ---------------------------------------------------------------------------
// fp16 GEMM mainloop (mma.sync), templated on 2-pass (A hi+lo) vs 1-pass.
// CTA 128x128, K-chunk 32, 4-stage cp.async pipeline (96 KB smem), 2 CTAs/SM.
// ---------------------------------------------------------------------------
#define ST_BYTES 24576
#define NST 4
#define GEMM_SMEM_TOTAL (NST*ST_BYTES)   // 98304

template <bool TP>
__device__ __forceinline__ void load_stage(
    uint32_t sb, int s,
    const __half* __restrict__ Ah, const __half* __restrict__ Al,
    const __half* __restrict__ Bs,
    int m0, int n0, int k0, int tid)
{
    uint32_t abase = sb + s * ST_BYTES;
    uint32_t bbase = abase + 16384;
    #pragma unroll
    for (int it = 0; it < 4; it++) {
        int cid = tid + it * 256;         // 0..1023
        int r = cid >> 3, c = cid & 7;
        if (TP || c < 4) {
            uint32_t off = (uint32_t)(r * 128 + ((c ^ (r & 7)) << 4));
            const __half* srcA =
                (c < 4 ? Ah : Al) + (size_t)(m0 + r) * 1024 + k0 + (c & 3) * 8;
            cp16(abase + off, srcA);
        }
    }
    #pragma unroll
    for (int it = 0; it < 2; it++) {
        int cid = tid + it * 256;         // 0..511
        int r = cid >> 2, c = cid & 3;
        uint32_t off = (uint32_t)(r * 64 + ((c ^ (r & 3)) << 4));
        cp16(bbase + off, Bs + (size_t)(n0 + r) * 1024 + k0 + c * 8);
    }
}

template <bool TP>
__device__ __forceinline__ void compute_stage(
    uint32_t abase, uint32_t bbase, int wm, int wn, int lane,
    float acc[4][4][4])
{
    const int jlow  = (lane >> 3) & 1;
    const int jhigh = lane >> 4;
    const int rsub  = lane & 7;

    #pragma unroll
    for (int ks = 0; ks < 2; ks++) {
        const int ch = 2 * ks + jhigh;     // 0..3
        uint32_t b[4][2];
        #pragma unroll
        for (int nb = 0; nb < 2; nb++) {
            int row = wn + 16 * nb + jlow * 8 + rsub;
            uint32_t t[4];
            ldsm_x4(t, bbase + (uint32_t)(row * 64 + ((ch ^ (row & 3)) << 4)));
            b[2*nb][0] = t[0]; b[2*nb+1][0] = t[1];
            b[2*nb][1] = t[2]; b[2*nb+1][1] = t[3];
        }
        uint32_t a[4][4];
        #pragma unroll
        for (int mi = 0; mi < 4; mi++) {
            int row = wm + 16 * mi + jlow * 8 + rsub;
            ldsm_x4(a[mi], abase + (uint32_t)(row * 128 + ((ch ^ (row & 7)) << 4)));
        }
        #pragma unroll
        for (int mi = 0; mi < 4; mi++)
            #pragma unroll
            for (int ni = 0; ni < 4; ni++)
                mma_f16(acc[mi][ni], a[mi], b[ni]);
        if (TP) {
            #pragma unroll
            for (int mi = 0; mi < 4; mi++) {
                int row = wm + 16 * mi + jlow * 8 + rsub;
                ldsm_x4(a[mi], abase + (uint32_t)(row * 128 + (((ch + 4) ^ (row & 7)) << 4)));
            }
            #pragma unroll
            for (int mi = 0; mi < 4; mi++)
                #pragma unroll
                for (int ni = 0; ni < 4; ni++)
                    mma_f16(acc[mi][ni], a[mi], b[ni]);
        }
    }
}

template <bool TP>
__device__ __forceinline__ void gemm_mainloop(
    uint32_t sb,
    const __half* Ah, const __half* Al, const __half* Bs,
    int m0, int n0, int wm, int wn, int lane, int tid,
    float acc[4][4][4])
{
    load_stage<TP>(sb, 0, Ah, Al, Bs, m0, n0, 0, tid);   cp_commit();
    load_stage<TP>(sb, 1, Ah, Al, Bs, m0, n0, 32, tid);  cp_commit();
    load_stage<TP>(sb, 2, Ah, Al, Bs, m0, n0, 64, tid);  cp_commit();
    #pragma unroll 1
    for (int i = 0; i < 32; i++) {
        if (i < 30)       cp_wait<2>();
        else if (i == 30) cp_wait<1>();
        else              cp_wait<0>();
        __syncthreads();
        if (i + 3 < 32) {
            load_stage<TP>(sb, (i + 3) % NST, Ah, Al, Bs, m0, n0, (i + 3) * 32, tid);
            cp_commit();
        }
        uint32_t abase = sb + (i % NST) * ST_BYTES;
        compute_stage<TP>(abase, abase + 16384, wm, wn, lane, acc);
    }
}

// ---------------------------------------------------------------------------
// QKV GEMM: Q columns (n0 < 1024) use hi/lo 2-pass; K/V columns single-pass.
// Epilogue writes Q(hi/lo fp16, scaled), K(single fp16), V(fp32).
// ---------------------------------------------------------------------------
__global__ __launch_bounds__(256, 2) void qkv_gemm_kernel()
{
    extern __shared__ char smem[];
    uint32_t sb = smem_to_u32(smem);
    const int tid = threadIdx.x;
    const int wid = tid >> 5, lane = tid & 31;
    const int n0 = blockIdx.x * 128;
    const int m0 = blockIdx.y * 128;
    const int wm = (wid & 1) * 64;
    const int wn = (wid >> 1) * 32;

    float acc[4][4][4] = {};
    if (n0 < 1024)
        gemm_mainloop<true >(sb, g_x_hi, g_x_lo, g_wqkv, m0, n0, wm, wn, lane, tid, acc);
    else
        gemm_mainloop<false>(sb, g_x_hi, g_x_lo, g_wqkv, m0, n0, wm, wn, lane, tid, acc);

    const int b = m0 >> 11;          // whole CTA inside one batch
    #pragma unroll
    for (int mi = 0; mi < 4; mi++) {
        int m = m0 + wm + mi * 16 + (lane >> 2);
        int t = m & (T_ - 1);
        #pragma unroll
        for (int ni = 0; ni < 4; ni++) {
            int n = n0 + wn + ni * 8 + 2 * (lane & 3);
            int mat = n >> 10, h = (n >> 6) & 15, d = n & 63;
            int bh = b * H_ + h;
            size_t off0 = ((size_t)bh * T_ + t) * HS_ + d;
            size_t off1 = off0 + 8 * HS_;
            float c0 = acc[mi][ni][0], c1 = acc[mi][ni][1];
            float c2 = acc[mi][ni][2], c3 = acc[mi][ni][3];
            if (mat == 0) {
                c0 *= 0.03125f; c1 *= 0.03125f; c2 *= 0.03125f; c3 *= 0.03125f;
                *(uint32_t*)(g_q_hi + off0) = pack_h(c0, c1);
                *(uint32_t*)(g_q_lo + off0) = lo_pack_h(c0, c1);
                *(uint32_t*)(g_q_hi + off1) = pack_h(c2, c3);
                *(uint32_t*)(g_q_lo + off1) = lo_pack_h(c2, c3);
            } else if (mat == 1) {
                *(uint32_t*)(g_k + off0) = pack_h(c0, c1);
                *(uint32_t*)(g_k + off1) = pack_h(c2, c3);
            } else {
                *(float2*)(g_v + off0) = make_float2(c0, c1);
                *(float2*)(g_v + off1) = make_float2(c2, c3);
            }
        }
    }
}

// ---------------------------------------------------------------------------
// Projection GEMM: out[m][n] = att[m][:] . wp_t[n][:] + bp[n]  (att hi/lo 2-pass)
// ---------------------------------------------------------------------------
__global__ __launch_bounds__(256, 2) void proj_gemm_kernel(
    const float* __restrict__ bp, float* __restrict__ out)
{
    extern __shared__ char smem[];
    uint32_t sb = smem_to_u32(smem);
    const int tid = threadIdx.x;
    const int wid = tid >> 5, lane = tid & 31;
    const int n0 = blockIdx.x * 128;
    const int m0 = blockIdx.y * 128;
    const int wm = (wid & 1) * 64;
    const int wn = (wid >> 1) * 32;

    float acc[4][4][4] = {};
    gemm_mainloop<true>(sb, g_att_hi, g_att_lo, g_wp, m0, n0, wm, wn, lane, tid, acc);

    #pragma unroll
    for (int mi = 0; mi < 4; mi++) {
        int m = m0 + wm + mi * 16 + (lane >> 2);
        #pragma unroll
        for (int ni = 0; ni < 4; ni++) {
            int n = n0 + wn + ni * 8 + 2 * (lane & 3);
            float2 bb = *(const float2*)(bp + n);
            float* dst = out + (size_t)m * C_ + n;
            *(float2*)dst = make_float2(acc[mi][ni][0] + bb.x, acc[mi][ni][1] + bb.y);
            *(float2*)(dst + 8 * C_) = make_float2(acc[mi][ni][2] + bb.x, acc[mi][ni][3] + bb.y);
        }
    }
}

// ---------------------------------------------------------------------------
// Tensor-core causal flash attention, fp16 (unchanged from round 7).
// ---------------------------------------------------------------------------
#define AT_QLO   16384
#define AT_STAGE 32768
#define AT_STAGE_BYTES 16384
#define AT_VHI    8192
#define AT_NST 4
#define AT_SMEM_TOTAL (AT_STAGE + AT_NST*AT_STAGE_BYTES)   // 98304

__device__ __forceinline__ void issue_kv_stage(uint32_t sb, int bh, int stage,
                                               int s0, int tid)
{
    uint32_t st = sb + AT_STAGE + stage * AT_STAGE_BYTES;
    const __half* kk = g_k  + ((size_t)bh * T_ + s0) * HS_;
    const __half* vh = g_vt + (size_t)bh * HS_ * T_ + s0;
    #pragma unroll
    for (int it = 0; it < 2; it++) {
        int cid = tid + it * 256;        // 0..511
        int r = cid >> 3, c = cid & 7;
        uint32_t off = (uint32_t)(r * 128 + ((c ^ (r & 7)) << 4));
        cp16(st + off,          kk + (size_t)r * HS_ + c * 8);
        cp16(st + AT_VHI + off, vh + (size_t)r * T_ + c * 8);
    }
}

__global__ __launch_bounds__(256, 2) void attn2_kernel()
{
    extern __shared__ char smem[];
    uint32_t sb = smem_to_u32(smem);
    const int tid = threadIdx.x;
    const int wid = tid >> 5, lane = tid & 31;
    const int qi = (int)gridDim.x - 1 - (int)blockIdx.x;   // heavy first
    const int bh = blockIdx.y;
    const int t0 = qi * 128;
    const int ntiles = 2 * qi + 2;

    const int jlow = (lane >> 3) & 1, jhigh = lane >> 4, rsub = lane & 7;

    {
        const __half* qh = g_q_hi + ((size_t)bh * T_ + t0) * HS_;
        const __half* ql = g_q_lo + ((size_t)bh * T_ + t0) * HS_;
        #pragma unroll
        for (int it = 0; it < 4; it++) {
            int cid = tid + it * 256;    // 0..1023
            int r = cid >> 3, c = cid & 7;
            uint32_t off = (uint32_t)(r * 128 + ((c ^ (r & 7)) << 4));
            cp16(sb + off,          qh + (size_t)r * HS_ + c * 8);
            cp16(sb + AT_QLO + off, ql + (size_t)r * HS_ + c * 8);
        }
        issue_kv_stage(sb, bh, 0, 0, tid);
        cp_commit();
        issue_kv_stage(sb, bh, 1, 64, tid);
        cp_commit();
        if (2 < ntiles) issue_kv_stage(sb, bh, 2, 128, tid);
        cp_commit();
    }

    uint32_t aq_hi[4][4], aq_lo[4][4];
    float O[8][4] = {};
    float rm0 = -1e30f, rm1 = -1e30f, rl0 = 0.f, rl1 = 0.f;

    for (int j = 0; j < ntiles; j++) {
        cp_wait<2>();
        __syncthreads();

        if (j == 0) {
            #pragma unroll
            for (int kc = 0; kc < 4; kc++) {
                int row = 16 * wid + jlow * 8 + rsub;
                int ch = 2 * kc + jhigh;
                uint32_t sw = (uint32_t)(row * 128 + ((ch ^ (row & 7)) << 4));
                ldsm_x4(aq_hi[kc], sb + sw);
                ldsm_x4(aq_lo[kc], sb + AT_QLO + sw);
            }
        }

        if (j + 3 < ntiles)
            issue_kv_stage(sb, bh, (j + 3) % AT_NST, (j + 3) * 64, tid);
        cp_commit();

        uint32_t kbase = sb + AT_STAGE + (j % AT_NST) * AT_STAGE_BYTES;

        // ---- S = Q @ K^T (Q hi/lo x K single) ----
        float s[8][4] = {};
        #pragma unroll
        for (int kc = 0; kc < 4; kc++) {
            #pragma unroll
            for (int nbp = 0; nbp < 4; nbp++) {
                int row = 16 * nbp + jlow * 8 + rsub;
                uint32_t sw = (uint32_t)(row * 128 +
                              (((2 * kc + jhigh) ^ (row & 7)) << 4));
                uint32_t t4[4];
                ldsm_x4(t4, kbase + sw);
                uint32_t b0[2] = {t4[0], t4[2]}, b1[2] = {t4[1], t4[3]};
                mma_f16(s[2*nbp],   aq_hi[kc], b0);
                mma_f16(s[2*nbp+1], aq_hi[kc], b1);
                mma_f16(s[2*nbp],   aq_lo[kc], b0);
                mma_f16(s[2*nbp+1], aq_lo[kc], b1);
            }
        }

        const int grow0 = t0 + 16 * wid + (lane >> 2);
        if (j >= ntiles - 2) {
            int s0 = j * 64;
            #pragma unroll
            for (int j8 = 0; j8 < 8; j8++) {
                int col = s0 + j8 * 8 + 2 * (lane & 3);
                if (col     > grow0)     s[j8][0] = -1e30f;
                if (col + 1 > grow0)     s[j8][1] = -1e30f;
                if (col     > grow0 + 8) s[j8][2] = -1e30f;
                if (col + 1 > grow0 + 8) s[j8][3] = -1e30f;
            }
        }

        // ---- online softmax ----
        float mx0 = -1e30f, mx1 = -1e30f;
        #pragma unroll
        for (int j8 = 0; j8 < 8; j8++) {
            mx0 = fmaxf(mx0, fmaxf(s[j8][0], s[j8][1]));
            mx1 = fmaxf(mx1, fmaxf(s[j8][2], s[j8][3]));
        }
        mx0 = fmaxf(mx0, __shfl_xor_sync(0xffffffffu, mx0, 1));
        mx0 = fmaxf(mx0, __shfl_xor_sync(0xffffffffu, mx0, 2));
        mx1 = fmaxf(mx1, __shfl_xor_sync(0xffffffffu, mx1, 1));
        mx1 = fmaxf(mx1, __shfl_xor_sync(0xffffffffu, mx1, 2));
        float mn0 = fmaxf(rm0, mx0), mn1 = fmaxf(rm1, mx1);
        float al0 = __expf(rm0 - mn0), al1 = __expf(rm1 - mn1);
        rm0 = mn0; rm1 = mn1;
        float sum0 = 0.f, sum1 = 0.f;
        #pragma unroll
        for (int j8 = 0; j8 < 8; j8++) {
            s[j8][0] = __expf(s[j8][0] - mn0); sum0 += s[j8][0];
            s[j8][1] = __expf(s[j8][1] - mn0); sum0 += s[j8][1];
            s[j8][2] = __expf(s[j8][2] - mn1); sum1 += s[j8][2];
            s[j8][3] = __expf(s[j8][3] - mn1); sum1 += s[j8][3];
        }
        sum0 += __shfl_xor_sync(0xffffffffu, sum0, 1);
        sum0 += __shfl_xor_sync(0xffffffffu, sum0, 2);
        sum1 += __shfl_xor_sync(0xffffffffu, sum1, 1);
        sum1 += __shfl_xor_sync(0xffffffffu, sum1, 2);
        rl0 = rl0 * al0 + sum0;
        rl1 = rl1 * al1 + sum1;
        #pragma unroll
        for (int j8 = 0; j8 < 8; j8++) {
            O[j8][0] *= al0; O[j8][1] *= al0;
            O[j8][2] *= al1; O[j8][3] *= al1;
        }

        // ---- P fragments (single fp16) ----
        uint32_t pa[4][4];
        #pragma unroll
        for (int kc = 0; kc < 4; kc++) {
            pa[kc][0] = pack_h(s[2*kc][0],   s[2*kc][1]);
            pa[kc][1] = pack_h(s[2*kc][2],   s[2*kc][3]);
            pa[kc][2] = pack_h(s[2*kc+1][0], s[2*kc+1][1]);
            pa[kc][3] = pack_h(s[2*kc+1][2], s[2*kc+1][3]);
        }

        // ---- O += P @ V (both single fp16) ----
        uint32_t vbase = kbase + AT_VHI;
        #pragma unroll
        for (int kc = 0; kc < 4; kc++) {
            #pragma unroll
            for (int nbp = 0; nbp < 4; nbp++) {
                int row = 16 * nbp + jlow * 8 + rsub;
                uint32_t sw = (uint32_t)(row * 128 +
                              (((2 * kc + jhigh) ^ (row & 7)) << 4));
                uint32_t t4[4];
                ldsm_x4(t4, vbase + sw);
                uint32_t b0[2] = {t4[0], t4[2]}, b1[2] = {t4[1], t4[3]};
                mma_f16(O[2*nbp],   pa[kc], b0);
                mma_f16(O[2*nbp+1], pa[kc], b1);
            }
        }
    }

    // ---- epilogue: normalize, hi/lo split, write g_att ----
    float inv0 = 1.0f / rl0, inv1 = 1.0f / rl1;
    const int b = bh >> 4, h = bh & 15;
    const int trow = t0 + 16 * wid + (lane >> 2);
    size_t base0 = ((size_t)(b * T_) + trow) * C_ + h * HS_;
    size_t base1 = base0 + (size_t)8 * C_;
    #pragma unroll
    for (int j8 = 0; j8 < 8; j8++) {
        int d = j8 * 8 + 2 * (lane & 3);
        float f0 = O[j8][0] * inv0, f1 = O[j8][1] * inv0;
        float f2 = O[j8][2] * inv1, f3 = O[j8][3] * inv1;
        *(uint32_t*)(g_att_hi + base0 + d) = pack_h(f0, f1);
        *(uint32_t*)(g_att_lo + base0 + d) = lo_pack_h(f0, f1);
        *(uint32_t*)(g_att_hi + base1 + d) = pack_h(f2, f3);
        *(uint32_t*)(g_att_lo + base1 + d) = lo_pack_h(f2, f3);
    }
}

// ---------------------------------------------------------------------------
extern "C" void kernel_launch(void* const* d_in, const int* in_sizes, int n_in,
                              void* d_out, int out_size)
{
    const float* x  = (const float*)d_in[0];
    const float* Wq = (const float*)d_in[1];
    const float* Wk = (const float*)d_in[2];
    const float* Wv = (const float*)d_in[3];
    const float* Wp = (const float*)d_in[4];
    const float* bp = (const float*)d_in[5];
    float* out = (float*)d_out;

    cudaFuncSetAttribute(qkv_gemm_kernel,
        cudaFuncAttributeMaxDynamicSharedMemorySize, GEMM_SMEM_TOTAL);
    cudaFuncSetAttribute(proj_gemm_kernel,
        cudaFuncAttributeMaxDynamicSharedMemorySize, GEMM_SMEM_TOTAL);
    cudaFuncSetAttribute(attn2_kernel,
        cudaFuncAttributeMaxDynamicSharedMemorySize, AT_SMEM_TOTAL);

    conv_x_kernel<<<BT_*C_/1024, 256>>>(x);
    conv_wqkv_kernel<<<dim3(16, 48), 256>>>(Wq, Wk, Wv);
    conv_wp_kernel<<<dim3(16, 16), 256>>>(Wp);
    qkv_gemm_kernel<<<dim3(NQKV_/128, BT_/128), 256, GEMM_SMEM_TOTAL>>>();
    conv_vt_kernel<<<dim3(T_/64, NBH_), 256>>>();
    attn2_kernel<<<dim3(T_/128, NBH_), 256, AT_SMEM_TOTAL>>>();
    proj_gemm_kernel<<<dim3(C_/128, BT_/128), 256, GEMM_SMEM_TOTAL>>>(bp, out);
}

// round 9
// speedup vs baseline: 6.3390x; 1.3074x over previous
#include <cuda_runtime.h>
#include <cuda_fp16.h>
#include <math.h>
#include <stdint.h>

// Problem constants
#define B_ 4
#define T_ 2048
#define C_ 1024
#define H_ 16
#define HS_ 64
#define BT_ (B_*T_)      // 8192
#define NQKV_ 3072       // 3*H*HS
#define NBH_ (B_*H_)     // 64

// ---------------------------------------------------------------------------
// Scratch (device globals: allocation-free rule). All operands single fp16 now.
// ---------------------------------------------------------------------------
__device__ __half g_x   [BT_*C_];       // [m][c]
__device__ __half g_wqkv[NQKV_*C_];     // [n=mat*1024+h*64+d][c] K-major
__device__ __half g_wp  [C_*C_];        // [n][k] K-major (transposed Wp)
__device__ __half g_q   [NBH_*T_*HS_];  // [bh][t][d], pre-scaled by 1/32
__device__ __half g_k   [NBH_*T_*HS_];  // [bh][s][d]
__device__ float  g_v   [NBH_*T_*HS_];  // fp32, [bh][s][d]
__device__ __half g_vt  [NBH_*HS_*T_];  // [bh][d][s]  (V transposed)
__device__ __half g_att [BT_*C_];       // attention output

// ---------------------------------------------------------------------------
// Portable (compute_100-safe) tensor-core primitives
// ---------------------------------------------------------------------------
__device__ __forceinline__ uint32_t smem_to_u32(const void* p) {
    uint32_t a;
    asm("{ .reg .u64 t; cvta.to.shared.u64 t, %1; cvt.u32.u64 %0, t; }"
        : "=r"(a) : "l"(p));
    return a;
}

__device__ __forceinline__ void ldsm_x4(uint32_t* r, uint32_t addr) {
    asm volatile("ldmatrix.sync.aligned.m8n8.x4.shared.b16 {%0,%1,%2,%3}, [%4];\n"
        : "=r"(r[0]), "=r"(r[1]), "=r"(r[2]), "=r"(r[3]) : "r"(addr));
}

__device__ __forceinline__ void mma_f16(float* c, const uint32_t* a, const uint32_t* b) {
    asm volatile(
        "mma.sync.aligned.m16n8k16.row.col.f32.f16.f16.f32 "
        "{%0,%1,%2,%3}, {%4,%5,%6,%7}, {%8,%9}, {%0,%1,%2,%3};\n"
        : "+f"(c[0]), "+f"(c[1]), "+f"(c[2]), "+f"(c[3])
        : "r"(a[0]), "r"(a[1]), "r"(a[2]), "r"(a[3]), "r"(b[0]), "r"(b[1]));
}

__device__ __forceinline__ void cp16(uint32_t dst, const void* src) {
    asm volatile("cp.async.cg.shared.global [%0], [%1], 16;\n" :: "r"(dst), "l"(src));
}
__device__ __forceinline__ void cp_commit() {
    asm volatile("cp.async.commit_group;\n" ::: "memory");
}
template <int N>
__device__ __forceinline__ void cp_wait() {
    asm volatile("cp.async.wait_group %0;\n" :: "n"(N) : "memory");
}

__device__ __forceinline__ uint32_t pack_h(float a, float b) {
    __half2 t = __floats2half2_rn(a, b);
    return *(uint32_t*)&t;
}

// ---------------------------------------------------------------------------
// Conversion kernels
// ---------------------------------------------------------------------------
__global__ __launch_bounds__(256) void conv_x_kernel(const float* __restrict__ x)
{
    size_t idx = (size_t)blockIdx.x * 256 + threadIdx.x;   // float4 index
    float4 a = *(const float4*)(x + idx * 4);
    *(uint2*)(g_x + idx * 4) = make_uint2(pack_h(a.x, a.y), pack_h(a.z, a.w));
}

// 64x64 transpose-convert tile, single fp16 output
__device__ __forceinline__ void transpose_tile_s(
    const float* __restrict__ in, int in_stride,
    __half* __restrict__ oh, size_t out_stride, float (*sm)[68])
{
    const int tid = threadIdx.x;
    #pragma unroll
    for (int it = 0; it < 4; it++) {
        int v = tid + it * 256;
        int r = v >> 4, c4 = (v & 15) * 4;
        float4 a = *(const float4*)(in + (size_t)r * in_stride + c4);
        sm[r][c4] = a.x; sm[r][c4 + 1] = a.y; sm[r][c4 + 2] = a.z; sm[r][c4 + 3] = a.w;
    }
    __syncthreads();
    #pragma unroll
    for (int it = 0; it < 4; it++) {
        int v = tid + it * 256;
        int d = v >> 4, r4 = (v & 15) * 4;
        float f0 = sm[r4][d], f1 = sm[r4 + 1][d], f2 = sm[r4 + 2][d], f3 = sm[r4 + 3][d];
        *(uint2*)(oh + (size_t)d * out_stride + r4) =
            make_uint2(pack_h(f0, f1), pack_h(f2, f3));
    }
}

__global__ __launch_bounds__(256) void conv_wqkv_kernel(
    const float* __restrict__ Wq, const float* __restrict__ Wk,
    const float* __restrict__ Wv)
{
    __shared__ float sm[64][68];
    const int c0 = blockIdx.x * 64;
    const int g  = blockIdx.y;        // 0..47
    const int mat = g >> 4, h = g & 15;
    const float* Wsel = (mat == 0 ? Wq : (mat == 1 ? Wk : Wv));
    const float* in = Wsel + (size_t)h * C_ * HS_ + (size_t)c0 * HS_;
    size_t ob = (size_t)(mat * 1024 + h * 64) * C_ + c0;
    transpose_tile_s(in, HS_, g_wqkv + ob, C_, sm);
}

__global__ __launch_bounds__(256) void conv_wp_kernel(const float* __restrict__ Wp)
{
    __shared__ float sm[64][68];
    const int k0 = blockIdx.x * 64;
    const int n0 = blockIdx.y * 64;
    const float* in = Wp + (size_t)k0 * C_ + n0;
    size_t ob = (size_t)n0 * C_ + k0;
    transpose_tile_s(in, C_, g_wp + ob, C_, sm);
}

__global__ __launch_bounds__(256) void conv_vt_kernel()
{
    __shared__ float sm[64][68];
    const int s0 = blockIdx.x * 64;
    const int bh = blockIdx.y;
    const float* in = g_v + ((size_t)bh * T_ + s0) * HS_;
    size_t ob = (size_t)bh * HS_ * T_ + s0;
    transpose_tile_s(in, HS_, g_vt + ob, T_, sm);
}

// ---------------------------------------------------------------------------
// fp16 single-pass GEMM mainloop (mma.sync).
// CTA 128x128, K-chunk 32, 4-stage cp.async pipeline, 2 CTAs/SM.
// Stage: A 128x32 (64B rows, 8KB) + B 128x32 (64B rows, 8KB) = 16 KB.
// ---------------------------------------------------------------------------
#define ST_BYTES 16384
#define NST 4
#define GEMM_SMEM_TOTAL (NST*ST_BYTES)   // 65536

__device__ __forceinline__ void load_stage(
    uint32_t sb, int s,
    const __half* __restrict__ As, const __half* __restrict__ Bs,
    int m0, int n0, int k0, int tid)
{
    uint32_t abase = sb + s * ST_BYTES;
    uint32_t bbase = abase + 8192;
    #pragma unroll
    for (int it = 0; it < 2; it++) {
        int cid = tid + it * 256;         // 0..511
        int r = cid >> 2, c = cid & 3;
        uint32_t off = (uint32_t)(r * 64 + ((c ^ (r & 3)) << 4));
        cp16(abase + off, As + (size_t)(m0 + r) * 1024 + k0 + c * 8);
        cp16(bbase + off, Bs + (size_t)(n0 + r) * 1024 + k0 + c * 8);
    }
}

__device__ __forceinline__ void compute_stage(
    uint32_t abase, uint32_t bbase, int wm, int wn, int lane,
    float acc[4][4][4])
{
    const int jlow  = (lane >> 3) & 1;
    const int jhigh = lane >> 4;
    const int rsub  = lane & 7;

    #pragma unroll
    for (int ks = 0; ks < 2; ks++) {
        const int ch = 2 * ks + jhigh;     // 0..3
        uint32_t b[4][2];
        #pragma unroll
        for (int nb = 0; nb < 2; nb++) {
            int row = wn + 16 * nb + jlow * 8 + rsub;
            uint32_t t[4];
            ldsm_x4(t, bbase + (uint32_t)(row * 64 + ((ch ^ (row & 3)) << 4)));
            b[2*nb][0] = t[0]; b[2*nb+1][0] = t[1];
            b[2*nb][1] = t[2]; b[2*nb+1][1] = t[3];
        }
        uint32_t a[4][4];
        #pragma unroll
        for (int mi = 0; mi < 4; mi++) {
            int row = wm + 16 * mi + jlow * 8 + rsub;
            ldsm_x4(a[mi], abase + (uint32_t)(row * 64 + ((ch ^ (row & 3)) << 4)));
        }
        #pragma unroll
        for (int mi = 0; mi < 4; mi++)
            #pragma unroll
            for (int ni = 0; ni < 4; ni++)
                mma_f16(acc[mi][ni], a[mi], b[ni]);
    }
}

__device__ __forceinline__ void gemm_mainloop(
    uint32_t sb,
    const __half* As, const __half* Bs,
    int m0, int n0, int wm, int wn, int lane, int tid,
    float acc[4][4][4])
{
    load_stage(sb, 0, As, Bs, m0, n0, 0, tid);   cp_commit();
    load_stage(sb, 1, As, Bs, m0, n0, 32, tid);  cp_commit();
    load_stage(sb, 2, As, Bs, m0, n0, 64, tid);  cp_commit();
    #pragma unroll 1
    for (int i = 0; i < 32; i++) {
        if (i < 30)       cp_wait<2>();
        else if (i == 30) cp_wait<1>();
        else              cp_wait<0>();
        __syncthreads();
        if (i + 3 < 32) {
            load_stage(sb, (i + 3) % NST, As, Bs, m0, n0, (i + 3) * 32, tid);
            cp_commit();
        }
        uint32_t abase = sb + (i % NST) * ST_BYTES;
        compute_stage(abase, abase + 8192, wm, wn, lane, acc);
    }
}

// ---------------------------------------------------------------------------
// QKV GEMM: epilogue writes Q(fp16, scaled), K(fp16), V(fp32)
// ---------------------------------------------------------------------------
__global__ __launch_bounds__(256, 2) void qkv_gemm_kernel()
{
    extern __shared__ char smem[];
    uint32_t sb = smem_to_u32(smem);
    const int tid = threadIdx.x;
    const int wid = tid >> 5, lane = tid & 31;
    const int n0 = blockIdx.x * 128;
    const int m0 = blockIdx.y * 128;
    const int wm = (wid & 1) * 64;
    const int wn = (wid >> 1) * 32;

    float acc[4][4][4] = {};
    gemm_mainloop(sb, g_x, g_wqkv, m0, n0, wm, wn, lane, tid, acc);

    const int b = m0 >> 11;          // whole CTA inside one batch
    #pragma unroll
    for (int mi = 0; mi < 4; mi++) {
        int m = m0 + wm + mi * 16 + (lane >> 2);
        int t = m & (T_ - 1);
        #pragma unroll
        for (int ni = 0; ni < 4; ni++) {
            int n = n0 + wn + ni * 8 + 2 * (lane & 3);
            int mat = n >> 10, h = (n >> 6) & 15, d = n & 63;
            int bh = b * H_ + h;
            size_t off0 = ((size_t)bh * T_ + t) * HS_ + d;
            size_t off1 = off0 + 8 * HS_;
            float c0 = acc[mi][ni][0], c1 = acc[mi][ni][1];
            float c2 = acc[mi][ni][2], c3 = acc[mi][ni][3];
            if (mat == 0) {
                c0 *= 0.03125f; c1 *= 0.03125f; c2 *= 0.03125f; c3 *= 0.03125f;
                *(uint32_t*)(g_q + off0) = pack_h(c0, c1);
                *(uint32_t*)(g_q + off1) = pack_h(c2, c3);
            } else if (mat == 1) {
                *(uint32_t*)(g_k + off0) = pack_h(c0, c1);
                *(uint32_t*)(g_k + off1) = pack_h(c2, c3);
            } else {
                *(float2*)(g_v + off0) = make_float2(c0, c1);
                *(float2*)(g_v + off1) = make_float2(c2, c3);
            }
        }
    }
}

// ---------------------------------------------------------------------------
// Projection GEMM: out[m][n] = att[m][:] . wp_t[n][:] + bp[n]
// ---------------------------------------------------------------------------
__global__ __launch_bounds__(256, 2) void proj_gemm_kernel(
    const float* __restrict__ bp, float* __restrict__ out)
{
    extern __shared__ char smem[];
    uint32_t sb = smem_to_u32(smem);
    const int tid = threadIdx.x;
    const int wid = tid >> 5, lane = tid & 31;
    const int n0 = blockIdx.x * 128;
    const int m0 = blockIdx.y * 128;
    const int wm = (wid & 1) * 64;
    const int wn = (wid >> 1) * 32;

    float acc[4][4][4] = {};
    gemm_mainloop(sb, g_att, g_wp, m0, n0, wm, wn, lane, tid, acc);

    #pragma unroll
    for (int mi = 0; mi < 4; mi++) {
        int m = m0 + wm + mi * 16 + (lane >> 2);
        #pragma unroll
        for (int ni = 0; ni < 4; ni++) {
            int n = n0 + wn + ni * 8 + 2 * (lane & 3);
            float2 bb = *(const float2*)(bp + n);
            float* dst = out + (size_t)m * C_ + n;
            *(float2*)dst = make_float2(acc[mi][ni][0] + bb.x, acc[mi][ni][1] + bb.y);
            *(float2*)(dst + 8 * C_) = make_float2(acc[mi][ni][2] + bb.x, acc[mi][ni][3] + bb.y);
        }
    }
}

// ---------------------------------------------------------------------------
// Tensor-core causal flash attention, all operands single fp16.
// CTA: 128 Q rows x one bh; 2 CTAs/SM. KV tiles of 64; 4-stage pipeline.
// smem: Q 16KB + 4 x (K 8KB + Vt 8KB) = 80KB.
// ---------------------------------------------------------------------------
#define AT_STAGE 16384
#define AT_STAGE_BYTES 16384
#define AT_VHI    8192
#define AT_NST 4
#define AT_SMEM_TOTAL (AT_STAGE + AT_NST*AT_STAGE_BYTES)   // 81920

__device__ __forceinline__ void issue_kv_stage(uint32_t sb, int bh, int stage,
                                               int s0, int tid)
{
    uint32_t st = sb + AT_STAGE + stage * AT_STAGE_BYTES;
    const __half* kk = g_k  + ((size_t)bh * T_ + s0) * HS_;
    const __half* vh = g_vt + (size_t)bh * HS_ * T_ + s0;
    #pragma unroll
    for (int it = 0; it < 2; it++) {
        int cid = tid + it * 256;        // 0..511
        int r = cid >> 3, c = cid & 7;
        uint32_t off = (uint32_t)(r * 128 + ((c ^ (r & 7)) << 4));
        cp16(st + off,          kk + (size_t)r * HS_ + c * 8);
        cp16(st + AT_VHI + off, vh + (size_t)r * T_ + c * 8);
    }
}

__global__ __launch_bounds__(256, 2) void attn2_kernel()
{
    extern __shared__ char smem[];
    uint32_t sb = smem_to_u32(smem);
    const int tid = threadIdx.x;
    const int wid = tid >> 5, lane = tid & 31;
    const int qi = (int)gridDim.x - 1 - (int)blockIdx.x;   // heavy first
    const int bh = blockIdx.y;
    const int t0 = qi * 128;
    const int ntiles = 2 * qi + 2;

    const int jlow = (lane >> 3) & 1, jhigh = lane >> 4, rsub = lane & 7;

    // Prologue: Q (128x64, 128B rows) + stages 0..2
    {
        const __half* qh = g_q + ((size_t)bh * T_ + t0) * HS_;
        #pragma unroll
        for (int it = 0; it < 4; it++) {
            int cid = tid + it * 256;    // 0..1023
            int r = cid >> 3, c = cid & 7;
            uint32_t off = (uint32_t)(r * 128 + ((c ^ (r & 7)) << 4));
            cp16(sb + off, qh + (size_t)r * HS_ + c * 8);
        }
        issue_kv_stage(sb, bh, 0, 0, tid);
        cp_commit();
        issue_kv_stage(sb, bh, 1, 64, tid);   // ntiles >= 2 always
        cp_commit();
        if (2 < ntiles) issue_kv_stage(sb, bh, 2, 128, tid);
        cp_commit();
    }

    uint32_t aq[4][4];
    float O[8][4] = {};
    float rm0 = -1e30f, rm1 = -1e30f, rl0 = 0.f, rl1 = 0.f;

    for (int j = 0; j < ntiles; j++) {
        cp_wait<2>();
        __syncthreads();

        if (j == 0) {
            #pragma unroll
            for (int kc = 0; kc < 4; kc++) {
                int row = 16 * wid + jlow * 8 + rsub;
                int ch = 2 * kc + jhigh;
                uint32_t sw = (uint32_t)(row * 128 + ((ch ^ (row & 7)) << 4));
                ldsm_x4(aq[kc], sb + sw);
            }
        }

        if (j + 3 < ntiles)
            issue_kv_stage(sb, bh, (j + 3) % AT_NST, (j + 3) * 64, tid);
        cp_commit();

        uint32_t kbase = sb + AT_STAGE + (j % AT_NST) * AT_STAGE_BYTES;

        // ---- S = Q @ K^T (single fp16) ----
        float s[8][4] = {};
        #pragma unroll
        for (int kc = 0; kc < 4; kc++) {
            #pragma unroll
            for (int nbp = 0; nbp < 4; nbp++) {
                int row = 16 * nbp + jlow * 8 + rsub;
                uint32_t sw = (uint32_t)(row * 128 +
                              (((2 * kc + jhigh) ^ (row & 7)) << 4));
                uint32_t t4[4];
                ldsm_x4(t4, kbase + sw);
                uint32_t b0[2] = {t4[0], t4[2]}, b1[2] = {t4[1], t4[3]};
                mma_f16(s[2*nbp],   aq[kc], b0);
                mma_f16(s[2*nbp+1], aq[kc], b1);
            }
        }

        const int grow0 = t0 + 16 * wid + (lane >> 2);
        if (j >= ntiles - 2) {
            int s0 = j * 64;
            #pragma unroll
            for (int j8 = 0; j8 < 8; j8++) {
                int col = s0 + j8 * 8 + 2 * (lane & 3);
                if (col     > grow0)     s[j8][0] = -1e30f;
                if (col + 1 > grow0)     s[j8][1] = -1e30f;
                if (col     > grow0 + 8) s[j8][2] = -1e30f;
                if (col + 1 > grow0 + 8) s[j8][3] = -1e30f;
            }
        }

        // ---- online softmax ----
        float mx0 = -1e30f, mx1 = -1e30f;
        #pragma unroll
        for (int j8 = 0; j8 < 8; j8++) {
            mx0 = fmaxf(mx0, fmaxf(s[j8][0], s[j8][1]));
            mx1 = fmaxf(mx1, fmaxf(s[j8][2], s[j8][3]));
        }
        mx0 = fmaxf(mx0, __shfl_xor_sync(0xffffffffu, mx0, 1));
        mx0 = fmaxf(mx0, __shfl_xor_sync(0xffffffffu, mx0, 2));
        mx1 = fmaxf(mx1, __shfl_xor_sync(0xffffffffu, mx1, 1));
        mx1 = fmaxf(mx1, __shfl_xor_sync(0xffffffffu, mx1, 2));
        float mn0 = fmaxf(rm0, mx0), mn1 = fmaxf(rm1, mx1);
        float al0 = __expf(rm0 - mn0), al1 = __expf(rm1 - mn1);
        rm0 = mn0; rm1 = mn1;
        float sum0 = 0.f, sum1 = 0.f;
        #pragma unroll
        for (int j8 = 0; j8 < 8; j8++) {
            s[j8][0] = __expf(s[j8][0] - mn0); sum0 += s[j8][0];
            s[j8][1] = __expf(s[j8][1] - mn0); sum0 += s[j8][1];
            s[j8][2] = __expf(s[j8][2] - mn1); sum1 += s[j8][2];
            s[j8][3] = __expf(s[j8][3] - mn1); sum1 += s[j8][3];
        }
        sum0 += __shfl_xor_sync(0xffffffffu, sum0, 1);
        sum0 += __shfl_xor_sync(0xffffffffu, sum0, 2);
        sum1 += __shfl_xor_sync(0xffffffffu, sum1, 1);
        sum1 += __shfl_xor_sync(0xffffffffu, sum1, 2);
        rl0 = rl0 * al0 + sum0;
        rl1 = rl1 * al1 + sum1;
        #pragma unroll
        for (int j8 = 0; j8 < 8; j8++) {
            O[j8][0] *= al0; O[j8][1] *= al0;
            O[j8][2] *= al1; O[j8][3] *= al1;
        }

        // ---- P fragments (single fp16) ----
        uint32_t pa[4][4];
        #pragma unroll
        for (int kc = 0; kc < 4; kc++) {
            pa[kc][0] = pack_h(s[2*kc][0],   s[2*kc][1]);
            pa[kc][1] = pack_h(s[2*kc][2],   s[2*kc][3]);
            pa[kc][2] = pack_h(s[2*kc+1][0], s[2*kc+1][1]);
            pa[kc][3] = pack_h(s[2*kc+1][2], s[2*kc+1][3]);
        }

        // ---- O += P @ V (single fp16) ----
        uint32_t vbase = kbase + AT_VHI;
        #pragma unroll
        for (int kc = 0; kc < 4; kc++) {
            #pragma unroll
            for (int nbp = 0; nbp < 4; nbp++) {
                int row = 16 * nbp + jlow * 8 + rsub;
                uint32_t sw = (uint32_t)(row * 128 +
                              (((2 * kc + jhigh) ^ (row & 7)) << 4));
                uint32_t t4[4];
                ldsm_x4(t4, vbase + sw);
                uint32_t b0[2] = {t4[0], t4[2]}, b1[2] = {t4[1], t4[3]};
                mma_f16(O[2*nbp],   pa[kc], b0);
                mma_f16(O[2*nbp+1], pa[kc], b1);
            }
        }
    }

    // ---- epilogue: normalize, write g_att (single fp16) ----
    float inv0 = 1.0f / rl0, inv1 = 1.0f / rl1;
    const int b = bh >> 4, h = bh & 15;
    const int trow = t0 + 16 * wid + (lane >> 2);
    size_t base0 = ((size_t)(b * T_) + trow) * C_ + h * HS_;
    size_t base1 = base0 + (size_t)8 * C_;
    #pragma unroll
    for (int j8 = 0; j8 < 8; j8++) {
        int d = j8 * 8 + 2 * (lane & 3);
        *(uint32_t*)(g_att + base0 + d) = pack_h(O[j8][0] * inv0, O[j8][1] * inv0);
        *(uint32_t*)(g_att + base1 + d) = pack_h(O[j8][2] * inv1, O[j8][3] * inv1);
    }
}

// ---------------------------------------------------------------------------
extern "C" void kernel_launch(void* const* d_in, const int* in_sizes, int n_in,
                              void* d_out, int out_size)
{
    const float* x  = (const float*)d_in[0];
    const float* Wq = (const float*)d_in[1];
    const float* Wk = (const float*)d_in[2];
    const float* Wv = (const float*)d_in[3];
    const float* Wp = (const float*)d_in[4];
    const float* bp = (const float*)d_in[5];
    float* out = (float*)d_out;

    cudaFuncSetAttribute(qkv_gemm_kernel,
        cudaFuncAttributeMaxDynamicSharedMemorySize, GEMM_SMEM_TOTAL);
    cudaFuncSetAttribute(proj_gemm_kernel,
        cudaFuncAttributeMaxDynamicSharedMemorySize, GEMM_SMEM_TOTAL);
    cudaFuncSetAttribute(attn2_kernel,
        cudaFuncAttributeMaxDynamicSharedMemorySize, AT_SMEM_TOTAL);

    conv_x_kernel<<<BT_*C_/1024, 256>>>(x);
    conv_wqkv_kernel<<<dim3(16, 48), 256>>>(Wq, Wk, Wv);
    conv_wp_kernel<<<dim3(16, 16), 256>>>(Wp);
    qkv_gemm_kernel<<<dim3(NQKV_/128, BT_/128), 256, GEMM_SMEM_TOTAL>>>();
    conv_vt_kernel<<<dim3(T_/64, NBH_), 256>>>();
    attn2_kernel<<<dim3(T_/128, NBH_), 256, AT_SMEM_TOTAL>>>();
    proj_gemm_kernel<<<dim3(C_/128, BT_/128), 256, GEMM_SMEM_TOTAL>>>(bp, out);
}